// round 11
// baseline (speedup 1.0000x reference)
#include <cuda_runtime.h>
#include <cuda_bf16.h>
#include <cstdint>

// ---------------------------------------------------------------------------
// Problem constants
// ---------------------------------------------------------------------------
#define E_MAX 262144
#define T_MAX 2097152
#define MT    32          // rows per CTA tile

// ---------------------------------------------------------------------------
// Scratch (device globals -- no allocation allowed)
// ---------------------------------------------------------------------------
__device__ float g_h1  [(size_t)E_MAX * 128];
__device__ float g_ang [(size_t)E_MAX * 64];
__device__ float g_agg [(size_t)E_MAX * 64];
__device__ float g_t   [(size_t)E_MAX * 128];
__device__ float g_m   [(size_t)E_MAX * 128];
__device__ float g_rbf8[(size_t)E_MAX * 8];
__device__ float g_sbf8[(size_t)T_MAX * 8];
__device__ float g_wb  [163840];   // 640KB: bf16 hi/lo weight fragments

#define EP_SWISH      0
#define EP_SWISH_ADD  2

__device__ __forceinline__ float swishf(float v) { return v / (1.0f + __expf(-v)); }

__device__ __forceinline__ uint32_t smem_u32(const void* p) {
    uint32_t a;
    asm("{ .reg .u64 t; cvta.to.shared.u64 t, %1; cvt.u32.u64 %0, t; }"
        : "=r"(a) : "l"(p));
    return a;
}

__device__ __forceinline__ void ldm_x4(uint32_t* r, uint32_t addr) {
    asm volatile("ldmatrix.sync.aligned.m8n8.x4.shared.b16 {%0,%1,%2,%3}, [%4];"
                 : "=r"(r[0]), "=r"(r[1]), "=r"(r[2]), "=r"(r[3]) : "r"(addr));
}

__device__ __forceinline__ void mma_bf16(float* d, const uint32_t* a, uint32_t b0, uint32_t b1) {
    asm volatile("mma.sync.aligned.m16n8k16.row.col.f32.bf16.bf16.f32 "
                 "{%0,%1,%2,%3}, {%4,%5,%6,%7}, {%8,%9}, {%0,%1,%2,%3};"
                 : "+f"(d[0]), "+f"(d[1]), "+f"(d[2]), "+f"(d[3])
                 : "r"(a[0]), "r"(a[1]), "r"(a[2]), "r"(a[3]), "r"(b0), "r"(b1));
}

// ---------------------------------------------------------------------------
// Weight conversion: W[K,N] f32 -> bf16 hi/lo in m16n8k16 B-fragment layout.
// ---------------------------------------------------------------------------
__device__ __forceinline__ void wconv_one(const float* __restrict__ W,
                                          __nv_bfloat16* __restrict__ d16,
                                          int K, int N, int start, int stride)
{
    const int KST = K >> 4;
    const int loOff = K * N;
    for (int i = start; i < K * N; i += stride) {
        int k = i / N, n = i % N;
        float v = W[i];
        __nv_bfloat16 h = __float2bfloat16_rn(v);
        __nv_bfloat16 l = __float2bfloat16_rn(v - __bfloat162float(h));
        int ks = k >> 4, kin = k & 15, n8 = n >> 3, nin = n & 7;
        int lane = nin * 4 + ((kin & 7) >> 1);
        int reg  = kin >> 3;
        int half = kin & 1;
        int idx16 = ((((n8 * KST + ks) * 32 + lane) * 2 + reg) << 1) + half;
        d16[idx16] = h;
        d16[loOff + idx16] = l;
    }
}

struct W9 { const float* s[9]; unsigned off[9]; };

__global__ void wconv9_kernel(W9 w, char* base)
{
    const int wi = blockIdx.y;
    wconv_one(w.s[wi], (__nv_bfloat16*)(base + w.off[wi]), 128, 128,
              threadIdx.x + blockIdx.x * 256, 256 * gridDim.x);
}

struct W2 { const float* s[2]; unsigned off[2]; int K[2]; int N[2]; };

__global__ void wconv2_kernel(W2 w, char* base)
{
    const int wi = blockIdx.y;
    wconv_one(w.s[wi], (__nv_bfloat16*)(base + w.off[wi]), w.K[wi], w.N[wi],
              threadIdx.x + blockIdx.x * 256, 256 * gridDim.x);
}

// ---------------------------------------------------------------------------
// A staging: MT rows of f32 global -> bf16 hi/lo smem (row stride K+8 elems)
// ---------------------------------------------------------------------------
template<int K>
__device__ __forceinline__ void stage_A(const float* __restrict__ A, size_t rowBase,
                                        char* AhiB, char* AloB, int tid)
{
    constexpr int LDA = K + 8;
    const float4* Ab = (const float4*)(A + rowBase * K);
    constexpr int NF4 = MT * K / 4;
    #pragma unroll 4
    for (int i = tid; i < NF4; i += 256) {
        int r  = i / (K / 4);
        int c4 = (i % (K / 4)) * 4;
        float4 v = Ab[i];
        __nv_bfloat162 h01, h23, l01, l23;
        h01.x = __float2bfloat16_rn(v.x);
        h01.y = __float2bfloat16_rn(v.y);
        h23.x = __float2bfloat16_rn(v.z);
        h23.y = __float2bfloat16_rn(v.w);
        l01.x = __float2bfloat16_rn(v.x - __bfloat162float(h01.x));
        l01.y = __float2bfloat16_rn(v.y - __bfloat162float(h01.y));
        l23.x = __float2bfloat16_rn(v.z - __bfloat162float(h23.x));
        l23.y = __float2bfloat16_rn(v.w - __bfloat162float(h23.y));
        uint2 hv, lv;
        hv.x = *(uint32_t*)&h01; hv.y = *(uint32_t*)&h23;
        lv.x = *(uint32_t*)&l01; lv.y = *(uint32_t*)&l23;
        size_t off = (size_t)r * LDA * 2 + (size_t)c4 * 2;
        *(uint2*)(AhiB + off) = hv;
        *(uint2*)(AloB + off) = lv;
    }
}

// ---------------------------------------------------------------------------
// 3-term MMA mainloop. Warp tile = 16 rows x NW cols (NW/8 fragments).
// ---------------------------------------------------------------------------
template<int NW, int N, int K>
__device__ __forceinline__ void run_mma(float (&acc)[NW / 8][4],
                                        uint32_t aHiAddr, uint32_t aLoAddr,
                                        const uint32_t* __restrict__ Bpre,
                                        int lane, int n8base)
{
    constexpr int KST = K / 16;
    constexpr int NF  = NW / 8;
    constexpr int BTERM = N * K / 2;

    #pragma unroll
    for (int term = 0; term < 3; term++) {
        const uint32_t aBase = (term == 2) ? aLoAddr : aHiAddr;
        const uint32_t* Bp = Bpre + ((term == 1) ? BTERM : 0);
        #pragma unroll
        for (int ks = 0; ks < KST; ks++) {
            uint2 b[NF];
            #pragma unroll
            for (int j = 0; j < NF; j++)
                b[j] = *(const uint2*)(Bp + (((size_t)(n8base + j) * KST + ks) * 32 + lane) * 2);
            uint32_t a0[4];
            ldm_x4(a0, aBase + ks * 32);
            #pragma unroll
            for (int j = 0; j < NF; j++)
                mma_bf16(acc[j], a0, b[j].x, b[j].y);
        }
    }
}

template<int NW>
__device__ __forceinline__ void zero_acc(float (&acc)[NW / 8][4])
{
    #pragma unroll
    for (int j = 0; j < NW / 8; j++)
        #pragma unroll
        for (int q = 0; q < 4; q++) acc[j][q] = 0.0f;
}

// ---------------------------------------------------------------------------
// HMMA GEMM: C[E x N] = epilogue(A[E x K] @ W[K x N]), fp32 in/out.
// CTA: 32 rows, 8 warps: (wid&1)->16-row band, (wid>>1)->col quarter.
// ---------------------------------------------------------------------------
template<int N, int K, int MODE>
__global__ __launch_bounds__(256, 3) void mma_gemm(
    const float*    __restrict__ A,
    const uint32_t* __restrict__ Bpre,
    const float*    __restrict__ bias,
    const float*    __restrict__ extra,
    float*          __restrict__ C)
{
    constexpr int NW   = N / 4;          // cols per warp
    constexpr int NF   = NW / 8;
    constexpr int LDA  = K + 8;
    constexpr int ABYT = MT * LDA * 2;

    extern __shared__ __align__(16) char smem[];
    float* sbias = (float*)smem;
    char*  AhiB  = smem + 1024;
    char*  AloB  = AhiB + ABYT;

    const int tid = threadIdx.x, wid = tid >> 5, lane = tid & 31;
    const size_t rowBase = (size_t)blockIdx.x * MT;

    if (bias)
        for (int i = tid; i < N; i += 256) sbias[i] = bias[i];

    stage_A<K>(A, rowBase, AhiB, AloB, tid);
    __syncthreads();

    const int warpM = (wid & 1) * 16;
    const int warpN = (wid >> 1) * NW;
    const int n8base = warpN >> 3;

    float acc[NF][4];
    zero_acc<NW>(acc);

    const uint32_t aHiAddr = smem_u32(AhiB) +
        (uint32_t)(warpM + (lane & 15)) * (LDA * 2) + (uint32_t)(lane >> 4) * 16;
    const uint32_t aLoAddr = aHiAddr + (uint32_t)ABYT;

    run_mma<NW, N, K>(acc, aHiAddr, aLoAddr, Bpre, lane, n8base);

    const int r0 = lane >> 2;
    const int c0 = (lane & 3) * 2;

    {
        const size_t gA = rowBase + warpM + r0;
        const size_t gB = gA + 8;

        #pragma unroll
        for (int j = 0; j < NF; j++) {
            const int col = warpN + j * 8 + c0;
            float v0 = acc[j][0], v1 = acc[j][1];
            float v2 = acc[j][2], v3 = acc[j][3];
            if (bias) {
                float b0 = sbias[col], b1 = sbias[col + 1];
                v0 += b0; v1 += b1; v2 += b0; v3 += b1;
            }
            v0 = swishf(v0); v1 = swishf(v1);
            v2 = swishf(v2); v3 = swishf(v3);
            if (MODE == EP_SWISH_ADD) {
                float2 eA = *(const float2*)(extra + gA * N + col);
                float2 eB = *(const float2*)(extra + gB * N + col);
                v0 += eA.x; v1 += eA.y; v2 += eB.x; v3 += eB.y;
            }
            *(float2*)(C + gA * N + col) = make_float2(v0, v1);
            *(float2*)(C + gB * N + col) = make_float2(v2, v3);
        }
    }
}

// ---------------------------------------------------------------------------
// Edge mega-fusion (K=128, one A staging for three GEMMs):
//   m_pre = swish(m_input @ W_ji + b_ji)                 -> g_m
//   h1    = swish(m_input @ W_kj + b_kj) * (rbf8 @ Wg)   -> A smem (bf16)
//   ang   = swish(h1 @ W_down)                           -> g_ang
// ---------------------------------------------------------------------------
__global__ __launch_bounds__(256, 3) void edge_fused(
    const float*    __restrict__ m_input,
    const uint32_t* __restrict__ Bji, const float* __restrict__ bji,
    const uint32_t* __restrict__ Bkj, const float* __restrict__ bkj,
    const uint32_t* __restrict__ Bdown,
    const float*    __restrict__ Wg,    // [8 x 128] f32
    const float*    __restrict__ rbf8,  // [E x 8]
    float*          __restrict__ m_pre,
    float*          __restrict__ ang)
{
    constexpr int K = 128, N = 128;
    constexpr int NW   = N / 4;          // 32
    constexpr int NF   = NW / 8;         // 4
    constexpr int LDA  = K + 8;
    constexpr int LDA2 = LDA * 2;
    constexpr int ABYT = MT * LDA * 2;

    extern __shared__ __align__(16) char smem[];
    float* sbji = (float*)smem;              // 512 B
    float* sbkj = (float*)(smem + 512);      // 512 B
    float* sWg  = (float*)(smem + 1024);     // 4 KB
    char*  AhiB = smem + 5120;
    char*  AloB = AhiB + ABYT;

    const int tid = threadIdx.x, wid = tid >> 5, lane = tid & 31;
    const size_t rowBase = (size_t)blockIdx.x * MT;

    for (int i = tid; i < N; i += 256) { sbji[i] = bji[i]; sbkj[i] = bkj[i]; }
    for (int i = tid; i < 8 * N; i += 256) sWg[i] = Wg[i];

    stage_A<K>(m_input, rowBase, AhiB, AloB, tid);
    __syncthreads();

    const int warpM = (wid & 1) * 16;
    const int warpN = (wid >> 1) * NW;
    const int n8base = warpN >> 3;

    const uint32_t aHiAddr = smem_u32(AhiB) +
        (uint32_t)(warpM + (lane & 15)) * LDA2 + (uint32_t)(lane >> 4) * 16;
    const uint32_t aLoAddr = aHiAddr + (uint32_t)ABYT;

    const int r0 = lane >> 2;
    const int c0 = (lane & 3) * 2;

    float acc[NF][4];

    // ---- GEMM 1: W_ji -> m_pre ----
    zero_acc<NW>(acc);
    run_mma<NW, N, K>(acc, aHiAddr, aLoAddr, Bji, lane, n8base);
    {
        const size_t gA = rowBase + warpM + r0;
        const size_t gB = gA + 8;
        #pragma unroll
        for (int j = 0; j < NF; j++) {
            const int col = warpN + j * 8 + c0;
            float b0 = sbji[col], b1 = sbji[col + 1];
            *(float2*)(m_pre + gA * N + col) =
                make_float2(swishf(acc[j][0] + b0), swishf(acc[j][1] + b1));
            *(float2*)(m_pre + gB * N + col) =
                make_float2(swishf(acc[j][2] + b0), swishf(acc[j][3] + b1));
        }
    }

    // ---- GEMM 2: W_kj + rbf gate -> h1 into A smem ----
    zero_acc<NW>(acc);
    run_mma<NW, N, K>(acc, aHiAddr, aLoAddr, Bkj, lane, n8base);
    __syncthreads();   // everyone done reading A before overwrite

    {
        const int rowA = warpM + r0;
        const int rowB = rowA + 8;
        const size_t gA = rowBase + rowA;
        const size_t gB = rowBase + rowB;

        float r8A[8], r8B[8];
        {
            float4 a0 = *(const float4*)(rbf8 + gA * 8);
            float4 a1 = *(const float4*)(rbf8 + gA * 8 + 4);
            float4 b0 = *(const float4*)(rbf8 + gB * 8);
            float4 b1 = *(const float4*)(rbf8 + gB * 8 + 4);
            r8A[0]=a0.x; r8A[1]=a0.y; r8A[2]=a0.z; r8A[3]=a0.w;
            r8A[4]=a1.x; r8A[5]=a1.y; r8A[6]=a1.z; r8A[7]=a1.w;
            r8B[0]=b0.x; r8B[1]=b0.y; r8B[2]=b0.z; r8B[3]=b0.w;
            r8B[4]=b1.x; r8B[5]=b1.y; r8B[6]=b1.z; r8B[7]=b1.w;
        }

        #pragma unroll
        for (int j = 0; j < NF; j++) {
            const int col = warpN + j * 8 + c0;
            float b0 = sbkj[col], b1 = sbkj[col + 1];
            float v0 = swishf(acc[j][0] + b0);
            float v1 = swishf(acc[j][1] + b1);
            float v2 = swishf(acc[j][2] + b0);
            float v3 = swishf(acc[j][3] + b1);
            float gA0 = 0.f, gA1 = 0.f, gB0 = 0.f, gB1 = 0.f;
            #pragma unroll
            for (int b = 0; b < 8; b++) {
                float w0 = sWg[b * N + col], w1 = sWg[b * N + col + 1];
                gA0 = fmaf(r8A[b], w0, gA0);
                gA1 = fmaf(r8A[b], w1, gA1);
                gB0 = fmaf(r8B[b], w0, gB0);
                gB1 = fmaf(r8B[b], w1, gB1);
            }
            v0 *= gA0; v1 *= gA1; v2 *= gB0; v3 *= gB1;

            __nv_bfloat162 h, l;
            h.x = __float2bfloat16_rn(v0);
            h.y = __float2bfloat16_rn(v1);
            l.x = __float2bfloat16_rn(v0 - __bfloat162float(h.x));
            l.y = __float2bfloat16_rn(v1 - __bfloat162float(h.y));
            *(__nv_bfloat162*)(AhiB + rowA * LDA2 + col * 2) = h;
            *(__nv_bfloat162*)(AloB + rowA * LDA2 + col * 2) = l;
            h.x = __float2bfloat16_rn(v2);
            h.y = __float2bfloat16_rn(v3);
            l.x = __float2bfloat16_rn(v2 - __bfloat162float(h.x));
            l.y = __float2bfloat16_rn(v3 - __bfloat162float(h.y));
            *(__nv_bfloat162*)(AhiB + rowB * LDA2 + col * 2) = h;
            *(__nv_bfloat162*)(AloB + rowB * LDA2 + col * 2) = l;
        }
    }
    __syncthreads();

    // ---- GEMM 3: W_down (N=64) -> ang ----
    {
        constexpr int N2 = 64;
        constexpr int NW2 = N2 / 4;     // 16
        constexpr int NF2 = NW2 / 8;    // 2
        float acc2[NF2][4];
        zero_acc<NW2>(acc2);
        const int warpN2 = (wid >> 1) * NW2;
        run_mma<NW2, N2, K>(acc2, aHiAddr, aLoAddr, Bdown, lane, warpN2 >> 3);

        const size_t gA = rowBase + warpM + r0;
        const size_t gB = gA + 8;
        #pragma unroll
        for (int j = 0; j < NF2; j++) {
            const int col = warpN2 + j * 8 + c0;
            *(float2*)(ang + gA * N2 + col) =
                make_float2(swishf(acc2[j][0]), swishf(acc2[j][1]));
            *(float2*)(ang + gB * N2 + col) =
                make_float2(swishf(acc2[j][2]), swishf(acc2[j][3]));
        }
    }
}

// ---------------------------------------------------------------------------
// Fused residual block: C = X + swish(swish(X@W0+b0)@W1+b1)   (N=K=128)
// ---------------------------------------------------------------------------
__global__ __launch_bounds__(256, 3) void fused_res(
    const float*    __restrict__ X,
    const uint32_t* __restrict__ B0, const float* __restrict__ bias0,
    const uint32_t* __restrict__ B1, const float* __restrict__ bias1,
    float*          __restrict__ C)
{
    constexpr int N = 128, K = 128;
    constexpr int NW   = N / 4;
    constexpr int NF   = NW / 8;
    constexpr int LDA  = K + 8;
    constexpr int LDA2 = LDA * 2;
    constexpr int ABYT = MT * LDA * 2;

    extern __shared__ __align__(16) char smem[];
    float* sb0  = (float*)smem;
    float* sb1  = (float*)(smem + 512);
    char*  AhiB = smem + 1024;
    char*  AloB = AhiB + ABYT;

    const int tid = threadIdx.x, wid = tid >> 5, lane = tid & 31;
    const size_t rowBase = (size_t)blockIdx.x * MT;

    for (int i = tid; i < N; i += 256) { sb0[i] = bias0[i]; sb1[i] = bias1[i]; }

    stage_A<K>(X, rowBase, AhiB, AloB, tid);
    __syncthreads();

    const int warpM = (wid & 1) * 16;
    const int warpN = (wid >> 1) * NW;
    const int n8base = warpN >> 3;

    float acc[NF][4];
    zero_acc<NW>(acc);

    const uint32_t aHiAddr = smem_u32(AhiB) +
        (uint32_t)(warpM + (lane & 15)) * LDA2 + (uint32_t)(lane >> 4) * 16;
    const uint32_t aLoAddr = aHiAddr + (uint32_t)ABYT;

    run_mma<NW, N, K>(acc, aHiAddr, aLoAddr, B0, lane, n8base);
    __syncthreads();

    const int r0 = lane >> 2;
    const int c0 = (lane & 3) * 2;

    {
        const int rowA = warpM + r0;
        const int rowB = rowA + 8;
        #pragma unroll
        for (int j = 0; j < NF; j++) {
            const int col = warpN + j * 8 + c0;
            float b0 = sb0[col], b1 = sb0[col + 1];
            float v0 = swishf(acc[j][0] + b0);
            float v1 = swishf(acc[j][1] + b1);
            float v2 = swishf(acc[j][2] + b0);
            float v3 = swishf(acc[j][3] + b1);
            acc[j][0] = 0.f; acc[j][1] = 0.f;
            acc[j][2] = 0.f; acc[j][3] = 0.f;

            __nv_bfloat162 h, l;
            h.x = __float2bfloat16_rn(v0);
            h.y = __float2bfloat16_rn(v1);
            l.x = __float2bfloat16_rn(v0 - __bfloat162float(h.x));
            l.y = __float2bfloat16_rn(v1 - __bfloat162float(h.y));
            *(__nv_bfloat162*)(AhiB + rowA * LDA2 + col * 2) = h;
            *(__nv_bfloat162*)(AloB + rowA * LDA2 + col * 2) = l;
            h.x = __float2bfloat16_rn(v2);
            h.y = __float2bfloat16_rn(v3);
            l.x = __float2bfloat16_rn(v2 - __bfloat162float(h.x));
            l.y = __float2bfloat16_rn(v3 - __bfloat162float(h.y));
            *(__nv_bfloat162*)(AhiB + rowB * LDA2 + col * 2) = h;
            *(__nv_bfloat162*)(AloB + rowB * LDA2 + col * 2) = l;
        }
    }
    __syncthreads();

    run_mma<NW, N, K>(acc, aHiAddr, aLoAddr, B1, lane, n8base);

    {
        const size_t gA = rowBase + warpM + r0;
        const size_t gB = gA + 8;
        #pragma unroll
        for (int j = 0; j < NF; j++) {
            const int col = warpN + j * 8 + c0;
            float b0 = sb1[col], b1 = sb1[col + 1];
            float v0 = swishf(acc[j][0] + b0);
            float v1 = swishf(acc[j][1] + b1);
            float v2 = swishf(acc[j][2] + b0);
            float v3 = swishf(acc[j][3] + b1);
            float2 xA = *(const float2*)(X + gA * N + col);
            float2 xB = *(const float2*)(X + gB * N + col);
            *(float2*)(C + gA * N + col) = make_float2(xA.x + v0, xA.y + v1);
            *(float2*)(C + gB * N + col) = make_float2(xB.x + v2, xB.y + v3);
        }
    }
}

// ---------------------------------------------------------------------------
// proj8: out[rows x 8] = X[rows x NIN] @ W[NIN x 8]
// ---------------------------------------------------------------------------
template<int NIN>
__global__ __launch_bounds__(256) void proj8_kernel(
    const float* __restrict__ X, const float* __restrict__ W,
    float* __restrict__ out)
{
    __shared__ float tile[256 * NIN];
    __shared__ float Ws[NIN * 8];
    const size_t base = (size_t)blockIdx.x * 256;
    constexpr int NT4 = 256 * NIN / 4;
    const float4* src = (const float4*)(X + base * NIN);
    #pragma unroll 4
    for (int i = threadIdx.x; i < NT4; i += 256)
        ((float4*)tile)[i] = src[i];
    for (int i = threadIdx.x; i < NIN * 8; i += 256)
        Ws[i] = W[i];
    __syncthreads();

    const float* x = &tile[threadIdx.x * NIN];
    float o[8] = {0, 0, 0, 0, 0, 0, 0, 0};
    #pragma unroll
    for (int c = 0; c < NIN; c++) {
        float xv = x[c];
        #pragma unroll
        for (int b = 0; b < 8; b++)
            o[b] = fmaf(xv, Ws[c * 8 + b], o[b]);
    }
    float4* op = (float4*)(out + (base + threadIdx.x) * 8);
    op[0] = make_float4(o[0], o[1], o[2], o[3]);
    op[1] = make_float4(o[4], o[5], o[6], o[7]);
}

__global__ void zero_kernel(float4* __restrict__ p, size_t n4)
{
    size_t i = (size_t)blockIdx.x * blockDim.x + threadIdx.x;
    if (i < n4) p[i] = make_float4(0.f, 0.f, 0.f, 0.f);
}

// ---------------------------------------------------------------------------
// Triplet gather/gate/scatter -- 2 triplets per 16-lane group (MLP=2)
// ---------------------------------------------------------------------------
__global__ __launch_bounds__(256, 8) void triplet_kernel(
    const int* __restrict__ expand_to_kj,
    const int* __restrict__ reduce_to_ji,
    const float* __restrict__ sbf8,
    const float* __restrict__ Wsbf2,
    const float* __restrict__ ang,
    float* __restrict__ agg)
{
    __shared__ float Ws[8 * 64];
    for (int i = threadIdx.x; i < 512; i += 256) Ws[i] = Wsbf2[i];
    __syncthreads();

    const int lane16 = threadIdx.x & 15;
    const size_t grp = ((size_t)blockIdx.x * 256 + threadIdx.x) >> 4;
    const size_t t0 = grp * 2;
    const size_t t1 = t0 + 1;

    const int ekj0 = __ldg(&expand_to_kj[t0]);
    const int ekj1 = __ldg(&expand_to_kj[t1]);
    const int eji0 = __ldg(&reduce_to_ji[t0]);
    const int eji1 = __ldg(&reduce_to_ji[t1]);

    float4 a0 = __ldg((const float4*)(ang + (size_t)ekj0 * 64 + lane16 * 4));
    float4 a1 = __ldg((const float4*)(ang + (size_t)ekj1 * 64 + lane16 * 4));

    const float* s0 = sbf8 + t0 * 8;
    const float* s1 = sbf8 + t1 * 8;

    float g00 = 0.f, g01 = 0.f, g02 = 0.f, g03 = 0.f;
    float g10 = 0.f, g11 = 0.f, g12 = 0.f, g13 = 0.f;
    #pragma unroll
    for (int b = 0; b < 8; b++) {
        const float sb0 = __ldg(&s0[b]);
        const float sb1 = __ldg(&s1[b]);
        const float* w = &Ws[b * 64 + lane16 * 4];
        float w0 = w[0], w1 = w[1], w2 = w[2], w3 = w[3];
        g00 = fmaf(sb0, w0, g00); g01 = fmaf(sb0, w1, g01);
        g02 = fmaf(sb0, w2, g02); g03 = fmaf(sb0, w3, g03);
        g10 = fmaf(sb1, w0, g10); g11 = fmaf(sb1, w1, g11);
        g12 = fmaf(sb1, w2, g12); g13 = fmaf(sb1, w3, g13);
    }

    float v00 = a0.x * g00, v01 = a0.y * g01, v02 = a0.z * g02, v03 = a0.w * g03;
    float v10 = a1.x * g10, v11 = a1.y * g11, v12 = a1.z * g12, v13 = a1.w * g13;

    float* d0 = agg + (size_t)eji0 * 64 + lane16 * 4;
    float* d1 = agg + (size_t)eji1 * 64 + lane16 * 4;
    asm volatile("red.global.add.v4.f32 [%0], {%1,%2,%3,%4};"
                 :: "l"(d0), "f"(v00), "f"(v01), "f"(v02), "f"(v03) : "memory");
    asm volatile("red.global.add.v4.f32 [%0], {%1,%2,%3,%4};"
                 :: "l"(d1), "f"(v10), "f"(v11), "f"(v12), "f"(v13) : "memory");
}

// ---------------------------------------------------------------------------
// Host orchestration
// ---------------------------------------------------------------------------
static inline int gemm_smem(int K)  { return 1024 + 2 * (MT * (K + 8) * 2); }
static inline int edge_smemsz()     { return 5120 + 2 * (MT * 136 * 2); }

extern "C" void kernel_launch(void* const* d_in, const int* in_sizes, int n_in,
                              void* d_out, int out_size)
{
    const float* m_input = (const float*)d_in[0];
    const float* rbf     = (const float*)d_in[1];
    const float* sbf     = (const float*)d_in[2];
    const int*   expand  = (const int*)  d_in[3];
    const int*   reduce  = (const int*)  d_in[4];
    const float* W_kj    = (const float*)d_in[5];
    const float* b_kj    = (const float*)d_in[6];
    const float* W_rbf1  = (const float*)d_in[7];
    const float* W_rbf2  = (const float*)d_in[8];
    const float* W_sbf1  = (const float*)d_in[9];
    const float* W_sbf2  = (const float*)d_in[10];
    const float* W_down  = (const float*)d_in[11];
    const float* W_up    = (const float*)d_in[12];
    const float* W_ji    = (const float*)d_in[13];
    const float* b_ji    = (const float*)d_in[14];
    const float* W_res_b = (const float*)d_in[15];
    const float* b_res_b = (const float*)d_in[16];
    const float* W_final = (const float*)d_in[17];
    const float* b_final = (const float*)d_in[18];
    const float* W_res_a = (const float*)d_in[19];
    const float* b_res_a = (const float*)d_in[20];
    float* out = (float*)d_out;

    const int E = in_sizes[0] / 128;
    const int T = in_sizes[3];

    float *h1, *ang, *agg, *t, *m, *rbf8, *sbf8, *wb;
    cudaGetSymbolAddress((void**)&h1,   g_h1);
    cudaGetSymbolAddress((void**)&ang,  g_ang);
    cudaGetSymbolAddress((void**)&agg,  g_agg);
    cudaGetSymbolAddress((void**)&t,    g_t);
    cudaGetSymbolAddress((void**)&m,    g_m);
    cudaGetSymbolAddress((void**)&rbf8, g_rbf8);
    cudaGetSymbolAddress((void**)&sbf8, g_sbf8);
    cudaGetSymbolAddress((void**)&wb,   g_wb);

    cudaFuncSetAttribute(mma_gemm<128, 128, EP_SWISH_ADD>,
                         cudaFuncAttributeMaxDynamicSharedMemorySize, gemm_smem(128));
    cudaFuncSetAttribute(mma_gemm<128, 64, EP_SWISH_ADD>,
                         cudaFuncAttributeMaxDynamicSharedMemorySize, gemm_smem(64));
    cudaFuncSetAttribute(edge_fused,
                         cudaFuncAttributeMaxDynamicSharedMemorySize, edge_smemsz());
    cudaFuncSetAttribute(fused_res,
                         cudaFuncAttributeMaxDynamicSharedMemorySize, gemm_smem(128));

    char* wbb = (char*)wb;
    auto wat = [&](size_t off) { return (const uint32_t*)(wbb + off); };
    const unsigned OF_KJ = 0, OF_JI = 65536, OF_RB0 = 131072, OF_RB1 = 196608,
                   OF_FIN = 262144, OF_RA00 = 327680, OF_RA01 = 393216,
                   OF_RA10 = 458752, OF_RA11 = 524288,
                   OF_DOWN = 589824, OF_UP = 622592;

    // 0-1: weight conversion
    {
        W9 w;
        w.s[0] = W_kj;            w.off[0] = OF_KJ;
        w.s[1] = W_ji;            w.off[1] = OF_JI;
        w.s[2] = W_res_b;         w.off[2] = OF_RB0;
        w.s[3] = W_res_b + 16384; w.off[3] = OF_RB1;
        w.s[4] = W_final;         w.off[4] = OF_FIN;
        w.s[5] = W_res_a;         w.off[5] = OF_RA00;
        w.s[6] = W_res_a + 16384; w.off[6] = OF_RA01;
        w.s[7] = W_res_a + 32768; w.off[7] = OF_RA10;
        w.s[8] = W_res_a + 49152; w.off[8] = OF_RA11;
        wconv9_kernel<<<dim3(8, 9), 256>>>(w, wbb);

        W2 w2;
        w2.s[0] = W_down; w2.off[0] = OF_DOWN; w2.K[0] = 128; w2.N[0] = 64;
        w2.s[1] = W_up;   w2.off[1] = OF_UP;   w2.K[1] = 64;  w2.N[1] = 128;
        wconv2_kernel<<<dim3(8, 2), 256>>>(w2, wbb);
    }

    const int GE = E / MT;   // 8192

    // 2: rbf8 = rbf @ W_rbf1
    proj8_kernel<6><<<E / 256, 256>>>(rbf, W_rbf1, rbf8);

    // 3: edge fusion: m_pre -> g_m, ang -> g_ang    [ncu idx 3 -> GEMM profile]
    edge_fused<<<GE, 256, edge_smemsz()>>>(
        m_input, wat(OF_JI), b_ji, wat(OF_KJ), b_kj, wat(OF_DOWN),
        W_rbf2, rbf8, m, ang);

    // 4: sbf8
    proj8_kernel<42><<<T / 256, 256>>>(sbf, W_sbf1, sbf8);

    // 5: agg = 0
    {
        size_t n4 = (size_t)E * 64 / 4;
        zero_kernel<<<(unsigned)((n4 + 255) / 256), 256>>>((float4*)agg, n4);
    }

    // 6: scatter (2 triplets per 16-lane group)
    triplet_kernel<<<(unsigned)((size_t)T * 16 / 256 / 2), 256>>>(
        expand, reduce, sbf8, W_sbf2, ang, agg);

    // 7: t = swish(agg @ W_up) + m_pre
    mma_gemm<128, 64, EP_SWISH_ADD><<<GE, 256, gemm_smem(64)>>>(
        agg, wat(OF_UP), nullptr, m, t);

    // 8: h1 = t + f(f(t))                (residual block before skip)
    fused_res<<<GE, 256, gemm_smem(128)>>>(
        t, wat(OF_RB0), b_res_b, wat(OF_RB1), b_res_b + 128, h1);

    // 9: m = swish(h1 @ W_final + b_final) + m_input
    mma_gemm<128, 128, EP_SWISH_ADD><<<GE, 256, gemm_smem(128)>>>(
        h1, wat(OF_FIN), b_final, m_input, m);

    // 10: t = m + f(f(m))                (residual after skip, layer 1)
    fused_res<<<GE, 256, gemm_smem(128)>>>(
        m, wat(OF_RA00), b_res_a, wat(OF_RA01), b_res_a + 128, t);

    // 11: out = t + f(f(t))              (residual after skip, layer 2)
    fused_res<<<GE, 256, gemm_smem(128)>>>(
        t, wat(OF_RA10), b_res_a + 256, wat(OF_RA11), b_res_a + 384, out);
}

// round 12
// speedup vs baseline: 1.2219x; 1.2219x over previous
#include <cuda_runtime.h>
#include <cuda_bf16.h>
#include <cstdint>

// ---------------------------------------------------------------------------
// Problem constants
// ---------------------------------------------------------------------------
#define E_MAX 262144
#define T_MAX 2097152
#define MT    64          // rows per CTA tile

// ---------------------------------------------------------------------------
// Scratch (device globals -- no allocation allowed)
// ---------------------------------------------------------------------------
__device__ float g_h1  [(size_t)E_MAX * 128];
__device__ float g_ang [(size_t)E_MAX * 64];
__device__ float g_agg [(size_t)E_MAX * 64];
__device__ float g_t   [(size_t)E_MAX * 128];
__device__ float g_m   [(size_t)E_MAX * 128];
__device__ float g_rbf8[(size_t)E_MAX * 8];
__device__ float g_sbf8[(size_t)T_MAX * 8];
__device__ float g_wb  [163840];   // 640KB: bf16 hi/lo weight fragments

__device__ __forceinline__ float swishf(float v) { return v / (1.0f + __expf(-v)); }

__device__ __forceinline__ uint32_t smem_u32(const void* p) {
    uint32_t a;
    asm("{ .reg .u64 t; cvta.to.shared.u64 t, %1; cvt.u32.u64 %0, t; }"
        : "=r"(a) : "l"(p));
    return a;
}

__device__ __forceinline__ void ldm_x4(uint32_t* r, uint32_t addr) {
    asm volatile("ldmatrix.sync.aligned.m8n8.x4.shared.b16 {%0,%1,%2,%3}, [%4];"
                 : "=r"(r[0]), "=r"(r[1]), "=r"(r[2]), "=r"(r[3]) : "r"(addr));
}

__device__ __forceinline__ void mma_bf16(float* d, const uint32_t* a, uint32_t b0, uint32_t b1) {
    asm volatile("mma.sync.aligned.m16n8k16.row.col.f32.bf16.bf16.f32 "
                 "{%0,%1,%2,%3}, {%4,%5,%6,%7}, {%8,%9}, {%0,%1,%2,%3};"
                 : "+f"(d[0]), "+f"(d[1]), "+f"(d[2]), "+f"(d[3])
                 : "r"(a[0]), "r"(a[1]), "r"(a[2]), "r"(a[3]), "r"(b0), "r"(b1));
}

// ---------------------------------------------------------------------------
// Weight conversion: W[K,N] f32 -> bf16 hi/lo in m16n8k16 B-fragment layout.
// ---------------------------------------------------------------------------
__device__ __forceinline__ void wconv_one(const float* __restrict__ W,
                                          __nv_bfloat16* __restrict__ d16,
                                          int K, int N, int start, int stride)
{
    const int KST = K >> 4;
    const int loOff = K * N;
    for (int i = start; i < K * N; i += stride) {
        int k = i / N, n = i % N;
        float v = W[i];
        __nv_bfloat16 h = __float2bfloat16_rn(v);
        __nv_bfloat16 l = __float2bfloat16_rn(v - __bfloat162float(h));
        int ks = k >> 4, kin = k & 15, n8 = n >> 3, nin = n & 7;
        int lane = nin * 4 + ((kin & 7) >> 1);
        int reg  = kin >> 3;
        int half = kin & 1;
        int idx16 = ((((n8 * KST + ks) * 32 + lane) * 2 + reg) << 1) + half;
        d16[idx16] = h;
        d16[loOff + idx16] = l;
    }
}

struct W9 { const float* s[9]; unsigned off[9]; };

__global__ void wconv9_kernel(W9 w, char* base)
{
    const int wi = blockIdx.y;
    wconv_one(w.s[wi], (__nv_bfloat16*)(base + w.off[wi]), 128, 128,
              threadIdx.x + blockIdx.x * 256, 256 * gridDim.x);
}

struct W2 { const float* s[2]; unsigned off[2]; int K[2]; int N[2]; };

__global__ void wconv2_kernel(W2 w, char* base)
{
    const int wi = blockIdx.y;
    wconv_one(w.s[wi], (__nv_bfloat16*)(base + w.off[wi]), w.K[wi], w.N[wi],
              threadIdx.x + blockIdx.x * 256, 256 * gridDim.x);
}

// ---------------------------------------------------------------------------
// A staging: MT rows of f32 global -> bf16 hi/lo smem (row stride K+8 elems)
// ---------------------------------------------------------------------------
template<int K>
__device__ __forceinline__ void stage_A(const float* __restrict__ A, size_t rowBase,
                                        char* AhiB, char* AloB, int tid)
{
    constexpr int LDA = K + 8;
    const float4* Ab = (const float4*)(A + rowBase * K);
    constexpr int NF4 = MT * K / 4;
    #pragma unroll 4
    for (int i = tid; i < NF4; i += 256) {
        int r  = i / (K / 4);
        int c4 = (i % (K / 4)) * 4;
        float4 v = Ab[i];
        __nv_bfloat162 h01, h23, l01, l23;
        h01.x = __float2bfloat16_rn(v.x);
        h01.y = __float2bfloat16_rn(v.y);
        h23.x = __float2bfloat16_rn(v.z);
        h23.y = __float2bfloat16_rn(v.w);
        l01.x = __float2bfloat16_rn(v.x - __bfloat162float(h01.x));
        l01.y = __float2bfloat16_rn(v.y - __bfloat162float(h01.y));
        l23.x = __float2bfloat16_rn(v.z - __bfloat162float(h23.x));
        l23.y = __float2bfloat16_rn(v.w - __bfloat162float(h23.y));
        uint2 hv, lv;
        hv.x = *(uint32_t*)&h01; hv.y = *(uint32_t*)&h23;
        lv.x = *(uint32_t*)&l01; lv.y = *(uint32_t*)&l23;
        size_t off = (size_t)r * LDA * 2 + (size_t)c4 * 2;
        *(uint2*)(AhiB + off) = hv;
        *(uint2*)(AloB + off) = lv;
    }
}

// ---------------------------------------------------------------------------
// 3-term MMA mainloop. Warp tile = 16 rows x (N/2) cols.  (R10-proven)
// ---------------------------------------------------------------------------
template<int N, int K>
__device__ __forceinline__ void run_mma(float (&acc)[N / 16][4],
                                        uint32_t aHiAddr, uint32_t aLoAddr,
                                        const uint32_t* __restrict__ Bpre,
                                        int lane, int n8base)
{
    constexpr int KST = K / 16;
    constexpr int N8  = N / 16;
    constexpr int BTERM = N * K / 2;

    #pragma unroll
    for (int term = 0; term < 3; term++) {
        const uint32_t aBase = (term == 2) ? aLoAddr : aHiAddr;
        const uint32_t* Bp = Bpre + ((term == 1) ? BTERM : 0);
        #pragma unroll
        for (int ks = 0; ks < KST; ks++) {
            uint2 b[N8];
            #pragma unroll
            for (int j = 0; j < N8; j++)
                b[j] = *(const uint2*)(Bp + (((size_t)(n8base + j) * KST + ks) * 32 + lane) * 2);
            uint32_t a0[4];
            ldm_x4(a0, aBase + ks * 32);
            #pragma unroll
            for (int j = 0; j < N8; j++)
                mma_bf16(acc[j], a0, b[j].x, b[j].y);
        }
    }
}

template<int N>
__device__ __forceinline__ void zero_acc(float (&acc)[N / 16][4])
{
    #pragma unroll
    for (int j = 0; j < N / 16; j++)
        #pragma unroll
        for (int q = 0; q < 4; q++) acc[j][q] = 0.0f;
}

// helper: swish result -> bf16 hi/lo into A smem (one float2 pair per row)
__device__ __forceinline__ void store_hl(char* AhiB, char* AloB, int row, int col,
                                         float v0, float v1, int LDA2)
{
    __nv_bfloat162 h, l;
    h.x = __float2bfloat16_rn(v0);
    h.y = __float2bfloat16_rn(v1);
    l.x = __float2bfloat16_rn(v0 - __bfloat162float(h.x));
    l.y = __float2bfloat16_rn(v1 - __bfloat162float(h.y));
    *(__nv_bfloat162*)(AhiB + row * LDA2 + col * 2) = h;
    *(__nv_bfloat162*)(AloB + row * LDA2 + col * 2) = l;
}

// ---------------------------------------------------------------------------
// Edge mega-fusion (R10-proven, unchanged)
// ---------------------------------------------------------------------------
__global__ __launch_bounds__(256, 2) void edge_fused(
    const float*    __restrict__ m_input,
    const uint32_t* __restrict__ Bji, const float* __restrict__ bji,
    const uint32_t* __restrict__ Bkj, const float* __restrict__ bkj,
    const uint32_t* __restrict__ Bdown,
    const float*    __restrict__ Wg,
    const float*    __restrict__ rbf8,
    float*          __restrict__ m_pre,
    float*          __restrict__ ang)
{
    constexpr int K = 128, N = 128;
    constexpr int N8   = N / 16;
    constexpr int LDA  = K + 8;
    constexpr int LDA2 = LDA * 2;
    constexpr int ABYT = MT * LDA * 2;

    extern __shared__ __align__(16) char smem[];
    float* sbji = (float*)smem;
    float* sbkj = (float*)(smem + 512);
    float* sWg  = (float*)(smem + 1024);
    char*  AhiB = smem + 5120;
    char*  AloB = AhiB + ABYT;

    const int tid = threadIdx.x, wid = tid >> 5, lane = tid & 31;
    const size_t rowBase = (size_t)blockIdx.x * MT;

    for (int i = tid; i < N; i += 256) { sbji[i] = bji[i]; sbkj[i] = bkj[i]; }
    for (int i = tid; i < 8 * N; i += 256) sWg[i] = Wg[i];

    stage_A<K>(m_input, rowBase, AhiB, AloB, tid);
    __syncthreads();

    const int warpM = (wid & 3) * 16;
    const int warpN = (wid >> 2) * (N / 2);
    const int n8base = warpN >> 3;

    const uint32_t aHiAddr = smem_u32(AhiB) +
        (uint32_t)(warpM + (lane & 15)) * LDA2 + (uint32_t)(lane >> 4) * 16;
    const uint32_t aLoAddr = aHiAddr + (uint32_t)ABYT;

    const int r0 = lane >> 2;
    const int c0 = (lane & 3) * 2;

    float acc[N8][4];

    zero_acc<N>(acc);
    run_mma<N, K>(acc, aHiAddr, aLoAddr, Bji, lane, n8base);
    {
        const size_t gA = rowBase + warpM + r0;
        const size_t gB = gA + 8;
        #pragma unroll
        for (int j = 0; j < N8; j++) {
            const int col = warpN + j * 8 + c0;
            float b0 = sbji[col], b1 = sbji[col + 1];
            *(float2*)(m_pre + gA * N + col) =
                make_float2(swishf(acc[j][0] + b0), swishf(acc[j][1] + b1));
            *(float2*)(m_pre + gB * N + col) =
                make_float2(swishf(acc[j][2] + b0), swishf(acc[j][3] + b1));
        }
    }

    zero_acc<N>(acc);
    run_mma<N, K>(acc, aHiAddr, aLoAddr, Bkj, lane, n8base);
    __syncthreads();

    {
        const int rowA = warpM + r0;
        const int rowB = rowA + 8;
        const size_t gA = rowBase + rowA;
        const size_t gB = rowBase + rowB;

        float r8A[8], r8B[8];
        {
            float4 a0 = *(const float4*)(rbf8 + gA * 8);
            float4 a1 = *(const float4*)(rbf8 + gA * 8 + 4);
            float4 b0 = *(const float4*)(rbf8 + gB * 8);
            float4 b1 = *(const float4*)(rbf8 + gB * 8 + 4);
            r8A[0]=a0.x; r8A[1]=a0.y; r8A[2]=a0.z; r8A[3]=a0.w;
            r8A[4]=a1.x; r8A[5]=a1.y; r8A[6]=a1.z; r8A[7]=a1.w;
            r8B[0]=b0.x; r8B[1]=b0.y; r8B[2]=b0.z; r8B[3]=b0.w;
            r8B[4]=b1.x; r8B[5]=b1.y; r8B[6]=b1.z; r8B[7]=b1.w;
        }

        #pragma unroll
        for (int j = 0; j < N8; j++) {
            const int col = warpN + j * 8 + c0;
            float b0 = sbkj[col], b1 = sbkj[col + 1];
            float v0 = swishf(acc[j][0] + b0);
            float v1 = swishf(acc[j][1] + b1);
            float v2 = swishf(acc[j][2] + b0);
            float v3 = swishf(acc[j][3] + b1);
            float gA0 = 0.f, gA1 = 0.f, gB0 = 0.f, gB1 = 0.f;
            #pragma unroll
            for (int b = 0; b < 8; b++) {
                float w0 = sWg[b * N + col], w1 = sWg[b * N + col + 1];
                gA0 = fmaf(r8A[b], w0, gA0);
                gA1 = fmaf(r8A[b], w1, gA1);
                gB0 = fmaf(r8B[b], w0, gB0);
                gB1 = fmaf(r8B[b], w1, gB1);
            }
            v0 *= gA0; v1 *= gA1; v2 *= gB0; v3 *= gB1;
            store_hl(AhiB, AloB, rowA, col, v0, v1, LDA2);
            store_hl(AhiB, AloB, rowB, col, v2, v3, LDA2);
        }
    }
    __syncthreads();

    {
        constexpr int N2 = 64;
        constexpr int N28 = N2 / 16;
        float acc2[N28][4];
        zero_acc<N2>(acc2);
        const int warpN2 = (wid >> 2) * (N2 / 2);
        run_mma<N2, K>(acc2, aHiAddr, aLoAddr, Bdown, lane, warpN2 >> 3);

        const size_t gA = rowBase + warpM + r0;
        const size_t gB = gA + 8;
        #pragma unroll
        for (int j = 0; j < N28; j++) {
            const int col = warpN2 + j * 8 + c0;
            *(float2*)(ang + gA * N2 + col) =
                make_float2(swishf(acc2[j][0]), swishf(acc2[j][1]));
            *(float2*)(ang + gB * N2 + col) =
                make_float2(swishf(acc2[j][2]), swishf(acc2[j][3]));
        }
    }
}

// ---------------------------------------------------------------------------
// up_res: h1 = t + f(f(t)),  t = swish(agg @ W_up) + m_pre   (steps 7+8)
// t kept fp32 in smem (skip) and bf16 in A smem (next GEMM input).
// ---------------------------------------------------------------------------
#define LDT 132      // fp32 smem row stride (conflict-free)

__global__ __launch_bounds__(256, 2) void up_res(
    const float*    __restrict__ agg,
    const uint32_t* __restrict__ Bup,
    const float*    __restrict__ m_pre,
    const uint32_t* __restrict__ B0, const float* __restrict__ bias0,
    const uint32_t* __restrict__ B1, const float* __restrict__ bias1,
    float*          __restrict__ h1out)
{
    constexpr int N = 128;
    constexpr int N8 = N / 16;
    constexpr int LDA128 = 136, LDA2_128 = 272;
    constexpr int LDA64  = 72,  LDA2_64  = 144;
    constexpr int ABYT = MT * LDA128 * 2;          // 17408

    extern __shared__ __align__(16) char smem[];
    float* sb0 = (float*)smem;                     // 512
    float* sb1 = (float*)(smem + 512);             // 512
    float* Tf  = (float*)(smem + 2048);            // 64*132*4 = 33792
    char*  AhiB = smem + 2048 + MT * LDT * 4;
    char*  AloB = AhiB + ABYT;

    const int tid = threadIdx.x, wid = tid >> 5, lane = tid & 31;
    const size_t rowBase = (size_t)blockIdx.x * MT;

    for (int i = tid; i < N; i += 256) { sb0[i] = bias0[i]; sb1[i] = bias1[i]; }

    stage_A<64>(agg, rowBase, AhiB, AloB, tid);
    __syncthreads();

    const int warpM = (wid & 3) * 16;
    const int warpN = (wid >> 2) * (N / 2);
    const int n8base = warpN >> 3;
    const int r0 = lane >> 2;
    const int c0 = (lane & 3) * 2;
    const int rowA = warpM + r0;
    const int rowB = rowA + 8;
    const size_t gA = rowBase + rowA;
    const size_t gB = rowBase + rowB;

    const uint32_t aOff128 = (uint32_t)(warpM + (lane & 15)) * LDA2_128 + (uint32_t)(lane >> 4) * 16;
    const uint32_t aOff64  = (uint32_t)(warpM + (lane & 15)) * LDA2_64  + (uint32_t)(lane >> 4) * 16;
    const uint32_t hiBase = smem_u32(AhiB);
    const uint32_t loBase = smem_u32(AloB);

    float acc[N8][4];

    // ---- GEMM up (K=64): t = swish(agg @ W_up) + m_pre ----
    zero_acc<N>(acc);
    run_mma<N, 64>(acc, hiBase + aOff64, loBase + aOff64, Bup, lane, n8base);
    __syncthreads();   // done reading K=64 A before overwrite

    #pragma unroll
    for (int j = 0; j < N8; j++) {
        const int col = warpN + j * 8 + c0;
        float v0 = swishf(acc[j][0]);
        float v1 = swishf(acc[j][1]);
        float v2 = swishf(acc[j][2]);
        float v3 = swishf(acc[j][3]);
        float2 eA = *(const float2*)(m_pre + gA * N + col);
        float2 eB = *(const float2*)(m_pre + gB * N + col);
        v0 += eA.x; v1 += eA.y; v2 += eB.x; v3 += eB.y;
        *(float2*)(Tf + rowA * LDT + col) = make_float2(v0, v1);
        *(float2*)(Tf + rowB * LDT + col) = make_float2(v2, v3);
        store_hl(AhiB, AloB, rowA, col, v0, v1, LDA2_128);
        store_hl(AhiB, AloB, rowB, col, v2, v3, LDA2_128);
        acc[j][0] = 0.f; acc[j][1] = 0.f; acc[j][2] = 0.f; acc[j][3] = 0.f;
    }
    __syncthreads();

    // ---- GEMM resb0: swish -> A smem ----
    run_mma<N, 128>(acc, hiBase + aOff128, loBase + aOff128, B0, lane, n8base);
    __syncthreads();
    #pragma unroll
    for (int j = 0; j < N8; j++) {
        const int col = warpN + j * 8 + c0;
        float b0 = sb0[col], b1 = sb0[col + 1];
        store_hl(AhiB, AloB, rowA, col, swishf(acc[j][0] + b0), swishf(acc[j][1] + b1), LDA2_128);
        store_hl(AhiB, AloB, rowB, col, swishf(acc[j][2] + b0), swishf(acc[j][3] + b1), LDA2_128);
        acc[j][0] = 0.f; acc[j][1] = 0.f; acc[j][2] = 0.f; acc[j][3] = 0.f;
    }
    __syncthreads();

    // ---- GEMM resb1: h1 = t + swish(acc + b1) ----
    run_mma<N, 128>(acc, hiBase + aOff128, loBase + aOff128, B1, lane, n8base);
    #pragma unroll
    for (int j = 0; j < N8; j++) {
        const int col = warpN + j * 8 + c0;
        float b0 = sb1[col], b1 = sb1[col + 1];
        float v0 = swishf(acc[j][0] + b0);
        float v1 = swishf(acc[j][1] + b1);
        float v2 = swishf(acc[j][2] + b0);
        float v3 = swishf(acc[j][3] + b1);
        float2 tA = *(const float2*)(Tf + rowA * LDT + col);
        float2 tB = *(const float2*)(Tf + rowB * LDT + col);
        *(float2*)(h1out + gA * N + col) = make_float2(tA.x + v0, tA.y + v1);
        *(float2*)(h1out + gB * N + col) = make_float2(tB.x + v2, tB.y + v3);
    }
}

// ---------------------------------------------------------------------------
// fin_res: t = m + f(f(m)),  m = swish(h1 @ W_fin + b_fin) + m_input  (9+10)
// ---------------------------------------------------------------------------
__global__ __launch_bounds__(256, 2) void fin_res(
    const float*    __restrict__ h1,
    const uint32_t* __restrict__ Bfin, const float* __restrict__ bfin,
    const float*    __restrict__ m_input,
    const uint32_t* __restrict__ B0, const float* __restrict__ bias0,
    const uint32_t* __restrict__ B1, const float* __restrict__ bias1,
    float*          __restrict__ tout)
{
    constexpr int N = 128;
    constexpr int N8 = N / 16;
    constexpr int LDA128 = 136, LDA2_128 = 272;
    constexpr int ABYT = MT * LDA128 * 2;

    extern __shared__ __align__(16) char smem[];
    float* sbf = (float*)smem;                     // 512
    float* sb0 = (float*)(smem + 512);             // 512
    float* sb1 = (float*)(smem + 1024);            // 512
    float* Tf  = (float*)(smem + 2048);
    char*  AhiB = smem + 2048 + MT * LDT * 4;
    char*  AloB = AhiB + ABYT;

    const int tid = threadIdx.x, wid = tid >> 5, lane = tid & 31;
    const size_t rowBase = (size_t)blockIdx.x * MT;

    for (int i = tid; i < N; i += 256) { sbf[i] = bfin[i]; sb0[i] = bias0[i]; sb1[i] = bias1[i]; }

    stage_A<128>(h1, rowBase, AhiB, AloB, tid);
    __syncthreads();

    const int warpM = (wid & 3) * 16;
    const int warpN = (wid >> 2) * (N / 2);
    const int n8base = warpN >> 3;
    const int r0 = lane >> 2;
    const int c0 = (lane & 3) * 2;
    const int rowA = warpM + r0;
    const int rowB = rowA + 8;
    const size_t gA = rowBase + rowA;
    const size_t gB = rowBase + rowB;

    const uint32_t aOff = (uint32_t)(warpM + (lane & 15)) * LDA2_128 + (uint32_t)(lane >> 4) * 16;
    const uint32_t hiBase = smem_u32(AhiB);
    const uint32_t loBase = smem_u32(AloB);

    float acc[N8][4];

    // ---- GEMM fin: m = swish(h1 @ W_fin + b_fin) + m_input ----
    zero_acc<N>(acc);
    run_mma<N, 128>(acc, hiBase + aOff, loBase + aOff, Bfin, lane, n8base);
    __syncthreads();

    #pragma unroll
    for (int j = 0; j < N8; j++) {
        const int col = warpN + j * 8 + c0;
        float b0 = sbf[col], b1 = sbf[col + 1];
        float v0 = swishf(acc[j][0] + b0);
        float v1 = swishf(acc[j][1] + b1);
        float v2 = swishf(acc[j][2] + b0);
        float v3 = swishf(acc[j][3] + b1);
        float2 eA = *(const float2*)(m_input + gA * N + col);
        float2 eB = *(const float2*)(m_input + gB * N + col);
        v0 += eA.x; v1 += eA.y; v2 += eB.x; v3 += eB.y;
        *(float2*)(Tf + rowA * LDT + col) = make_float2(v0, v1);
        *(float2*)(Tf + rowB * LDT + col) = make_float2(v2, v3);
        store_hl(AhiB, AloB, rowA, col, v0, v1, LDA2_128);
        store_hl(AhiB, AloB, rowB, col, v2, v3, LDA2_128);
        acc[j][0] = 0.f; acc[j][1] = 0.f; acc[j][2] = 0.f; acc[j][3] = 0.f;
    }
    __syncthreads();

    // ---- GEMM resa00 ----
    run_mma<N, 128>(acc, hiBase + aOff, loBase + aOff, B0, lane, n8base);
    __syncthreads();
    #pragma unroll
    for (int j = 0; j < N8; j++) {
        const int col = warpN + j * 8 + c0;
        float b0 = sb0[col], b1 = sb0[col + 1];
        store_hl(AhiB, AloB, rowA, col, swishf(acc[j][0] + b0), swishf(acc[j][1] + b1), LDA2_128);
        store_hl(AhiB, AloB, rowB, col, swishf(acc[j][2] + b0), swishf(acc[j][3] + b1), LDA2_128);
        acc[j][0] = 0.f; acc[j][1] = 0.f; acc[j][2] = 0.f; acc[j][3] = 0.f;
    }
    __syncthreads();

    // ---- GEMM resa01: t = m + swish(acc + b1) ----
    run_mma<N, 128>(acc, hiBase + aOff, loBase + aOff, B1, lane, n8base);
    #pragma unroll
    for (int j = 0; j < N8; j++) {
        const int col = warpN + j * 8 + c0;
        float b0 = sb1[col], b1 = sb1[col + 1];
        float v0 = swishf(acc[j][0] + b0);
        float v1 = swishf(acc[j][1] + b1);
        float v2 = swishf(acc[j][2] + b0);
        float v3 = swishf(acc[j][3] + b1);
        float2 tA = *(const float2*)(Tf + rowA * LDT + col);
        float2 tB = *(const float2*)(Tf + rowB * LDT + col);
        *(float2*)(tout + gA * N + col) = make_float2(tA.x + v0, tA.y + v1);
        *(float2*)(tout + gB * N + col) = make_float2(tB.x + v2, tB.y + v3);
    }
}

// ---------------------------------------------------------------------------
// Fused residual block (R10-proven): C = X + f(f(X))
// ---------------------------------------------------------------------------
__global__ __launch_bounds__(256, 2) void fused_res(
    const float*    __restrict__ X,
    const uint32_t* __restrict__ B0, const float* __restrict__ bias0,
    const uint32_t* __restrict__ B1, const float* __restrict__ bias1,
    float*          __restrict__ C)
{
    constexpr int N = 128, K = 128;
    constexpr int N8   = N / 16;
    constexpr int LDA  = K + 8;
    constexpr int LDA2 = LDA * 2;
    constexpr int ABYT = MT * LDA * 2;

    extern __shared__ __align__(16) char smem[];
    float* sb0  = (float*)smem;
    float* sb1  = (float*)(smem + 512);
    char*  AhiB = smem + 1024;
    char*  AloB = AhiB + ABYT;

    const int tid = threadIdx.x, wid = tid >> 5, lane = tid & 31;
    const size_t rowBase = (size_t)blockIdx.x * MT;

    for (int i = tid; i < N; i += 256) { sb0[i] = bias0[i]; sb1[i] = bias1[i]; }

    stage_A<K>(X, rowBase, AhiB, AloB, tid);
    __syncthreads();

    const int warpM = (wid & 3) * 16;
    const int warpN = (wid >> 2) * (N / 2);
    const int n8base = warpN >> 3;

    float acc[N8][4];
    zero_acc<N>(acc);

    const uint32_t aHiAddr = smem_u32(AhiB) +
        (uint32_t)(warpM + (lane & 15)) * LDA2 + (uint32_t)(lane >> 4) * 16;
    const uint32_t aLoAddr = aHiAddr + (uint32_t)ABYT;

    run_mma<N, K>(acc, aHiAddr, aLoAddr, B0, lane, n8base);
    __syncthreads();

    const int r0 = lane >> 2;
    const int c0 = (lane & 3) * 2;

    {
        const int rowA = warpM + r0;
        const int rowB = rowA + 8;
        #pragma unroll
        for (int j = 0; j < N8; j++) {
            const int col = warpN + j * 8 + c0;
            float b0 = sb0[col], b1 = sb0[col + 1];
            store_hl(AhiB, AloB, rowA, col, swishf(acc[j][0] + b0), swishf(acc[j][1] + b1), LDA2);
            store_hl(AhiB, AloB, rowB, col, swishf(acc[j][2] + b0), swishf(acc[j][3] + b1), LDA2);
            acc[j][0] = 0.f; acc[j][1] = 0.f;
            acc[j][2] = 0.f; acc[j][3] = 0.f;
        }
    }
    __syncthreads();

    run_mma<N, K>(acc, aHiAddr, aLoAddr, B1, lane, n8base);

    {
        const int rowA = warpM + r0;
        const int rowB = rowA + 8;
        const size_t gA = rowBase + rowA;
        const size_t gB = rowBase + rowB;
        #pragma unroll
        for (int j = 0; j < N8; j++) {
            const int col = warpN + j * 8 + c0;
            float b0 = sb1[col], b1 = sb1[col + 1];
            float v0 = swishf(acc[j][0] + b0);
            float v1 = swishf(acc[j][1] + b1);
            float v2 = swishf(acc[j][2] + b0);
            float v3 = swishf(acc[j][3] + b1);
            float2 xA = *(const float2*)(X + gA * N + col);
            float2 xB = *(const float2*)(X + gB * N + col);
            *(float2*)(C + gA * N + col) = make_float2(xA.x + v0, xA.y + v1);
            *(float2*)(C + gB * N + col) = make_float2(xB.x + v2, xB.y + v3);
        }
    }
}

// ---------------------------------------------------------------------------
// proj8: out[rows x 8] = X[rows x NIN] @ W[NIN x 8]
// ---------------------------------------------------------------------------
template<int NIN>
__global__ __launch_bounds__(256) void proj8_kernel(
    const float* __restrict__ X, const float* __restrict__ W,
    float* __restrict__ out)
{
    __shared__ float tile[256 * NIN];
    __shared__ float Ws[NIN * 8];
    const size_t base = (size_t)blockIdx.x * 256;
    constexpr int NT4 = 256 * NIN / 4;
    const float4* src = (const float4*)(X + base * NIN);
    #pragma unroll 4
    for (int i = threadIdx.x; i < NT4; i += 256)
        ((float4*)tile)[i] = src[i];
    for (int i = threadIdx.x; i < NIN * 8; i += 256)
        Ws[i] = W[i];
    __syncthreads();

    const float* x = &tile[threadIdx.x * NIN];
    float o[8] = {0, 0, 0, 0, 0, 0, 0, 0};
    #pragma unroll
    for (int c = 0; c < NIN; c++) {
        float xv = x[c];
        #pragma unroll
        for (int b = 0; b < 8; b++)
            o[b] = fmaf(xv, Ws[c * 8 + b], o[b]);
    }
    float4* op = (float4*)(out + (base + threadIdx.x) * 8);
    op[0] = make_float4(o[0], o[1], o[2], o[3]);
    op[1] = make_float4(o[4], o[5], o[6], o[7]);
}

__global__ void zero_kernel(float4* __restrict__ p, size_t n4)
{
    size_t i = (size_t)blockIdx.x * blockDim.x + threadIdx.x;
    if (i < n4) p[i] = make_float4(0.f, 0.f, 0.f, 0.f);
}

// ---------------------------------------------------------------------------
// Triplet gather/gate/scatter -- 2 triplets per 16-lane group (R10-proven)
// ---------------------------------------------------------------------------
__global__ __launch_bounds__(256, 8) void triplet_kernel(
    const int* __restrict__ expand_to_kj,
    const int* __restrict__ reduce_to_ji,
    const float* __restrict__ sbf8,
    const float* __restrict__ Wsbf2,
    const float* __restrict__ ang,
    float* __restrict__ agg)
{
    __shared__ float Ws[8 * 64];
    for (int i = threadIdx.x; i < 512; i += 256) Ws[i] = Wsbf2[i];
    __syncthreads();

    const int lane16 = threadIdx.x & 15;
    const size_t grp = ((size_t)blockIdx.x * 256 + threadIdx.x) >> 4;
    const size_t t0 = grp * 2;
    const size_t t1 = t0 + 1;

    const int ekj0 = __ldg(&expand_to_kj[t0]);
    const int ekj1 = __ldg(&expand_to_kj[t1]);
    const int eji0 = __ldg(&reduce_to_ji[t0]);
    const int eji1 = __ldg(&reduce_to_ji[t1]);

    float4 a0 = __ldg((const float4*)(ang + (size_t)ekj0 * 64 + lane16 * 4));
    float4 a1 = __ldg((const float4*)(ang + (size_t)ekj1 * 64 + lane16 * 4));

    const float* s0 = sbf8 + t0 * 8;
    const float* s1 = sbf8 + t1 * 8;

    float g00 = 0.f, g01 = 0.f, g02 = 0.f, g03 = 0.f;
    float g10 = 0.f, g11 = 0.f, g12 = 0.f, g13 = 0.f;
    #pragma unroll
    for (int b = 0; b < 8; b++) {
        const float sb0 = __ldg(&s0[b]);
        const float sb1 = __ldg(&s1[b]);
        const float* w = &Ws[b * 64 + lane16 * 4];
        float w0 = w[0], w1 = w[1], w2 = w[2], w3 = w[3];
        g00 = fmaf(sb0, w0, g00); g01 = fmaf(sb0, w1, g01);
        g02 = fmaf(sb0, w2, g02); g03 = fmaf(sb0, w3, g03);
        g10 = fmaf(sb1, w0, g10); g11 = fmaf(sb1, w1, g11);
        g12 = fmaf(sb1, w2, g12); g13 = fmaf(sb1, w3, g13);
    }

    float v00 = a0.x * g00, v01 = a0.y * g01, v02 = a0.z * g02, v03 = a0.w * g03;
    float v10 = a1.x * g10, v11 = a1.y * g11, v12 = a1.z * g12, v13 = a1.w * g13;

    float* d0 = agg + (size_t)eji0 * 64 + lane16 * 4;
    float* d1 = agg + (size_t)eji1 * 64 + lane16 * 4;
    asm volatile("red.global.add.v4.f32 [%0], {%1,%2,%3,%4};"
                 :: "l"(d0), "f"(v00), "f"(v01), "f"(v02), "f"(v03) : "memory");
    asm volatile("red.global.add.v4.f32 [%0], {%1,%2,%3,%4};"
                 :: "l"(d1), "f"(v10), "f"(v11), "f"(v12), "f"(v13) : "memory");
}

// ---------------------------------------------------------------------------
// Host orchestration
// ---------------------------------------------------------------------------
static inline int gemm_smem(int K)  { return 1024 + 2 * (MT * (K + 8) * 2); }
static inline int edge_smemsz()     { return 5120 + 2 * (MT * 136 * 2); }
static inline int mega_smemsz()     { return 2048 + MT * LDT * 4 + 2 * (MT * 136 * 2); }

extern "C" void kernel_launch(void* const* d_in, const int* in_sizes, int n_in,
                              void* d_out, int out_size)
{
    const float* m_input = (const float*)d_in[0];
    const float* rbf     = (const float*)d_in[1];
    const float* sbf     = (const float*)d_in[2];
    const int*   expand  = (const int*)  d_in[3];
    const int*   reduce  = (const int*)  d_in[4];
    const float* W_kj    = (const float*)d_in[5];
    const float* b_kj    = (const float*)d_in[6];
    const float* W_rbf1  = (const float*)d_in[7];
    const float* W_rbf2  = (const float*)d_in[8];
    const float* W_sbf1  = (const float*)d_in[9];
    const float* W_sbf2  = (const float*)d_in[10];
    const float* W_down  = (const float*)d_in[11];
    const float* W_up    = (const float*)d_in[12];
    const float* W_ji    = (const float*)d_in[13];
    const float* b_ji    = (const float*)d_in[14];
    const float* W_res_b = (const float*)d_in[15];
    const float* b_res_b = (const float*)d_in[16];
    const float* W_final = (const float*)d_in[17];
    const float* b_final = (const float*)d_in[18];
    const float* W_res_a = (const float*)d_in[19];
    const float* b_res_a = (const float*)d_in[20];
    float* out = (float*)d_out;

    const int E = in_sizes[0] / 128;
    const int T = in_sizes[3];

    float *h1, *ang, *agg, *t, *m, *rbf8, *sbf8, *wb;
    cudaGetSymbolAddress((void**)&h1,   g_h1);
    cudaGetSymbolAddress((void**)&ang,  g_ang);
    cudaGetSymbolAddress((void**)&agg,  g_agg);
    cudaGetSymbolAddress((void**)&t,    g_t);
    cudaGetSymbolAddress((void**)&m,    g_m);
    cudaGetSymbolAddress((void**)&rbf8, g_rbf8);
    cudaGetSymbolAddress((void**)&sbf8, g_sbf8);
    cudaGetSymbolAddress((void**)&wb,   g_wb);

    cudaFuncSetAttribute(edge_fused,
                         cudaFuncAttributeMaxDynamicSharedMemorySize, edge_smemsz());
    cudaFuncSetAttribute(fused_res,
                         cudaFuncAttributeMaxDynamicSharedMemorySize, gemm_smem(128));
    cudaFuncSetAttribute(up_res,
                         cudaFuncAttributeMaxDynamicSharedMemorySize, mega_smemsz());
    cudaFuncSetAttribute(fin_res,
                         cudaFuncAttributeMaxDynamicSharedMemorySize, mega_smemsz());

    char* wbb = (char*)wb;
    auto wat = [&](size_t off) { return (const uint32_t*)(wbb + off); };
    const unsigned OF_KJ = 0, OF_JI = 65536, OF_RB0 = 131072, OF_RB1 = 196608,
                   OF_FIN = 262144, OF_RA00 = 327680, OF_RA01 = 393216,
                   OF_RA10 = 458752, OF_RA11 = 524288,
                   OF_DOWN = 589824, OF_UP = 622592;

    // 0-1: weight conversion
    {
        W9 w;
        w.s[0] = W_kj;            w.off[0] = OF_KJ;
        w.s[1] = W_ji;            w.off[1] = OF_JI;
        w.s[2] = W_res_b;         w.off[2] = OF_RB0;
        w.s[3] = W_res_b + 16384; w.off[3] = OF_RB1;
        w.s[4] = W_final;         w.off[4] = OF_FIN;
        w.s[5] = W_res_a;         w.off[5] = OF_RA00;
        w.s[6] = W_res_a + 16384; w.off[6] = OF_RA01;
        w.s[7] = W_res_a + 32768; w.off[7] = OF_RA10;
        w.s[8] = W_res_a + 49152; w.off[8] = OF_RA11;
        wconv9_kernel<<<dim3(8, 9), 256>>>(w, wbb);

        W2 w2;
        w2.s[0] = W_down; w2.off[0] = OF_DOWN; w2.K[0] = 128; w2.N[0] = 64;
        w2.s[1] = W_up;   w2.off[1] = OF_UP;   w2.K[1] = 64;  w2.N[1] = 128;
        wconv2_kernel<<<dim3(8, 2), 256>>>(w2, wbb);
    }

    const int GE = E / MT;   // 4096

    // 2: rbf8 = rbf @ W_rbf1
    proj8_kernel<6><<<E / 256, 256>>>(rbf, W_rbf1, rbf8);

    // 3: edge fusion: m_pre -> g_m, ang -> g_ang    [ncu idx 3]
    edge_fused<<<GE, 256, edge_smemsz()>>>(
        m_input, wat(OF_JI), b_ji, wat(OF_KJ), b_kj, wat(OF_DOWN),
        W_rbf2, rbf8, m, ang);

    // 4: sbf8
    proj8_kernel<42><<<T / 256, 256>>>(sbf, W_sbf1, sbf8);

    // 5: agg = 0
    {
        size_t n4 = (size_t)E * 64 / 4;
        zero_kernel<<<(unsigned)((n4 + 255) / 256), 256>>>((float4*)agg, n4);
    }

    // 6: scatter
    triplet_kernel<<<(unsigned)((size_t)T * 16 / 256 / 2), 256>>>(
        expand, reduce, sbf8, W_sbf2, ang, agg);

    // 7: h1 = t + f(f(t)), t = swish(agg@W_up) + m_pre      (steps 7+8)
    up_res<<<GE, 256, mega_smemsz()>>>(
        agg, wat(OF_UP), m,
        wat(OF_RB0), b_res_b, wat(OF_RB1), b_res_b + 128, h1);

    // 8: t = m2 + f(f(m2)), m2 = swish(h1@W_fin+b) + m_input (steps 9+10)
    fin_res<<<GE, 256, mega_smemsz()>>>(
        h1, wat(OF_FIN), b_final, m_input,
        wat(OF_RA00), b_res_a, wat(OF_RA01), b_res_a + 128, t);

    // 9: out = t + f(f(t))                                   (step 11)
    fused_res<<<GE, 256, gemm_smem(128)>>>(
        t, wat(OF_RA10), b_res_a + 256, wat(OF_RA11), b_res_a + 384, out);
}

// round 13
// speedup vs baseline: 1.3901x; 1.1376x over previous
#include <cuda_runtime.h>
#include <cuda_bf16.h>
#include <cstdint>

// ---------------------------------------------------------------------------
// Problem constants
// ---------------------------------------------------------------------------
#define E_MAX 262144
#define T_MAX 2097152
#define MT    64          // rows per CTA tile

// ---------------------------------------------------------------------------
// Scratch (device globals -- no allocation allowed)
// ---------------------------------------------------------------------------
__device__ float g_h1  [(size_t)E_MAX * 128];
__device__ float g_ang [(size_t)E_MAX * 64];
__device__ float g_agg [(size_t)E_MAX * 64];
__device__ float g_t   [(size_t)E_MAX * 128];
__device__ float g_m   [(size_t)E_MAX * 128];
__device__ float g_rbf8[(size_t)E_MAX * 8];
__device__ float g_sbf8[(size_t)T_MAX * 8];
__device__ float g_wb  [163840];   // 640KB: bf16 hi|lo interleaved weight fragments

__device__ __forceinline__ float swishf(float v) { return v / (1.0f + __expf(-v)); }

__device__ __forceinline__ uint32_t smem_u32(const void* p) {
    uint32_t a;
    asm("{ .reg .u64 t; cvta.to.shared.u64 t, %1; cvt.u32.u64 %0, t; }"
        : "=r"(a) : "l"(p));
    return a;
}

__device__ __forceinline__ void ldm_x4(uint32_t* r, uint32_t addr) {
    asm volatile("ldmatrix.sync.aligned.m8n8.x4.shared.b16 {%0,%1,%2,%3}, [%4];"
                 : "=r"(r[0]), "=r"(r[1]), "=r"(r[2]), "=r"(r[3]) : "r"(addr));
}

__device__ __forceinline__ void mma_bf16(float* d, const uint32_t* a, uint32_t b0, uint32_t b1) {
    asm volatile("mma.sync.aligned.m16n8k16.row.col.f32.bf16.bf16.f32 "
                 "{%0,%1,%2,%3}, {%4,%5,%6,%7}, {%8,%9}, {%0,%1,%2,%3};"
                 : "+f"(d[0]), "+f"(d[1]), "+f"(d[2]), "+f"(d[3])
                 : "r"(a[0]), "r"(a[1]), "r"(a[2]), "r"(a[3]), "r"(b0), "r"(b1));
}

// ---------------------------------------------------------------------------
// Weight conversion: W[K,N] f32 -> interleaved bf16 hi|lo fragments.
// u32 index = ((n8*KST + ks)*32 + lane)*4 + prec*2 + reg    (prec: 0=hi,1=lo)
// One uint4 per (n8,ks,lane) carries both precisions' fragments.
// ---------------------------------------------------------------------------
__device__ __forceinline__ void wconv_one(const float* __restrict__ W,
                                          __nv_bfloat16* __restrict__ d16,
                                          int K, int N, int start, int stride)
{
    const int KST = K >> 4;
    for (int i = start; i < K * N; i += stride) {
        int k = i / N, n = i % N;
        float v = W[i];
        __nv_bfloat16 h = __float2bfloat16_rn(v);
        __nv_bfloat16 l = __float2bfloat16_rn(v - __bfloat162float(h));
        int ks = k >> 4, kin = k & 15, n8 = n >> 3, nin = n & 7;
        int lane = nin * 4 + ((kin & 7) >> 1);
        int reg  = kin >> 3;
        int half = kin & 1;
        int base32 = (((n8 * KST + ks) * 32 + lane) << 2) + reg;   // prec=0 slot
        d16[(base32 << 1) + half]       = h;                        // hi
        d16[((base32 + 2) << 1) + half] = l;                        // lo (prec*2=2)
    }
}

struct W9 { const float* s[9]; unsigned off[9]; };

__global__ void wconv9_kernel(W9 w, char* base)
{
    const int wi = blockIdx.y;
    wconv_one(w.s[wi], (__nv_bfloat16*)(base + w.off[wi]), 128, 128,
              threadIdx.x + blockIdx.x * 256, 256 * gridDim.x);
}

struct W2 { const float* s[2]; unsigned off[2]; int K[2]; int N[2]; };

__global__ void wconv2_kernel(W2 w, char* base)
{
    const int wi = blockIdx.y;
    wconv_one(w.s[wi], (__nv_bfloat16*)(base + w.off[wi]), w.K[wi], w.N[wi],
              threadIdx.x + blockIdx.x * 256, 256 * gridDim.x);
}

// ---------------------------------------------------------------------------
// A staging: MT rows of f32 global -> bf16 hi/lo smem (row stride K+8 elems)
// ---------------------------------------------------------------------------
template<int K>
__device__ __forceinline__ void stage_A(const float* __restrict__ A, size_t rowBase,
                                        char* AhiB, char* AloB, int tid)
{
    constexpr int LDA = K + 8;
    const float4* Ab = (const float4*)(A + rowBase * K);
    constexpr int NF4 = MT * K / 4;
    #pragma unroll 4
    for (int i = tid; i < NF4; i += 256) {
        int r  = i / (K / 4);
        int c4 = (i % (K / 4)) * 4;
        float4 v = Ab[i];
        __nv_bfloat162 h01, h23, l01, l23;
        h01.x = __float2bfloat16_rn(v.x);
        h01.y = __float2bfloat16_rn(v.y);
        h23.x = __float2bfloat16_rn(v.z);
        h23.y = __float2bfloat16_rn(v.w);
        l01.x = __float2bfloat16_rn(v.x - __bfloat162float(h01.x));
        l01.y = __float2bfloat16_rn(v.y - __bfloat162float(h01.y));
        l23.x = __float2bfloat16_rn(v.z - __bfloat162float(h23.x));
        l23.y = __float2bfloat16_rn(v.w - __bfloat162float(h23.y));
        uint2 hv, lv;
        hv.x = *(uint32_t*)&h01; hv.y = *(uint32_t*)&h23;
        lv.x = *(uint32_t*)&l01; lv.y = *(uint32_t*)&l23;
        size_t off = (size_t)r * LDA * 2 + (size_t)c4 * 2;
        *(uint2*)(AhiB + off) = hv;
        *(uint2*)(AloB + off) = lv;
    }
}

// ---------------------------------------------------------------------------
// 3-term MMA mainloop, single pass over k-steps. Per ks: ldmatrix Ahi+Alo,
// then per fragment one uint4 (Bhi|Blo) feeding 3 MMAs.
// ---------------------------------------------------------------------------
template<int N, int K>
__device__ __forceinline__ void run_mma(float (&acc)[N / 16][4],
                                        uint32_t aHiAddr, uint32_t aLoAddr,
                                        const uint32_t* __restrict__ Bpre,
                                        int lane, int n8base)
{
    constexpr int KST = K / 16;
    constexpr int N8  = N / 16;

    #pragma unroll
    for (int ks = 0; ks < KST; ks++) {
        uint32_t a_hi[4], a_lo[4];
        ldm_x4(a_hi, aHiAddr + ks * 32);
        ldm_x4(a_lo, aLoAddr + ks * 32);
        #pragma unroll
        for (int j = 0; j < N8; j++) {
            uint4 bb = *(const uint4*)(Bpre +
                ((((size_t)(n8base + j) * KST + ks) * 32 + lane) << 2));
            mma_bf16(acc[j], a_hi, bb.x, bb.y);   // hi*hi
            mma_bf16(acc[j], a_hi, bb.z, bb.w);   // hi*lo
            mma_bf16(acc[j], a_lo, bb.x, bb.y);   // lo*hi
        }
    }
}

template<int N>
__device__ __forceinline__ void zero_acc(float (&acc)[N / 16][4])
{
    #pragma unroll
    for (int j = 0; j < N / 16; j++)
        #pragma unroll
        for (int q = 0; q < 4; q++) acc[j][q] = 0.0f;
}

// helper: swish result -> bf16 hi/lo into A smem
__device__ __forceinline__ void store_hl(char* AhiB, char* AloB, int row, int col,
                                         float v0, float v1, int LDA2)
{
    __nv_bfloat162 h, l;
    h.x = __float2bfloat16_rn(v0);
    h.y = __float2bfloat16_rn(v1);
    l.x = __float2bfloat16_rn(v0 - __bfloat162float(h.x));
    l.y = __float2bfloat16_rn(v1 - __bfloat162float(h.y));
    *(__nv_bfloat162*)(AhiB + row * LDA2 + col * 2) = h;
    *(__nv_bfloat162*)(AloB + row * LDA2 + col * 2) = l;
}

// ---------------------------------------------------------------------------
// Edge mega-fusion
// ---------------------------------------------------------------------------
__global__ __launch_bounds__(256, 2) void edge_fused(
    const float*    __restrict__ m_input,
    const uint32_t* __restrict__ Bji, const float* __restrict__ bji,
    const uint32_t* __restrict__ Bkj, const float* __restrict__ bkj,
    const uint32_t* __restrict__ Bdown,
    const float*    __restrict__ Wg,
    const float*    __restrict__ rbf8,
    float*          __restrict__ m_pre,
    float*          __restrict__ ang)
{
    constexpr int K = 128, N = 128;
    constexpr int N8   = N / 16;
    constexpr int LDA  = K + 8;
    constexpr int LDA2 = LDA * 2;
    constexpr int ABYT = MT * LDA * 2;

    extern __shared__ __align__(16) char smem[];
    float* sbji = (float*)smem;
    float* sbkj = (float*)(smem + 512);
    float* sWg  = (float*)(smem + 1024);
    char*  AhiB = smem + 5120;
    char*  AloB = AhiB + ABYT;

    const int tid = threadIdx.x, wid = tid >> 5, lane = tid & 31;
    const size_t rowBase = (size_t)blockIdx.x * MT;

    for (int i = tid; i < N; i += 256) { sbji[i] = bji[i]; sbkj[i] = bkj[i]; }
    for (int i = tid; i < 8 * N; i += 256) sWg[i] = Wg[i];

    stage_A<K>(m_input, rowBase, AhiB, AloB, tid);
    __syncthreads();

    const int warpM = (wid & 3) * 16;
    const int warpN = (wid >> 2) * (N / 2);
    const int n8base = warpN >> 3;

    const uint32_t aHiAddr = smem_u32(AhiB) +
        (uint32_t)(warpM + (lane & 15)) * LDA2 + (uint32_t)(lane >> 4) * 16;
    const uint32_t aLoAddr = aHiAddr + (uint32_t)ABYT;

    const int r0 = lane >> 2;
    const int c0 = (lane & 3) * 2;

    float acc[N8][4];

    zero_acc<N>(acc);
    run_mma<N, K>(acc, aHiAddr, aLoAddr, Bji, lane, n8base);
    {
        const size_t gA = rowBase + warpM + r0;
        const size_t gB = gA + 8;
        #pragma unroll
        for (int j = 0; j < N8; j++) {
            const int col = warpN + j * 8 + c0;
            float b0 = sbji[col], b1 = sbji[col + 1];
            *(float2*)(m_pre + gA * N + col) =
                make_float2(swishf(acc[j][0] + b0), swishf(acc[j][1] + b1));
            *(float2*)(m_pre + gB * N + col) =
                make_float2(swishf(acc[j][2] + b0), swishf(acc[j][3] + b1));
        }
    }

    zero_acc<N>(acc);
    run_mma<N, K>(acc, aHiAddr, aLoAddr, Bkj, lane, n8base);
    __syncthreads();

    {
        const int rowA = warpM + r0;
        const int rowB = rowA + 8;
        const size_t gA = rowBase + rowA;
        const size_t gB = rowBase + rowB;

        float r8A[8], r8B[8];
        {
            float4 a0 = *(const float4*)(rbf8 + gA * 8);
            float4 a1 = *(const float4*)(rbf8 + gA * 8 + 4);
            float4 b0 = *(const float4*)(rbf8 + gB * 8);
            float4 b1 = *(const float4*)(rbf8 + gB * 8 + 4);
            r8A[0]=a0.x; r8A[1]=a0.y; r8A[2]=a0.z; r8A[3]=a0.w;
            r8A[4]=a1.x; r8A[5]=a1.y; r8A[6]=a1.z; r8A[7]=a1.w;
            r8B[0]=b0.x; r8B[1]=b0.y; r8B[2]=b0.z; r8B[3]=b0.w;
            r8B[4]=b1.x; r8B[5]=b1.y; r8B[6]=b1.z; r8B[7]=b1.w;
        }

        #pragma unroll
        for (int j = 0; j < N8; j++) {
            const int col = warpN + j * 8 + c0;
            float b0 = sbkj[col], b1 = sbkj[col + 1];
            float v0 = swishf(acc[j][0] + b0);
            float v1 = swishf(acc[j][1] + b1);
            float v2 = swishf(acc[j][2] + b0);
            float v3 = swishf(acc[j][3] + b1);
            float gA0 = 0.f, gA1 = 0.f, gB0 = 0.f, gB1 = 0.f;
            #pragma unroll
            for (int b = 0; b < 8; b++) {
                float w0 = sWg[b * N + col], w1 = sWg[b * N + col + 1];
                gA0 = fmaf(r8A[b], w0, gA0);
                gA1 = fmaf(r8A[b], w1, gA1);
                gB0 = fmaf(r8B[b], w0, gB0);
                gB1 = fmaf(r8B[b], w1, gB1);
            }
            v0 *= gA0; v1 *= gA1; v2 *= gB0; v3 *= gB1;
            store_hl(AhiB, AloB, rowA, col, v0, v1, LDA2);
            store_hl(AhiB, AloB, rowB, col, v2, v3, LDA2);
        }
    }
    __syncthreads();

    {
        constexpr int N2 = 64;
        constexpr int N28 = N2 / 16;
        float acc2[N28][4];
        zero_acc<N2>(acc2);
        const int warpN2 = (wid >> 2) * (N2 / 2);
        run_mma<N2, K>(acc2, aHiAddr, aLoAddr, Bdown, lane, warpN2 >> 3);

        const size_t gA = rowBase + warpM + r0;
        const size_t gB = gA + 8;
        #pragma unroll
        for (int j = 0; j < N28; j++) {
            const int col = warpN2 + j * 8 + c0;
            *(float2*)(ang + gA * N2 + col) =
                make_float2(swishf(acc2[j][0]), swishf(acc2[j][1]));
            *(float2*)(ang + gB * N2 + col) =
                make_float2(swishf(acc2[j][2]), swishf(acc2[j][3]));
        }
    }
}

// ---------------------------------------------------------------------------
// up_res: h1 = t + f(f(t)),  t = swish(agg @ W_up) + m_pre   (steps 7+8)
// ---------------------------------------------------------------------------
#define LDT 132

__global__ __launch_bounds__(256, 2) void up_res(
    const float*    __restrict__ agg,
    const uint32_t* __restrict__ Bup,
    const float*    __restrict__ m_pre,
    const uint32_t* __restrict__ B0, const float* __restrict__ bias0,
    const uint32_t* __restrict__ B1, const float* __restrict__ bias1,
    float*          __restrict__ h1out)
{
    constexpr int N = 128;
    constexpr int N8 = N / 16;
    constexpr int LDA128 = 136, LDA2_128 = 272;
    constexpr int LDA2_64  = 144;
    constexpr int ABYT = MT * LDA128 * 2;

    extern __shared__ __align__(16) char smem[];
    float* sb0 = (float*)smem;
    float* sb1 = (float*)(smem + 512);
    float* Tf  = (float*)(smem + 2048);
    char*  AhiB = smem + 2048 + MT * LDT * 4;
    char*  AloB = AhiB + ABYT;

    const int tid = threadIdx.x, wid = tid >> 5, lane = tid & 31;
    const size_t rowBase = (size_t)blockIdx.x * MT;

    for (int i = tid; i < N; i += 256) { sb0[i] = bias0[i]; sb1[i] = bias1[i]; }

    stage_A<64>(agg, rowBase, AhiB, AloB, tid);
    __syncthreads();

    const int warpM = (wid & 3) * 16;
    const int warpN = (wid >> 2) * (N / 2);
    const int n8base = warpN >> 3;
    const int r0 = lane >> 2;
    const int c0 = (lane & 3) * 2;
    const int rowA = warpM + r0;
    const int rowB = rowA + 8;
    const size_t gA = rowBase + rowA;
    const size_t gB = rowBase + rowB;

    const uint32_t aOff128 = (uint32_t)(warpM + (lane & 15)) * LDA2_128 + (uint32_t)(lane >> 4) * 16;
    const uint32_t aOff64  = (uint32_t)(warpM + (lane & 15)) * LDA2_64  + (uint32_t)(lane >> 4) * 16;
    const uint32_t hiBase = smem_u32(AhiB);
    const uint32_t loBase = smem_u32(AloB);

    float acc[N8][4];

    zero_acc<N>(acc);
    run_mma<N, 64>(acc, hiBase + aOff64, loBase + aOff64, Bup, lane, n8base);
    __syncthreads();

    #pragma unroll
    for (int j = 0; j < N8; j++) {
        const int col = warpN + j * 8 + c0;
        float v0 = swishf(acc[j][0]);
        float v1 = swishf(acc[j][1]);
        float v2 = swishf(acc[j][2]);
        float v3 = swishf(acc[j][3]);
        float2 eA = *(const float2*)(m_pre + gA * N + col);
        float2 eB = *(const float2*)(m_pre + gB * N + col);
        v0 += eA.x; v1 += eA.y; v2 += eB.x; v3 += eB.y;
        *(float2*)(Tf + rowA * LDT + col) = make_float2(v0, v1);
        *(float2*)(Tf + rowB * LDT + col) = make_float2(v2, v3);
        store_hl(AhiB, AloB, rowA, col, v0, v1, LDA2_128);
        store_hl(AhiB, AloB, rowB, col, v2, v3, LDA2_128);
        acc[j][0] = 0.f; acc[j][1] = 0.f; acc[j][2] = 0.f; acc[j][3] = 0.f;
    }
    __syncthreads();

    run_mma<N, 128>(acc, hiBase + aOff128, loBase + aOff128, B0, lane, n8base);
    __syncthreads();
    #pragma unroll
    for (int j = 0; j < N8; j++) {
        const int col = warpN + j * 8 + c0;
        float b0 = sb0[col], b1 = sb0[col + 1];
        store_hl(AhiB, AloB, rowA, col, swishf(acc[j][0] + b0), swishf(acc[j][1] + b1), LDA2_128);
        store_hl(AhiB, AloB, rowB, col, swishf(acc[j][2] + b0), swishf(acc[j][3] + b1), LDA2_128);
        acc[j][0] = 0.f; acc[j][1] = 0.f; acc[j][2] = 0.f; acc[j][3] = 0.f;
    }
    __syncthreads();

    run_mma<N, 128>(acc, hiBase + aOff128, loBase + aOff128, B1, lane, n8base);
    #pragma unroll
    for (int j = 0; j < N8; j++) {
        const int col = warpN + j * 8 + c0;
        float b0 = sb1[col], b1 = sb1[col + 1];
        float v0 = swishf(acc[j][0] + b0);
        float v1 = swishf(acc[j][1] + b1);
        float v2 = swishf(acc[j][2] + b0);
        float v3 = swishf(acc[j][3] + b1);
        float2 tA = *(const float2*)(Tf + rowA * LDT + col);
        float2 tB = *(const float2*)(Tf + rowB * LDT + col);
        *(float2*)(h1out + gA * N + col) = make_float2(tA.x + v0, tA.y + v1);
        *(float2*)(h1out + gB * N + col) = make_float2(tB.x + v2, tB.y + v3);
    }
}

// ---------------------------------------------------------------------------
// fin_res: t = m + f(f(m)),  m = swish(h1 @ W_fin + b_fin) + m_input  (9+10)
// ---------------------------------------------------------------------------
__global__ __launch_bounds__(256, 2) void fin_res(
    const float*    __restrict__ h1,
    const uint32_t* __restrict__ Bfin, const float* __restrict__ bfin,
    const float*    __restrict__ m_input,
    const uint32_t* __restrict__ B0, const float* __restrict__ bias0,
    const uint32_t* __restrict__ B1, const float* __restrict__ bias1,
    float*          __restrict__ tout)
{
    constexpr int N = 128;
    constexpr int N8 = N / 16;
    constexpr int LDA128 = 136, LDA2_128 = 272;
    constexpr int ABYT = MT * LDA128 * 2;

    extern __shared__ __align__(16) char smem[];
    float* sbf = (float*)smem;
    float* sb0 = (float*)(smem + 512);
    float* sb1 = (float*)(smem + 1024);
    float* Tf  = (float*)(smem + 2048);
    char*  AhiB = smem + 2048 + MT * LDT * 4;
    char*  AloB = AhiB + ABYT;

    const int tid = threadIdx.x, wid = tid >> 5, lane = tid & 31;
    const size_t rowBase = (size_t)blockIdx.x * MT;

    for (int i = tid; i < N; i += 256) { sbf[i] = bfin[i]; sb0[i] = bias0[i]; sb1[i] = bias1[i]; }

    stage_A<128>(h1, rowBase, AhiB, AloB, tid);
    __syncthreads();

    const int warpM = (wid & 3) * 16;
    const int warpN = (wid >> 2) * (N / 2);
    const int n8base = warpN >> 3;
    const int r0 = lane >> 2;
    const int c0 = (lane & 3) * 2;
    const int rowA = warpM + r0;
    const int rowB = rowA + 8;
    const size_t gA = rowBase + rowA;
    const size_t gB = rowBase + rowB;

    const uint32_t aOff = (uint32_t)(warpM + (lane & 15)) * LDA2_128 + (uint32_t)(lane >> 4) * 16;
    const uint32_t hiBase = smem_u32(AhiB);
    const uint32_t loBase = smem_u32(AloB);

    float acc[N8][4];

    zero_acc<N>(acc);
    run_mma<N, 128>(acc, hiBase + aOff, loBase + aOff, Bfin, lane, n8base);
    __syncthreads();

    #pragma unroll
    for (int j = 0; j < N8; j++) {
        const int col = warpN + j * 8 + c0;
        float b0 = sbf[col], b1 = sbf[col + 1];
        float v0 = swishf(acc[j][0] + b0);
        float v1 = swishf(acc[j][1] + b1);
        float v2 = swishf(acc[j][2] + b0);
        float v3 = swishf(acc[j][3] + b1);
        float2 eA = *(const float2*)(m_input + gA * N + col);
        float2 eB = *(const float2*)(m_input + gB * N + col);
        v0 += eA.x; v1 += eA.y; v2 += eB.x; v3 += eB.y;
        *(float2*)(Tf + rowA * LDT + col) = make_float2(v0, v1);
        *(float2*)(Tf + rowB * LDT + col) = make_float2(v2, v3);
        store_hl(AhiB, AloB, rowA, col, v0, v1, LDA2_128);
        store_hl(AhiB, AloB, rowB, col, v2, v3, LDA2_128);
        acc[j][0] = 0.f; acc[j][1] = 0.f; acc[j][2] = 0.f; acc[j][3] = 0.f;
    }
    __syncthreads();

    run_mma<N, 128>(acc, hiBase + aOff, loBase + aOff, B0, lane, n8base);
    __syncthreads();
    #pragma unroll
    for (int j = 0; j < N8; j++) {
        const int col = warpN + j * 8 + c0;
        float b0 = sb0[col], b1 = sb0[col + 1];
        store_hl(AhiB, AloB, rowA, col, swishf(acc[j][0] + b0), swishf(acc[j][1] + b1), LDA2_128);
        store_hl(AhiB, AloB, rowB, col, swishf(acc[j][2] + b0), swishf(acc[j][3] + b1), LDA2_128);
        acc[j][0] = 0.f; acc[j][1] = 0.f; acc[j][2] = 0.f; acc[j][3] = 0.f;
    }
    __syncthreads();

    run_mma<N, 128>(acc, hiBase + aOff, loBase + aOff, B1, lane, n8base);
    #pragma unroll
    for (int j = 0; j < N8; j++) {
        const int col = warpN + j * 8 + c0;
        float b0 = sb1[col], b1 = sb1[col + 1];
        float v0 = swishf(acc[j][0] + b0);
        float v1 = swishf(acc[j][1] + b1);
        float v2 = swishf(acc[j][2] + b0);
        float v3 = swishf(acc[j][3] + b1);
        float2 tA = *(const float2*)(Tf + rowA * LDT + col);
        float2 tB = *(const float2*)(Tf + rowB * LDT + col);
        *(float2*)(tout + gA * N + col) = make_float2(tA.x + v0, tA.y + v1);
        *(float2*)(tout + gB * N + col) = make_float2(tB.x + v2, tB.y + v3);
    }
}

// ---------------------------------------------------------------------------
// Fused residual block: C = X + f(f(X))
// ---------------------------------------------------------------------------
__global__ __launch_bounds__(256, 2) void fused_res(
    const float*    __restrict__ X,
    const uint32_t* __restrict__ B0, const float* __restrict__ bias0,
    const uint32_t* __restrict__ B1, const float* __restrict__ bias1,
    float*          __restrict__ C)
{
    constexpr int N = 128, K = 128;
    constexpr int N8   = N / 16;
    constexpr int LDA  = K + 8;
    constexpr int LDA2 = LDA * 2;
    constexpr int ABYT = MT * LDA * 2;

    extern __shared__ __align__(16) char smem[];
    float* sb0  = (float*)smem;
    float* sb1  = (float*)(smem + 512);
    char*  AhiB = smem + 1024;
    char*  AloB = AhiB + ABYT;

    const int tid = threadIdx.x, wid = tid >> 5, lane = tid & 31;
    const size_t rowBase = (size_t)blockIdx.x * MT;

    for (int i = tid; i < N; i += 256) { sb0[i] = bias0[i]; sb1[i] = bias1[i]; }

    stage_A<K>(X, rowBase, AhiB, AloB, tid);
    __syncthreads();

    const int warpM = (wid & 3) * 16;
    const int warpN = (wid >> 2) * (N / 2);
    const int n8base = warpN >> 3;

    float acc[N8][4];
    zero_acc<N>(acc);

    const uint32_t aHiAddr = smem_u32(AhiB) +
        (uint32_t)(warpM + (lane & 15)) * LDA2 + (uint32_t)(lane >> 4) * 16;
    const uint32_t aLoAddr = aHiAddr + (uint32_t)ABYT;

    run_mma<N, K>(acc, aHiAddr, aLoAddr, B0, lane, n8base);
    __syncthreads();

    const int r0 = lane >> 2;
    const int c0 = (lane & 3) * 2;

    {
        const int rowA = warpM + r0;
        const int rowB = rowA + 8;
        #pragma unroll
        for (int j = 0; j < N8; j++) {
            const int col = warpN + j * 8 + c0;
            float b0 = sb0[col], b1 = sb0[col + 1];
            store_hl(AhiB, AloB, rowA, col, swishf(acc[j][0] + b0), swishf(acc[j][1] + b1), LDA2);
            store_hl(AhiB, AloB, rowB, col, swishf(acc[j][2] + b0), swishf(acc[j][3] + b1), LDA2);
            acc[j][0] = 0.f; acc[j][1] = 0.f;
            acc[j][2] = 0.f; acc[j][3] = 0.f;
        }
    }
    __syncthreads();

    run_mma<N, K>(acc, aHiAddr, aLoAddr, B1, lane, n8base);

    {
        const int rowA = warpM + r0;
        const int rowB = rowA + 8;
        const size_t gA = rowBase + rowA;
        const size_t gB = rowBase + rowB;
        #pragma unroll
        for (int j = 0; j < N8; j++) {
            const int col = warpN + j * 8 + c0;
            float b0 = sb1[col], b1 = sb1[col + 1];
            float v0 = swishf(acc[j][0] + b0);
            float v1 = swishf(acc[j][1] + b1);
            float v2 = swishf(acc[j][2] + b0);
            float v3 = swishf(acc[j][3] + b1);
            float2 xA = *(const float2*)(X + gA * N + col);
            float2 xB = *(const float2*)(X + gB * N + col);
            *(float2*)(C + gA * N + col) = make_float2(xA.x + v0, xA.y + v1);
            *(float2*)(C + gB * N + col) = make_float2(xB.x + v2, xB.y + v3);
        }
    }
}

// ---------------------------------------------------------------------------
// proj8: out[rows x 8] = X[rows x NIN] @ W[NIN x 8]
// ---------------------------------------------------------------------------
template<int NIN>
__global__ __launch_bounds__(256) void proj8_kernel(
    const float* __restrict__ X, const float* __restrict__ W,
    float* __restrict__ out)
{
    __shared__ float tile[256 * NIN];
    __shared__ float Ws[NIN * 8];
    const size_t base = (size_t)blockIdx.x * 256;
    constexpr int NT4 = 256 * NIN / 4;
    const float4* src = (const float4*)(X + base * NIN);
    #pragma unroll 4
    for (int i = threadIdx.x; i < NT4; i += 256)
        ((float4*)tile)[i] = src[i];
    for (int i = threadIdx.x; i < NIN * 8; i += 256)
        Ws[i] = W[i];
    __syncthreads();

    const float* x = &tile[threadIdx.x * NIN];
    float o[8] = {0, 0, 0, 0, 0, 0, 0, 0};
    #pragma unroll
    for (int c = 0; c < NIN; c++) {
        float xv = x[c];
        #pragma unroll
        for (int b = 0; b < 8; b++)
            o[b] = fmaf(xv, Ws[c * 8 + b], o[b]);
    }
    float4* op = (float4*)(out + (base + threadIdx.x) * 8);
    op[0] = make_float4(o[0], o[1], o[2], o[3]);
    op[1] = make_float4(o[4], o[5], o[6], o[7]);
}

__global__ void zero_kernel(float4* __restrict__ p, size_t n4)
{
    size_t i = (size_t)blockIdx.x * blockDim.x + threadIdx.x;
    if (i < n4) p[i] = make_float4(0.f, 0.f, 0.f, 0.f);
}

// ---------------------------------------------------------------------------
// Triplet gather/gate/scatter -- 2 triplets per 16-lane group
// ---------------------------------------------------------------------------
__global__ __launch_bounds__(256, 8) void triplet_kernel(
    const int* __restrict__ expand_to_kj,
    const int* __restrict__ reduce_to_ji,
    const float* __restrict__ sbf8,
    const float* __restrict__ Wsbf2,
    const float* __restrict__ ang,
    float* __restrict__ agg)
{
    __shared__ float Ws[8 * 64];
    for (int i = threadIdx.x; i < 512; i += 256) Ws[i] = Wsbf2[i];
    __syncthreads();

    const int lane16 = threadIdx.x & 15;
    const size_t grp = ((size_t)blockIdx.x * 256 + threadIdx.x) >> 4;
    const size_t t0 = grp * 2;
    const size_t t1 = t0 + 1;

    const int ekj0 = __ldg(&expand_to_kj[t0]);
    const int ekj1 = __ldg(&expand_to_kj[t1]);
    const int eji0 = __ldg(&reduce_to_ji[t0]);
    const int eji1 = __ldg(&reduce_to_ji[t1]);

    float4 a0 = __ldg((const float4*)(ang + (size_t)ekj0 * 64 + lane16 * 4));
    float4 a1 = __ldg((const float4*)(ang + (size_t)ekj1 * 64 + lane16 * 4));

    const float* s0 = sbf8 + t0 * 8;
    const float* s1 = sbf8 + t1 * 8;

    float g00 = 0.f, g01 = 0.f, g02 = 0.f, g03 = 0.f;
    float g10 = 0.f, g11 = 0.f, g12 = 0.f, g13 = 0.f;
    #pragma unroll
    for (int b = 0; b < 8; b++) {
        const float sb0 = __ldg(&s0[b]);
        const float sb1 = __ldg(&s1[b]);
        const float* w = &Ws[b * 64 + lane16 * 4];
        float w0 = w[0], w1 = w[1], w2 = w[2], w3 = w[3];
        g00 = fmaf(sb0, w0, g00); g01 = fmaf(sb0, w1, g01);
        g02 = fmaf(sb0, w2, g02); g03 = fmaf(sb0, w3, g03);
        g10 = fmaf(sb1, w0, g10); g11 = fmaf(sb1, w1, g11);
        g12 = fmaf(sb1, w2, g12); g13 = fmaf(sb1, w3, g13);
    }

    float v00 = a0.x * g00, v01 = a0.y * g01, v02 = a0.z * g02, v03 = a0.w * g03;
    float v10 = a1.x * g10, v11 = a1.y * g11, v12 = a1.z * g12, v13 = a1.w * g13;

    float* d0 = agg + (size_t)eji0 * 64 + lane16 * 4;
    float* d1 = agg + (size_t)eji1 * 64 + lane16 * 4;
    asm volatile("red.global.add.v4.f32 [%0], {%1,%2,%3,%4};"
                 :: "l"(d0), "f"(v00), "f"(v01), "f"(v02), "f"(v03) : "memory");
    asm volatile("red.global.add.v4.f32 [%0], {%1,%2,%3,%4};"
                 :: "l"(d1), "f"(v10), "f"(v11), "f"(v12), "f"(v13) : "memory");
}

// ---------------------------------------------------------------------------
// Host orchestration
// ---------------------------------------------------------------------------
static inline int gemm_smem(int K)  { return 1024 + 2 * (MT * (K + 8) * 2); }
static inline int edge_smemsz()     { return 5120 + 2 * (MT * 136 * 2); }
static inline int mega_smemsz()     { return 2048 + MT * LDT * 4 + 2 * (MT * 136 * 2); }

extern "C" void kernel_launch(void* const* d_in, const int* in_sizes, int n_in,
                              void* d_out, int out_size)
{
    const float* m_input = (const float*)d_in[0];
    const float* rbf     = (const float*)d_in[1];
    const float* sbf     = (const float*)d_in[2];
    const int*   expand  = (const int*)  d_in[3];
    const int*   reduce  = (const int*)  d_in[4];
    const float* W_kj    = (const float*)d_in[5];
    const float* b_kj    = (const float*)d_in[6];
    const float* W_rbf1  = (const float*)d_in[7];
    const float* W_rbf2  = (const float*)d_in[8];
    const float* W_sbf1  = (const float*)d_in[9];
    const float* W_sbf2  = (const float*)d_in[10];
    const float* W_down  = (const float*)d_in[11];
    const float* W_up    = (const float*)d_in[12];
    const float* W_ji    = (const float*)d_in[13];
    const float* b_ji    = (const float*)d_in[14];
    const float* W_res_b = (const float*)d_in[15];
    const float* b_res_b = (const float*)d_in[16];
    const float* W_final = (const float*)d_in[17];
    const float* b_final = (const float*)d_in[18];
    const float* W_res_a = (const float*)d_in[19];
    const float* b_res_a = (const float*)d_in[20];
    float* out = (float*)d_out;

    const int E = in_sizes[0] / 128;
    const int T = in_sizes[3];

    float *h1, *ang, *agg, *t, *m, *rbf8, *sbf8, *wb;
    cudaGetSymbolAddress((void**)&h1,   g_h1);
    cudaGetSymbolAddress((void**)&ang,  g_ang);
    cudaGetSymbolAddress((void**)&agg,  g_agg);
    cudaGetSymbolAddress((void**)&t,    g_t);
    cudaGetSymbolAddress((void**)&m,    g_m);
    cudaGetSymbolAddress((void**)&rbf8, g_rbf8);
    cudaGetSymbolAddress((void**)&sbf8, g_sbf8);
    cudaGetSymbolAddress((void**)&wb,   g_wb);

    cudaFuncSetAttribute(edge_fused,
                         cudaFuncAttributeMaxDynamicSharedMemorySize, edge_smemsz());
    cudaFuncSetAttribute(fused_res,
                         cudaFuncAttributeMaxDynamicSharedMemorySize, gemm_smem(128));
    cudaFuncSetAttribute(up_res,
                         cudaFuncAttributeMaxDynamicSharedMemorySize, mega_smemsz());
    cudaFuncSetAttribute(fin_res,
                         cudaFuncAttributeMaxDynamicSharedMemorySize, mega_smemsz());

    char* wbb = (char*)wb;
    auto wat = [&](size_t off) { return (const uint32_t*)(wbb + off); };
    const unsigned OF_KJ = 0, OF_JI = 65536, OF_RB0 = 131072, OF_RB1 = 196608,
                   OF_FIN = 262144, OF_RA00 = 327680, OF_RA01 = 393216,
                   OF_RA10 = 458752, OF_RA11 = 524288,
                   OF_DOWN = 589824, OF_UP = 622592;

    // 0-1: weight conversion (interleaved hi|lo layout)
    {
        W9 w;
        w.s[0] = W_kj;            w.off[0] = OF_KJ;
        w.s[1] = W_ji;            w.off[1] = OF_JI;
        w.s[2] = W_res_b;         w.off[2] = OF_RB0;
        w.s[3] = W_res_b + 16384; w.off[3] = OF_RB1;
        w.s[4] = W_final;         w.off[4] = OF_FIN;
        w.s[5] = W_res_a;         w.off[5] = OF_RA00;
        w.s[6] = W_res_a + 16384; w.off[6] = OF_RA01;
        w.s[7] = W_res_a + 32768; w.off[7] = OF_RA10;
        w.s[8] = W_res_a + 49152; w.off[8] = OF_RA11;
        wconv9_kernel<<<dim3(8, 9), 256>>>(w, wbb);

        W2 w2;
        w2.s[0] = W_down; w2.off[0] = OF_DOWN; w2.K[0] = 128; w2.N[0] = 64;
        w2.s[1] = W_up;   w2.off[1] = OF_UP;   w2.K[1] = 64;  w2.N[1] = 128;
        wconv2_kernel<<<dim3(8, 2), 256>>>(w2, wbb);
    }

    const int GE = E / MT;   // 4096

    // 2: rbf8 = rbf @ W_rbf1
    proj8_kernel<6><<<E / 256, 256>>>(rbf, W_rbf1, rbf8);

    // 3: edge fusion: m_pre -> g_m, ang -> g_ang    [ncu idx 3]
    edge_fused<<<GE, 256, edge_smemsz()>>>(
        m_input, wat(OF_JI), b_ji, wat(OF_KJ), b_kj, wat(OF_DOWN),
        W_rbf2, rbf8, m, ang);

    // 4: sbf8
    proj8_kernel<42><<<T / 256, 256>>>(sbf, W_sbf1, sbf8);

    // 5: agg = 0
    {
        size_t n4 = (size_t)E * 64 / 4;
        zero_kernel<<<(unsigned)((n4 + 255) / 256), 256>>>((float4*)agg, n4);
    }

    // 6: scatter
    triplet_kernel<<<(unsigned)((size_t)T * 16 / 256 / 2), 256>>>(
        expand, reduce, sbf8, W_sbf2, ang, agg);

    // 7: h1 = t + f(f(t)), t = swish(agg@W_up) + m_pre      (steps 7+8)
    up_res<<<GE, 256, mega_smemsz()>>>(
        agg, wat(OF_UP), m,
        wat(OF_RB0), b_res_b, wat(OF_RB1), b_res_b + 128, h1);

    // 8: t = m2 + f(f(m2)), m2 = swish(h1@W_fin+b) + m_input (steps 9+10)
    fin_res<<<GE, 256, mega_smemsz()>>>(
        h1, wat(OF_FIN), b_final, m_input,
        wat(OF_RA00), b_res_a, wat(OF_RA01), b_res_a + 128, t);

    // 9: out = t + f(f(t))                                   (step 11)
    fused_res<<<GE, 256, gemm_smem(128)>>>(
        t, wat(OF_RA10), b_res_a + 256, wat(OF_RA11), b_res_a + 384, out);
}

// round 14
// speedup vs baseline: 1.4646x; 1.0536x over previous
#include <cuda_runtime.h>
#include <cuda_bf16.h>
#include <cstdint>

// ---------------------------------------------------------------------------
// Problem constants
// ---------------------------------------------------------------------------
#define E_MAX 262144
#define T_MAX 2097152
#define MT    64          // rows per CTA tile

// ---------------------------------------------------------------------------
// Scratch (device globals -- no allocation allowed)
// ---------------------------------------------------------------------------
__device__ float g_ang [(size_t)E_MAX * 64];
__device__ float g_agg [(size_t)E_MAX * 64];
__device__ float g_m   [(size_t)E_MAX * 128];
__device__ float g_rbf8[(size_t)E_MAX * 8];
__device__ float g_sbf8[(size_t)T_MAX * 8];
__device__ float g_wb  [163840];   // 640KB: bf16 hi|lo interleaved weight fragments

__device__ __forceinline__ float swishf(float v) { return v / (1.0f + __expf(-v)); }

__device__ __forceinline__ uint32_t smem_u32(const void* p) {
    uint32_t a;
    asm("{ .reg .u64 t; cvta.to.shared.u64 t, %1; cvt.u32.u64 %0, t; }"
        : "=r"(a) : "l"(p));
    return a;
}

__device__ __forceinline__ void ldm_x4(uint32_t* r, uint32_t addr) {
    asm volatile("ldmatrix.sync.aligned.m8n8.x4.shared.b16 {%0,%1,%2,%3}, [%4];"
                 : "=r"(r[0]), "=r"(r[1]), "=r"(r[2]), "=r"(r[3]) : "r"(addr));
}

__device__ __forceinline__ void mma_bf16(float* d, const uint32_t* a, uint32_t b0, uint32_t b1) {
    asm volatile("mma.sync.aligned.m16n8k16.row.col.f32.bf16.bf16.f32 "
                 "{%0,%1,%2,%3}, {%4,%5,%6,%7}, {%8,%9}, {%0,%1,%2,%3};"
                 : "+f"(d[0]), "+f"(d[1]), "+f"(d[2]), "+f"(d[3])
                 : "r"(a[0]), "r"(a[1]), "r"(a[2]), "r"(a[3]), "r"(b0), "r"(b1));
}

// ---------------------------------------------------------------------------
// Weight conversion: W[K,N] f32 -> interleaved bf16 hi|lo fragments.
// u32 index = ((n8*KST + ks)*32 + lane)*4 + prec*2 + reg
// ---------------------------------------------------------------------------
__device__ __forceinline__ void wconv_one(const float* __restrict__ W,
                                          __nv_bfloat16* __restrict__ d16,
                                          int K, int N, int start, int stride)
{
    const int KST = K >> 4;
    for (int i = start; i < K * N; i += stride) {
        int k = i / N, n = i % N;
        float v = W[i];
        __nv_bfloat16 h = __float2bfloat16_rn(v);
        __nv_bfloat16 l = __float2bfloat16_rn(v - __bfloat162float(h));
        int ks = k >> 4, kin = k & 15, n8 = n >> 3, nin = n & 7;
        int lane = nin * 4 + ((kin & 7) >> 1);
        int reg  = kin >> 3;
        int half = kin & 1;
        int base32 = (((n8 * KST + ks) * 32 + lane) << 2) + reg;
        d16[(base32 << 1) + half]       = h;
        d16[((base32 + 2) << 1) + half] = l;
    }
}

struct W9 { const float* s[9]; unsigned off[9]; };

__global__ void wconv9_kernel(W9 w, char* base)
{
    const int wi = blockIdx.y;
    wconv_one(w.s[wi], (__nv_bfloat16*)(base + w.off[wi]), 128, 128,
              threadIdx.x + blockIdx.x * 256, 256 * gridDim.x);
}

struct W2 { const float* s[2]; unsigned off[2]; int K[2]; int N[2]; };

__global__ void wconv2_kernel(W2 w, char* base)
{
    const int wi = blockIdx.y;
    wconv_one(w.s[wi], (__nv_bfloat16*)(base + w.off[wi]), w.K[wi], w.N[wi],
              threadIdx.x + blockIdx.x * 256, 256 * gridDim.x);
}

// ---------------------------------------------------------------------------
// A staging: MT rows of f32 global -> bf16 hi/lo smem (row stride K+8 elems)
// ---------------------------------------------------------------------------
template<int K>
__device__ __forceinline__ void stage_A(const float* __restrict__ A, size_t rowBase,
                                        char* AhiB, char* AloB, int tid)
{
    constexpr int LDA = K + 8;
    const float4* Ab = (const float4*)(A + rowBase * K);
    constexpr int NF4 = MT * K / 4;
    #pragma unroll 4
    for (int i = tid; i < NF4; i += 256) {
        int r  = i / (K / 4);
        int c4 = (i % (K / 4)) * 4;
        float4 v = Ab[i];
        __nv_bfloat162 h01, h23, l01, l23;
        h01.x = __float2bfloat16_rn(v.x);
        h01.y = __float2bfloat16_rn(v.y);
        h23.x = __float2bfloat16_rn(v.z);
        h23.y = __float2bfloat16_rn(v.w);
        l01.x = __float2bfloat16_rn(v.x - __bfloat162float(h01.x));
        l01.y = __float2bfloat16_rn(v.y - __bfloat162float(h01.y));
        l23.x = __float2bfloat16_rn(v.z - __bfloat162float(h23.x));
        l23.y = __float2bfloat16_rn(v.w - __bfloat162float(h23.y));
        uint2 hv, lv;
        hv.x = *(uint32_t*)&h01; hv.y = *(uint32_t*)&h23;
        lv.x = *(uint32_t*)&l01; lv.y = *(uint32_t*)&l23;
        size_t off = (size_t)r * LDA * 2 + (size_t)c4 * 2;
        *(uint2*)(AhiB + off) = hv;
        *(uint2*)(AloB + off) = lv;
    }
}

// ---------------------------------------------------------------------------
// 3-term MMA mainloop, single pass over k-steps (R13-proven).
// ---------------------------------------------------------------------------
template<int N, int K>
__device__ __forceinline__ void run_mma(float (&acc)[N / 16][4],
                                        uint32_t aHiAddr, uint32_t aLoAddr,
                                        const uint32_t* __restrict__ Bpre,
                                        int lane, int n8base)
{
    constexpr int KST = K / 16;
    constexpr int N8  = N / 16;

    #pragma unroll
    for (int ks = 0; ks < KST; ks++) {
        uint32_t a_hi[4], a_lo[4];
        ldm_x4(a_hi, aHiAddr + ks * 32);
        ldm_x4(a_lo, aLoAddr + ks * 32);
        #pragma unroll
        for (int j = 0; j < N8; j++) {
            uint4 bb = *(const uint4*)(Bpre +
                ((((size_t)(n8base + j) * KST + ks) * 32 + lane) << 2));
            mma_bf16(acc[j], a_hi, bb.x, bb.y);
            mma_bf16(acc[j], a_hi, bb.z, bb.w);
            mma_bf16(acc[j], a_lo, bb.x, bb.y);
        }
    }
}

template<int N>
__device__ __forceinline__ void zero_acc(float (&acc)[N / 16][4])
{
    #pragma unroll
    for (int j = 0; j < N / 16; j++)
        #pragma unroll
        for (int q = 0; q < 4; q++) acc[j][q] = 0.0f;
}

__device__ __forceinline__ void store_hl(char* AhiB, char* AloB, int row, int col,
                                         float v0, float v1, int LDA2)
{
    __nv_bfloat162 h, l;
    h.x = __float2bfloat16_rn(v0);
    h.y = __float2bfloat16_rn(v1);
    l.x = __float2bfloat16_rn(v0 - __bfloat162float(h.x));
    l.y = __float2bfloat16_rn(v1 - __bfloat162float(h.y));
    *(__nv_bfloat162*)(AhiB + row * LDA2 + col * 2) = h;
    *(__nv_bfloat162*)(AloB + row * LDA2 + col * 2) = l;
}

// ---------------------------------------------------------------------------
// Edge mega-fusion (R13-proven, unchanged)
// ---------------------------------------------------------------------------
__global__ __launch_bounds__(256, 2) void edge_fused(
    const float*    __restrict__ m_input,
    const uint32_t* __restrict__ Bji, const float* __restrict__ bji,
    const uint32_t* __restrict__ Bkj, const float* __restrict__ bkj,
    const uint32_t* __restrict__ Bdown,
    const float*    __restrict__ Wg,
    const float*    __restrict__ rbf8,
    float*          __restrict__ m_pre,
    float*          __restrict__ ang)
{
    constexpr int K = 128, N = 128;
    constexpr int N8   = N / 16;
    constexpr int LDA  = K + 8;
    constexpr int LDA2 = LDA * 2;
    constexpr int ABYT = MT * LDA * 2;

    extern __shared__ __align__(16) char smem[];
    float* sbji = (float*)smem;
    float* sbkj = (float*)(smem + 512);
    float* sWg  = (float*)(smem + 1024);
    char*  AhiB = smem + 5120;
    char*  AloB = AhiB + ABYT;

    const int tid = threadIdx.x, wid = tid >> 5, lane = tid & 31;
    const size_t rowBase = (size_t)blockIdx.x * MT;

    for (int i = tid; i < N; i += 256) { sbji[i] = bji[i]; sbkj[i] = bkj[i]; }
    for (int i = tid; i < 8 * N; i += 256) sWg[i] = Wg[i];

    stage_A<K>(m_input, rowBase, AhiB, AloB, tid);
    __syncthreads();

    const int warpM = (wid & 3) * 16;
    const int warpN = (wid >> 2) * (N / 2);
    const int n8base = warpN >> 3;

    const uint32_t aHiAddr = smem_u32(AhiB) +
        (uint32_t)(warpM + (lane & 15)) * LDA2 + (uint32_t)(lane >> 4) * 16;
    const uint32_t aLoAddr = aHiAddr + (uint32_t)ABYT;

    const int r0 = lane >> 2;
    const int c0 = (lane & 3) * 2;

    float acc[N8][4];

    zero_acc<N>(acc);
    run_mma<N, K>(acc, aHiAddr, aLoAddr, Bji, lane, n8base);
    {
        const size_t gA = rowBase + warpM + r0;
        const size_t gB = gA + 8;
        #pragma unroll
        for (int j = 0; j < N8; j++) {
            const int col = warpN + j * 8 + c0;
            float b0 = sbji[col], b1 = sbji[col + 1];
            *(float2*)(m_pre + gA * N + col) =
                make_float2(swishf(acc[j][0] + b0), swishf(acc[j][1] + b1));
            *(float2*)(m_pre + gB * N + col) =
                make_float2(swishf(acc[j][2] + b0), swishf(acc[j][3] + b1));
        }
    }

    zero_acc<N>(acc);
    run_mma<N, K>(acc, aHiAddr, aLoAddr, Bkj, lane, n8base);
    __syncthreads();

    {
        const int rowA = warpM + r0;
        const int rowB = rowA + 8;
        const size_t gA = rowBase + rowA;
        const size_t gB = rowBase + rowB;

        float r8A[8], r8B[8];
        {
            float4 a0 = *(const float4*)(rbf8 + gA * 8);
            float4 a1 = *(const float4*)(rbf8 + gA * 8 + 4);
            float4 b0 = *(const float4*)(rbf8 + gB * 8);
            float4 b1 = *(const float4*)(rbf8 + gB * 8 + 4);
            r8A[0]=a0.x; r8A[1]=a0.y; r8A[2]=a0.z; r8A[3]=a0.w;
            r8A[4]=a1.x; r8A[5]=a1.y; r8A[6]=a1.z; r8A[7]=a1.w;
            r8B[0]=b0.x; r8B[1]=b0.y; r8B[2]=b0.z; r8B[3]=b0.w;
            r8B[4]=b1.x; r8B[5]=b1.y; r8B[6]=b1.z; r8B[7]=b1.w;
        }

        #pragma unroll
        for (int j = 0; j < N8; j++) {
            const int col = warpN + j * 8 + c0;
            float b0 = sbkj[col], b1 = sbkj[col + 1];
            float v0 = swishf(acc[j][0] + b0);
            float v1 = swishf(acc[j][1] + b1);
            float v2 = swishf(acc[j][2] + b0);
            float v3 = swishf(acc[j][3] + b1);
            float gA0 = 0.f, gA1 = 0.f, gB0 = 0.f, gB1 = 0.f;
            #pragma unroll
            for (int b = 0; b < 8; b++) {
                float w0 = sWg[b * N + col], w1 = sWg[b * N + col + 1];
                gA0 = fmaf(r8A[b], w0, gA0);
                gA1 = fmaf(r8A[b], w1, gA1);
                gB0 = fmaf(r8B[b], w0, gB0);
                gB1 = fmaf(r8B[b], w1, gB1);
            }
            v0 *= gA0; v1 *= gA1; v2 *= gB0; v3 *= gB1;
            store_hl(AhiB, AloB, rowA, col, v0, v1, LDA2);
            store_hl(AhiB, AloB, rowB, col, v2, v3, LDA2);
        }
    }
    __syncthreads();

    {
        constexpr int N2 = 64;
        constexpr int N28 = N2 / 16;
        float acc2[N28][4];
        zero_acc<N2>(acc2);
        const int warpN2 = (wid >> 2) * (N2 / 2);
        run_mma<N2, K>(acc2, aHiAddr, aLoAddr, Bdown, lane, warpN2 >> 3);

        const size_t gA = rowBase + warpM + r0;
        const size_t gB = gA + 8;
        #pragma unroll
        for (int j = 0; j < N28; j++) {
            const int col = warpN2 + j * 8 + c0;
            *(float2*)(ang + gA * N2 + col) =
                make_float2(swishf(acc2[j][0]), swishf(acc2[j][1]));
            *(float2*)(ang + gB * N2 + col) =
                make_float2(swishf(acc2[j][2]), swishf(acc2[j][3]));
        }
    }
}

// ---------------------------------------------------------------------------
// tail_fused: steps 7-11 in one kernel (8 GEMMs per CTA tile).
//   t  = swish(agg @ W_up) + m_pre            [Tf + A smem]
//   h1 = t + f_rb(f_rb(t))                    [Tf + A smem]
//   m2 = swish(h1 @ W_fin + b_fin) + m_input  [Tf + A smem]
//   t2 = m2 + f_ra0(f_ra0(m2))                [Tf + A smem]
//   out= t2 + f_ra1(f_ra1(t2))                [global]
// ---------------------------------------------------------------------------
#define LDT 132

struct TailW {
    const uint32_t *up, *rb0, *rb1, *fin, *ra00, *ra01, *ra10, *ra11;
    const float *b_rb0, *b_rb1, *b_fin, *b_ra00, *b_ra01, *b_ra10, *b_ra11;
};

__global__ __launch_bounds__(256, 2) void tail_fused(
    const float* __restrict__ agg,
    const float* __restrict__ m_pre,
    const float* __restrict__ m_input,
    TailW w,
    float* __restrict__ out)
{
    constexpr int N = 128;
    constexpr int N8 = N / 16;
    constexpr int LDA2_128 = 272;
    constexpr int LDA2_64  = 144;
    constexpr int ABYT = MT * 136 * 2;

    extern __shared__ __align__(16) char smem[];
    float* sb   = (float*)smem;                 // 7 x 128 bias vectors
    float* Tf   = (float*)(smem + 4096);
    char*  AhiB = smem + 4096 + MT * LDT * 4;
    char*  AloB = AhiB + ABYT;

    const int tid = threadIdx.x, wid = tid >> 5, lane = tid & 31;
    const size_t rowBase = (size_t)blockIdx.x * MT;

    // load 7 biases
    {
        const float* bs[7] = { w.b_rb0, w.b_rb1, w.b_fin, w.b_ra00, w.b_ra01, w.b_ra10, w.b_ra11 };
        for (int v = 0; v < 7; v++)
            for (int i = tid; i < N; i += 256) sb[v * 128 + i] = bs[v][i];
    }

    stage_A<64>(agg, rowBase, AhiB, AloB, tid);
    __syncthreads();

    const int warpM = (wid & 3) * 16;
    const int warpN = (wid >> 2) * (N / 2);
    const int n8base = warpN >> 3;
    const int r0 = lane >> 2;
    const int c0 = (lane & 3) * 2;
    const int rowA = warpM + r0;
    const int rowB = rowA + 8;
    const size_t gA = rowBase + rowA;
    const size_t gB = rowBase + rowB;

    const uint32_t aOff128 = (uint32_t)(warpM + (lane & 15)) * LDA2_128 + (uint32_t)(lane >> 4) * 16;
    const uint32_t aOff64  = (uint32_t)(warpM + (lane & 15)) * LDA2_64  + (uint32_t)(lane >> 4) * 16;
    const uint32_t hiBase = smem_u32(AhiB);
    const uint32_t loBase = smem_u32(AloB);

    float acc[N8][4];

    // ---- 1: up (K=64): t = swish(acc) + m_pre -> Tf + A ----
    zero_acc<N>(acc);
    run_mma<N, 64>(acc, hiBase + aOff64, loBase + aOff64, w.up, lane, n8base);
    __syncthreads();
    #pragma unroll
    for (int j = 0; j < N8; j++) {
        const int col = warpN + j * 8 + c0;
        float v0 = swishf(acc[j][0]);
        float v1 = swishf(acc[j][1]);
        float v2 = swishf(acc[j][2]);
        float v3 = swishf(acc[j][3]);
        float2 eA = *(const float2*)(m_pre + gA * N + col);
        float2 eB = *(const float2*)(m_pre + gB * N + col);
        v0 += eA.x; v1 += eA.y; v2 += eB.x; v3 += eB.y;
        *(float2*)(Tf + rowA * LDT + col) = make_float2(v0, v1);
        *(float2*)(Tf + rowB * LDT + col) = make_float2(v2, v3);
        store_hl(AhiB, AloB, rowA, col, v0, v1, LDA2_128);
        store_hl(AhiB, AloB, rowB, col, v2, v3, LDA2_128);
        acc[j][0] = 0.f; acc[j][1] = 0.f; acc[j][2] = 0.f; acc[j][3] = 0.f;
    }
    __syncthreads();

    // ---- 2: rb0: swish -> A ----
    run_mma<N, 128>(acc, hiBase + aOff128, loBase + aOff128, w.rb0, lane, n8base);
    __syncthreads();
    #pragma unroll
    for (int j = 0; j < N8; j++) {
        const int col = warpN + j * 8 + c0;
        float b0 = sb[0 * 128 + col], b1 = sb[0 * 128 + col + 1];
        store_hl(AhiB, AloB, rowA, col, swishf(acc[j][0] + b0), swishf(acc[j][1] + b1), LDA2_128);
        store_hl(AhiB, AloB, rowB, col, swishf(acc[j][2] + b0), swishf(acc[j][3] + b1), LDA2_128);
        acc[j][0] = 0.f; acc[j][1] = 0.f; acc[j][2] = 0.f; acc[j][3] = 0.f;
    }
    __syncthreads();

    // ---- 3: rb1: h1 = Tf + swish -> Tf + A ----
    run_mma<N, 128>(acc, hiBase + aOff128, loBase + aOff128, w.rb1, lane, n8base);
    __syncthreads();
    #pragma unroll
    for (int j = 0; j < N8; j++) {
        const int col = warpN + j * 8 + c0;
        float b0 = sb[1 * 128 + col], b1 = sb[1 * 128 + col + 1];
        float2 tA = *(const float2*)(Tf + rowA * LDT + col);
        float2 tB = *(const float2*)(Tf + rowB * LDT + col);
        float v0 = tA.x + swishf(acc[j][0] + b0);
        float v1 = tA.y + swishf(acc[j][1] + b1);
        float v2 = tB.x + swishf(acc[j][2] + b0);
        float v3 = tB.y + swishf(acc[j][3] + b1);
        *(float2*)(Tf + rowA * LDT + col) = make_float2(v0, v1);
        *(float2*)(Tf + rowB * LDT + col) = make_float2(v2, v3);
        store_hl(AhiB, AloB, rowA, col, v0, v1, LDA2_128);
        store_hl(AhiB, AloB, rowB, col, v2, v3, LDA2_128);
        acc[j][0] = 0.f; acc[j][1] = 0.f; acc[j][2] = 0.f; acc[j][3] = 0.f;
    }
    __syncthreads();

    // ---- 4: fin: m2 = swish(+b_fin) + m_input -> Tf + A ----
    run_mma<N, 128>(acc, hiBase + aOff128, loBase + aOff128, w.fin, lane, n8base);
    __syncthreads();
    #pragma unroll
    for (int j = 0; j < N8; j++) {
        const int col = warpN + j * 8 + c0;
        float b0 = sb[2 * 128 + col], b1 = sb[2 * 128 + col + 1];
        float v0 = swishf(acc[j][0] + b0);
        float v1 = swishf(acc[j][1] + b1);
        float v2 = swishf(acc[j][2] + b0);
        float v3 = swishf(acc[j][3] + b1);
        float2 eA = *(const float2*)(m_input + gA * N + col);
        float2 eB = *(const float2*)(m_input + gB * N + col);
        v0 += eA.x; v1 += eA.y; v2 += eB.x; v3 += eB.y;
        *(float2*)(Tf + rowA * LDT + col) = make_float2(v0, v1);
        *(float2*)(Tf + rowB * LDT + col) = make_float2(v2, v3);
        store_hl(AhiB, AloB, rowA, col, v0, v1, LDA2_128);
        store_hl(AhiB, AloB, rowB, col, v2, v3, LDA2_128);
        acc[j][0] = 0.f; acc[j][1] = 0.f; acc[j][2] = 0.f; acc[j][3] = 0.f;
    }
    __syncthreads();

    // ---- 5: ra00: swish -> A ----
    run_mma<N, 128>(acc, hiBase + aOff128, loBase + aOff128, w.ra00, lane, n8base);
    __syncthreads();
    #pragma unroll
    for (int j = 0; j < N8; j++) {
        const int col = warpN + j * 8 + c0;
        float b0 = sb[3 * 128 + col], b1 = sb[3 * 128 + col + 1];
        store_hl(AhiB, AloB, rowA, col, swishf(acc[j][0] + b0), swishf(acc[j][1] + b1), LDA2_128);
        store_hl(AhiB, AloB, rowB, col, swishf(acc[j][2] + b0), swishf(acc[j][3] + b1), LDA2_128);
        acc[j][0] = 0.f; acc[j][1] = 0.f; acc[j][2] = 0.f; acc[j][3] = 0.f;
    }
    __syncthreads();

    // ---- 6: ra01: t2 = Tf + swish -> Tf + A ----
    run_mma<N, 128>(acc, hiBase + aOff128, loBase + aOff128, w.ra01, lane, n8base);
    __syncthreads();
    #pragma unroll
    for (int j = 0; j < N8; j++) {
        const int col = warpN + j * 8 + c0;
        float b0 = sb[4 * 128 + col], b1 = sb[4 * 128 + col + 1];
        float2 tA = *(const float2*)(Tf + rowA * LDT + col);
        float2 tB = *(const float2*)(Tf + rowB * LDT + col);
        float v0 = tA.x + swishf(acc[j][0] + b0);
        float v1 = tA.y + swishf(acc[j][1] + b1);
        float v2 = tB.x + swishf(acc[j][2] + b0);
        float v3 = tB.y + swishf(acc[j][3] + b1);
        *(float2*)(Tf + rowA * LDT + col) = make_float2(v0, v1);
        *(float2*)(Tf + rowB * LDT + col) = make_float2(v2, v3);
        store_hl(AhiB, AloB, rowA, col, v0, v1, LDA2_128);
        store_hl(AhiB, AloB, rowB, col, v2, v3, LDA2_128);
        acc[j][0] = 0.f; acc[j][1] = 0.f; acc[j][2] = 0.f; acc[j][3] = 0.f;
    }
    __syncthreads();

    // ---- 7: ra10: swish -> A ----
    run_mma<N, 128>(acc, hiBase + aOff128, loBase + aOff128, w.ra10, lane, n8base);
    __syncthreads();
    #pragma unroll
    for (int j = 0; j < N8; j++) {
        const int col = warpN + j * 8 + c0;
        float b0 = sb[5 * 128 + col], b1 = sb[5 * 128 + col + 1];
        store_hl(AhiB, AloB, rowA, col, swishf(acc[j][0] + b0), swishf(acc[j][1] + b1), LDA2_128);
        store_hl(AhiB, AloB, rowB, col, swishf(acc[j][2] + b0), swishf(acc[j][3] + b1), LDA2_128);
        acc[j][0] = 0.f; acc[j][1] = 0.f; acc[j][2] = 0.f; acc[j][3] = 0.f;
    }
    __syncthreads();

    // ---- 8: ra11: out = Tf + swish -> global ----
    run_mma<N, 128>(acc, hiBase + aOff128, loBase + aOff128, w.ra11, lane, n8base);
    #pragma unroll
    for (int j = 0; j < N8; j++) {
        const int col = warpN + j * 8 + c0;
        float b0 = sb[6 * 128 + col], b1 = sb[6 * 128 + col + 1];
        float2 tA = *(const float2*)(Tf + rowA * LDT + col);
        float2 tB = *(const float2*)(Tf + rowB * LDT + col);
        *(float2*)(out + gA * N + col) =
            make_float2(tA.x + swishf(acc[j][0] + b0), tA.y + swishf(acc[j][1] + b1));
        *(float2*)(out + gB * N + col) =
            make_float2(tB.x + swishf(acc[j][2] + b0), tB.y + swishf(acc[j][3] + b1));
    }
}

// ---------------------------------------------------------------------------
// proj8: out[rows x 8] = X[rows x NIN] @ W[NIN x 8]
// ---------------------------------------------------------------------------
template<int NIN>
__global__ __launch_bounds__(256) void proj8_kernel(
    const float* __restrict__ X, const float* __restrict__ W,
    float* __restrict__ out)
{
    __shared__ float tile[256 * NIN];
    __shared__ float Ws[NIN * 8];
    const size_t base = (size_t)blockIdx.x * 256;
    constexpr int NT4 = 256 * NIN / 4;
    const float4* src = (const float4*)(X + base * NIN);
    #pragma unroll 4
    for (int i = threadIdx.x; i < NT4; i += 256)
        ((float4*)tile)[i] = src[i];
    for (int i = threadIdx.x; i < NIN * 8; i += 256)
        Ws[i] = W[i];
    __syncthreads();

    const float* x = &tile[threadIdx.x * NIN];
    float o[8] = {0, 0, 0, 0, 0, 0, 0, 0};
    #pragma unroll
    for (int c = 0; c < NIN; c++) {
        float xv = x[c];
        #pragma unroll
        for (int b = 0; b < 8; b++)
            o[b] = fmaf(xv, Ws[c * 8 + b], o[b]);
    }
    float4* op = (float4*)(out + (base + threadIdx.x) * 8);
    op[0] = make_float4(o[0], o[1], o[2], o[3]);
    op[1] = make_float4(o[4], o[5], o[6], o[7]);
}

__global__ void zero_kernel(float4* __restrict__ p, size_t n4)
{
    size_t i = (size_t)blockIdx.x * blockDim.x + threadIdx.x;
    if (i < n4) p[i] = make_float4(0.f, 0.f, 0.f, 0.f);
}

// ---------------------------------------------------------------------------
// Triplet gather/gate/scatter -- 2 triplets per 16-lane group
// ---------------------------------------------------------------------------
__global__ __launch_bounds__(256, 8) void triplet_kernel(
    const int* __restrict__ expand_to_kj,
    const int* __restrict__ reduce_to_ji,
    const float* __restrict__ sbf8,
    const float* __restrict__ Wsbf2,
    const float* __restrict__ ang,
    float* __restrict__ agg)
{
    __shared__ float Ws[8 * 64];
    for (int i = threadIdx.x; i < 512; i += 256) Ws[i] = Wsbf2[i];
    __syncthreads();

    const int lane16 = threadIdx.x & 15;
    const size_t grp = ((size_t)blockIdx.x * 256 + threadIdx.x) >> 4;
    const size_t t0 = grp * 2;
    const size_t t1 = t0 + 1;

    const int ekj0 = __ldg(&expand_to_kj[t0]);
    const int ekj1 = __ldg(&expand_to_kj[t1]);
    const int eji0 = __ldg(&reduce_to_ji[t0]);
    const int eji1 = __ldg(&reduce_to_ji[t1]);

    float4 a0 = __ldg((const float4*)(ang + (size_t)ekj0 * 64 + lane16 * 4));
    float4 a1 = __ldg((const float4*)(ang + (size_t)ekj1 * 64 + lane16 * 4));

    const float* s0 = sbf8 + t0 * 8;
    const float* s1 = sbf8 + t1 * 8;

    float g00 = 0.f, g01 = 0.f, g02 = 0.f, g03 = 0.f;
    float g10 = 0.f, g11 = 0.f, g12 = 0.f, g13 = 0.f;
    #pragma unroll
    for (int b = 0; b < 8; b++) {
        const float sb0 = __ldg(&s0[b]);
        const float sb1 = __ldg(&s1[b]);
        const float* w = &Ws[b * 64 + lane16 * 4];
        float w0 = w[0], w1 = w[1], w2 = w[2], w3 = w[3];
        g00 = fmaf(sb0, w0, g00); g01 = fmaf(sb0, w1, g01);
        g02 = fmaf(sb0, w2, g02); g03 = fmaf(sb0, w3, g03);
        g10 = fmaf(sb1, w0, g10); g11 = fmaf(sb1, w1, g11);
        g12 = fmaf(sb1, w2, g12); g13 = fmaf(sb1, w3, g13);
    }

    float v00 = a0.x * g00, v01 = a0.y * g01, v02 = a0.z * g02, v03 = a0.w * g03;
    float v10 = a1.x * g10, v11 = a1.y * g11, v12 = a1.z * g12, v13 = a1.w * g13;

    float* d0 = agg + (size_t)eji0 * 64 + lane16 * 4;
    float* d1 = agg + (size_t)eji1 * 64 + lane16 * 4;
    asm volatile("red.global.add.v4.f32 [%0], {%1,%2,%3,%4};"
                 :: "l"(d0), "f"(v00), "f"(v01), "f"(v02), "f"(v03) : "memory");
    asm volatile("red.global.add.v4.f32 [%0], {%1,%2,%3,%4};"
                 :: "l"(d1), "f"(v10), "f"(v11), "f"(v12), "f"(v13) : "memory");
}

// ---------------------------------------------------------------------------
// Host orchestration
// ---------------------------------------------------------------------------
static inline int edge_smemsz() { return 5120 + 2 * (MT * 136 * 2); }
static inline int tail_smemsz() { return 4096 + MT * LDT * 4 + 2 * (MT * 136 * 2); }

extern "C" void kernel_launch(void* const* d_in, const int* in_sizes, int n_in,
                              void* d_out, int out_size)
{
    const float* m_input = (const float*)d_in[0];
    const float* rbf     = (const float*)d_in[1];
    const float* sbf     = (const float*)d_in[2];
    const int*   expand  = (const int*)  d_in[3];
    const int*   reduce  = (const int*)  d_in[4];
    const float* W_kj    = (const float*)d_in[5];
    const float* b_kj    = (const float*)d_in[6];
    const float* W_rbf1  = (const float*)d_in[7];
    const float* W_rbf2  = (const float*)d_in[8];
    const float* W_sbf1  = (const float*)d_in[9];
    const float* W_sbf2  = (const float*)d_in[10];
    const float* W_down  = (const float*)d_in[11];
    const float* W_up    = (const float*)d_in[12];
    const float* W_ji    = (const float*)d_in[13];
    const float* b_ji    = (const float*)d_in[14];
    const float* W_res_b = (const float*)d_in[15];
    const float* b_res_b = (const float*)d_in[16];
    const float* W_final = (const float*)d_in[17];
    const float* b_final = (const float*)d_in[18];
    const float* W_res_a = (const float*)d_in[19];
    const float* b_res_a = (const float*)d_in[20];
    float* out = (float*)d_out;

    const int E = in_sizes[0] / 128;
    const int T = in_sizes[3];

    float *ang, *agg, *m, *rbf8, *sbf8, *wb;
    cudaGetSymbolAddress((void**)&ang,  g_ang);
    cudaGetSymbolAddress((void**)&agg,  g_agg);
    cudaGetSymbolAddress((void**)&m,    g_m);
    cudaGetSymbolAddress((void**)&rbf8, g_rbf8);
    cudaGetSymbolAddress((void**)&sbf8, g_sbf8);
    cudaGetSymbolAddress((void**)&wb,   g_wb);

    cudaFuncSetAttribute(edge_fused,
                         cudaFuncAttributeMaxDynamicSharedMemorySize, edge_smemsz());
    cudaFuncSetAttribute(tail_fused,
                         cudaFuncAttributeMaxDynamicSharedMemorySize, tail_smemsz());

    char* wbb = (char*)wb;
    auto wat = [&](size_t off) { return (const uint32_t*)(wbb + off); };
    const unsigned OF_KJ = 0, OF_JI = 65536, OF_RB0 = 131072, OF_RB1 = 196608,
                   OF_FIN = 262144, OF_RA00 = 327680, OF_RA01 = 393216,
                   OF_RA10 = 458752, OF_RA11 = 524288,
                   OF_DOWN = 589824, OF_UP = 622592;

    // 0-1: weight conversion (interleaved hi|lo layout)
    {
        W9 w;
        w.s[0] = W_kj;            w.off[0] = OF_KJ;
        w.s[1] = W_ji;            w.off[1] = OF_JI;
        w.s[2] = W_res_b;         w.off[2] = OF_RB0;
        w.s[3] = W_res_b + 16384; w.off[3] = OF_RB1;
        w.s[4] = W_final;         w.off[4] = OF_FIN;
        w.s[5] = W_res_a;         w.off[5] = OF_RA00;
        w.s[6] = W_res_a + 16384; w.off[6] = OF_RA01;
        w.s[7] = W_res_a + 32768; w.off[7] = OF_RA10;
        w.s[8] = W_res_a + 49152; w.off[8] = OF_RA11;
        wconv9_kernel<<<dim3(8, 9), 256>>>(w, wbb);

        W2 w2;
        w2.s[0] = W_down; w2.off[0] = OF_DOWN; w2.K[0] = 128; w2.N[0] = 64;
        w2.s[1] = W_up;   w2.off[1] = OF_UP;   w2.K[1] = 64;  w2.N[1] = 128;
        wconv2_kernel<<<dim3(8, 2), 256>>>(w2, wbb);
    }

    const int GE = E / MT;   // 4096

    // 2: rbf8
    proj8_kernel<6><<<E / 256, 256>>>(rbf, W_rbf1, rbf8);

    // 3: edge fusion: m_pre -> g_m, ang -> g_ang    [ncu idx 3]
    edge_fused<<<GE, 256, edge_smemsz()>>>(
        m_input, wat(OF_JI), b_ji, wat(OF_KJ), b_kj, wat(OF_DOWN),
        W_rbf2, rbf8, m, ang);

    // 4: sbf8
    proj8_kernel<42><<<T / 256, 256>>>(sbf, W_sbf1, sbf8);

    // 5: agg = 0
    {
        size_t n4 = (size_t)E * 64 / 4;
        zero_kernel<<<(unsigned)((n4 + 255) / 256), 256>>>((float4*)agg, n4);
    }

    // 6: scatter
    triplet_kernel<<<(unsigned)((size_t)T * 16 / 256 / 2), 256>>>(
        expand, reduce, sbf8, W_sbf2, ang, agg);

    // 7: tail: steps 7-11 fused -> out
    {
        TailW w;
        w.up   = wat(OF_UP);
        w.rb0  = wat(OF_RB0);  w.b_rb0  = b_res_b;
        w.rb1  = wat(OF_RB1);  w.b_rb1  = b_res_b + 128;
        w.fin  = wat(OF_FIN);  w.b_fin  = b_final;
        w.ra00 = wat(OF_RA00); w.b_ra00 = b_res_a;
        w.ra01 = wat(OF_RA01); w.b_ra01 = b_res_a + 128;
        w.ra10 = wat(OF_RA10); w.b_ra10 = b_res_a + 256;
        w.ra11 = wat(OF_RA11); w.b_ra11 = b_res_a + 384;
        tail_fused<<<GE, 256, tail_smemsz()>>>(agg, m, m_input, w, out);
    }
}

// round 15
// speedup vs baseline: 1.4886x; 1.0164x over previous
#include <cuda_runtime.h>
#include <cuda_bf16.h>
#include <cstdint>

// ---------------------------------------------------------------------------
// Problem constants
// ---------------------------------------------------------------------------
#define E_MAX 262144
#define T_MAX 2097152
#define MT    64          // rows per CTA tile

// ---------------------------------------------------------------------------
// Scratch (device globals -- no allocation allowed)
// ---------------------------------------------------------------------------
__device__ float g_ang [(size_t)E_MAX * 64];
__device__ float g_agg [(size_t)E_MAX * 64];
__device__ float g_rbf8[(size_t)E_MAX * 8];
__device__ float g_sbf8[(size_t)T_MAX * 8];
__device__ float g_wb  [163840];   // 640KB: bf16 hi|lo interleaved weight fragments

__device__ __forceinline__ float swishf(float v) { return v / (1.0f + __expf(-v)); }

__device__ __forceinline__ uint32_t smem_u32(const void* p) {
    uint32_t a;
    asm("{ .reg .u64 t; cvta.to.shared.u64 t, %1; cvt.u32.u64 %0, t; }"
        : "=r"(a) : "l"(p));
    return a;
}

__device__ __forceinline__ void ldm_x4(uint32_t* r, uint32_t addr) {
    asm volatile("ldmatrix.sync.aligned.m8n8.x4.shared.b16 {%0,%1,%2,%3}, [%4];"
                 : "=r"(r[0]), "=r"(r[1]), "=r"(r[2]), "=r"(r[3]) : "r"(addr));
}

__device__ __forceinline__ void mma_bf16(float* d, const uint32_t* a, uint32_t b0, uint32_t b1) {
    asm volatile("mma.sync.aligned.m16n8k16.row.col.f32.bf16.bf16.f32 "
                 "{%0,%1,%2,%3}, {%4,%5,%6,%7}, {%8,%9}, {%0,%1,%2,%3};"
                 : "+f"(d[0]), "+f"(d[1]), "+f"(d[2]), "+f"(d[3])
                 : "r"(a[0]), "r"(a[1]), "r"(a[2]), "r"(a[3]), "r"(b0), "r"(b1));
}

// ---------------------------------------------------------------------------
// Weight conversion: W[K,N] f32 -> interleaved bf16 hi|lo fragments.
// u32 index = ((n8*KST + ks)*32 + lane)*4 + prec*2 + reg
// ---------------------------------------------------------------------------
__device__ __forceinline__ void wconv_one(const float* __restrict__ W,
                                          __nv_bfloat16* __restrict__ d16,
                                          int K, int N, int start, int stride)
{
    const int KST = K >> 4;
    for (int i = start; i < K * N; i += stride) {
        int k = i / N, n = i % N;
        float v = W[i];
        __nv_bfloat16 h = __float2bfloat16_rn(v);
        __nv_bfloat16 l = __float2bfloat16_rn(v - __bfloat162float(h));
        int ks = k >> 4, kin = k & 15, n8 = n >> 3, nin = n & 7;
        int lane = nin * 4 + ((kin & 7) >> 1);
        int reg  = kin >> 3;
        int half = kin & 1;
        int base32 = (((n8 * KST + ks) * 32 + lane) << 2) + reg;
        d16[(base32 << 1) + half]       = h;
        d16[((base32 + 2) << 1) + half] = l;
    }
}

struct W9 { const float* s[9]; unsigned off[9]; };

__global__ void wconv9_kernel(W9 w, char* base)
{
    const int wi = blockIdx.y;
    wconv_one(w.s[wi], (__nv_bfloat16*)(base + w.off[wi]), 128, 128,
              threadIdx.x + blockIdx.x * 256, 256 * gridDim.x);
}

struct W2 { const float* s[2]; unsigned off[2]; int K[2]; int N[2]; };

__global__ void wconv2_kernel(W2 w, char* base)
{
    const int wi = blockIdx.y;
    wconv_one(w.s[wi], (__nv_bfloat16*)(base + w.off[wi]), w.K[wi], w.N[wi],
              threadIdx.x + blockIdx.x * 256, 256 * gridDim.x);
}

// ---------------------------------------------------------------------------
// A staging: MT rows of f32 global -> bf16 hi/lo smem (row stride K+8 elems)
// ---------------------------------------------------------------------------
template<int K>
__device__ __forceinline__ void stage_A(const float* __restrict__ A, size_t rowBase,
                                        char* AhiB, char* AloB, int tid)
{
    constexpr int LDA = K + 8;
    const float4* Ab = (const float4*)(A + rowBase * K);
    constexpr int NF4 = MT * K / 4;
    #pragma unroll 4
    for (int i = tid; i < NF4; i += 256) {
        int r  = i / (K / 4);
        int c4 = (i % (K / 4)) * 4;
        float4 v = Ab[i];
        __nv_bfloat162 h01, h23, l01, l23;
        h01.x = __float2bfloat16_rn(v.x);
        h01.y = __float2bfloat16_rn(v.y);
        h23.x = __float2bfloat16_rn(v.z);
        h23.y = __float2bfloat16_rn(v.w);
        l01.x = __float2bfloat16_rn(v.x - __bfloat162float(h01.x));
        l01.y = __float2bfloat16_rn(v.y - __bfloat162float(h01.y));
        l23.x = __float2bfloat16_rn(v.z - __bfloat162float(h23.x));
        l23.y = __float2bfloat16_rn(v.w - __bfloat162float(h23.y));
        uint2 hv, lv;
        hv.x = *(uint32_t*)&h01; hv.y = *(uint32_t*)&h23;
        lv.x = *(uint32_t*)&l01; lv.y = *(uint32_t*)&l23;
        size_t off = (size_t)r * LDA * 2 + (size_t)c4 * 2;
        *(uint2*)(AhiB + off) = hv;
        *(uint2*)(AloB + off) = lv;
    }
}

// ---------------------------------------------------------------------------
// 3-term MMA mainloop, single pass over k-steps (R13-proven).
// ---------------------------------------------------------------------------
template<int N, int K>
__device__ __forceinline__ void run_mma(float (&acc)[N / 16][4],
                                        uint32_t aHiAddr, uint32_t aLoAddr,
                                        const uint32_t* __restrict__ Bpre,
                                        int lane, int n8base)
{
    constexpr int KST = K / 16;
    constexpr int N8  = N / 16;

    #pragma unroll
    for (int ks = 0; ks < KST; ks++) {
        uint32_t a_hi[4], a_lo[4];
        ldm_x4(a_hi, aHiAddr + ks * 32);
        ldm_x4(a_lo, aLoAddr + ks * 32);
        #pragma unroll
        for (int j = 0; j < N8; j++) {
            uint4 bb = *(const uint4*)(Bpre +
                ((((size_t)(n8base + j) * KST + ks) * 32 + lane) << 2));
            mma_bf16(acc[j], a_hi, bb.x, bb.y);
            mma_bf16(acc[j], a_hi, bb.z, bb.w);
            mma_bf16(acc[j], a_lo, bb.x, bb.y);
        }
    }
}

template<int N>
__device__ __forceinline__ void zero_acc(float (&acc)[N / 16][4])
{
    #pragma unroll
    for (int j = 0; j < N / 16; j++)
        #pragma unroll
        for (int q = 0; q < 4; q++) acc[j][q] = 0.0f;
}

__device__ __forceinline__ void store_hl(char* AhiB, char* AloB, int row, int col,
                                         float v0, float v1, int LDA2)
{
    __nv_bfloat162 h, l;
    h.x = __float2bfloat16_rn(v0);
    h.y = __float2bfloat16_rn(v1);
    l.x = __float2bfloat16_rn(v0 - __bfloat162float(h.x));
    l.y = __float2bfloat16_rn(v1 - __bfloat162float(h.y));
    *(__nv_bfloat162*)(AhiB + row * LDA2 + col * 2) = h;
    *(__nv_bfloat162*)(AloB + row * LDA2 + col * 2) = l;
}

// ---------------------------------------------------------------------------
// Edge fusion (kj+gate -> down), m_pre moved to tail_fused.
//   h1  = swish(m_input @ W_kj + b_kj) * (rbf8 @ Wg)   -> A smem (bf16)
//   ang = swish(h1 @ W_down)                           -> g_ang
// ---------------------------------------------------------------------------
__global__ __launch_bounds__(256, 2) void edge_fused(
    const float*    __restrict__ m_input,
    const uint32_t* __restrict__ Bkj, const float* __restrict__ bkj,
    const uint32_t* __restrict__ Bdown,
    const float*    __restrict__ Wg,
    const float*    __restrict__ rbf8,
    float*          __restrict__ ang)
{
    constexpr int K = 128, N = 128;
    constexpr int N8   = N / 16;
    constexpr int LDA  = K + 8;
    constexpr int LDA2 = LDA * 2;
    constexpr int ABYT = MT * LDA * 2;

    extern __shared__ __align__(16) char smem[];
    float* sbkj = (float*)smem;              // 512 B
    float* sWg  = (float*)(smem + 512);      // 4 KB
    char*  AhiB = smem + 5120;
    char*  AloB = AhiB + ABYT;

    const int tid = threadIdx.x, wid = tid >> 5, lane = tid & 31;
    const size_t rowBase = (size_t)blockIdx.x * MT;

    for (int i = tid; i < N; i += 256) sbkj[i] = bkj[i];
    for (int i = tid; i < 8 * N; i += 256) sWg[i] = Wg[i];

    stage_A<K>(m_input, rowBase, AhiB, AloB, tid);
    __syncthreads();

    const int warpM = (wid & 3) * 16;
    const int warpN = (wid >> 2) * (N / 2);
    const int n8base = warpN >> 3;

    const uint32_t aHiAddr = smem_u32(AhiB) +
        (uint32_t)(warpM + (lane & 15)) * LDA2 + (uint32_t)(lane >> 4) * 16;
    const uint32_t aLoAddr = aHiAddr + (uint32_t)ABYT;

    const int r0 = lane >> 2;
    const int c0 = (lane & 3) * 2;

    float acc[N8][4];

    // ---- GEMM 1: W_kj + rbf gate -> h1 into A smem ----
    zero_acc<N>(acc);
    run_mma<N, K>(acc, aHiAddr, aLoAddr, Bkj, lane, n8base);
    __syncthreads();   // everyone done reading A before overwrite

    {
        const int rowA = warpM + r0;
        const int rowB = rowA + 8;
        const size_t gA = rowBase + rowA;
        const size_t gB = rowBase + rowB;

        float r8A[8], r8B[8];
        {
            float4 a0 = *(const float4*)(rbf8 + gA * 8);
            float4 a1 = *(const float4*)(rbf8 + gA * 8 + 4);
            float4 b0 = *(const float4*)(rbf8 + gB * 8);
            float4 b1 = *(const float4*)(rbf8 + gB * 8 + 4);
            r8A[0]=a0.x; r8A[1]=a0.y; r8A[2]=a0.z; r8A[3]=a0.w;
            r8A[4]=a1.x; r8A[5]=a1.y; r8A[6]=a1.z; r8A[7]=a1.w;
            r8B[0]=b0.x; r8B[1]=b0.y; r8B[2]=b0.z; r8B[3]=b0.w;
            r8B[4]=b1.x; r8B[5]=b1.y; r8B[6]=b1.z; r8B[7]=b1.w;
        }

        #pragma unroll
        for (int j = 0; j < N8; j++) {
            const int col = warpN + j * 8 + c0;
            float b0 = sbkj[col], b1 = sbkj[col + 1];
            float v0 = swishf(acc[j][0] + b0);
            float v1 = swishf(acc[j][1] + b1);
            float v2 = swishf(acc[j][2] + b0);
            float v3 = swishf(acc[j][3] + b1);
            float gA0 = 0.f, gA1 = 0.f, gB0 = 0.f, gB1 = 0.f;
            #pragma unroll
            for (int b = 0; b < 8; b++) {
                float w0 = sWg[b * N + col], w1 = sWg[b * N + col + 1];
                gA0 = fmaf(r8A[b], w0, gA0);
                gA1 = fmaf(r8A[b], w1, gA1);
                gB0 = fmaf(r8B[b], w0, gB0);
                gB1 = fmaf(r8B[b], w1, gB1);
            }
            v0 *= gA0; v1 *= gA1; v2 *= gB0; v3 *= gB1;
            store_hl(AhiB, AloB, rowA, col, v0, v1, LDA2);
            store_hl(AhiB, AloB, rowB, col, v2, v3, LDA2);
        }
    }
    __syncthreads();

    // ---- GEMM 2: W_down (N=64) -> ang ----
    {
        constexpr int N2 = 64;
        constexpr int N28 = N2 / 16;
        float acc2[N28][4];
        zero_acc<N2>(acc2);
        const int warpN2 = (wid >> 2) * (N2 / 2);
        run_mma<N2, K>(acc2, aHiAddr, aLoAddr, Bdown, lane, warpN2 >> 3);

        const size_t gA = rowBase + warpM + r0;
        const size_t gB = gA + 8;
        #pragma unroll
        for (int j = 0; j < N28; j++) {
            const int col = warpN2 + j * 8 + c0;
            *(float2*)(ang + gA * N2 + col) =
                make_float2(swishf(acc2[j][0]), swishf(acc2[j][1]));
            *(float2*)(ang + gB * N2 + col) =
                make_float2(swishf(acc2[j][2]), swishf(acc2[j][3]));
        }
    }
}

// ---------------------------------------------------------------------------
// tail_fused: steps 7-11 + the ji-GEMM, 9 GEMMs per CTA tile.
//   m_pre = swish(m_input @ W_ji + b_ji)       [Tf]
//   t  = swish(agg @ W_up) + m_pre             [Tf + A smem]
//   h1 = t + f_rb(f_rb(t))                     [Tf + A smem]
//   m2 = swish(h1 @ W_fin + b_fin) + m_input   [Tf + A smem]
//   t2 = m2 + f_ra0(f_ra0(m2))                 [Tf + A smem]
//   out= t2 + f_ra1(f_ra1(t2))                 [global]
// ---------------------------------------------------------------------------
#define LDT 132

struct TailW {
    const uint32_t *ji, *up, *rb0, *rb1, *fin, *ra00, *ra01, *ra10, *ra11;
    const float *b_ji, *b_rb0, *b_rb1, *b_fin, *b_ra00, *b_ra01, *b_ra10, *b_ra11;
};

__global__ __launch_bounds__(256, 2) void tail_fused(
    const float* __restrict__ agg,
    const float* __restrict__ m_input,
    TailW w,
    float* __restrict__ out)
{
    constexpr int N = 128;
    constexpr int N8 = N / 16;
    constexpr int LDA2_128 = 272;
    constexpr int LDA2_64  = 144;
    constexpr int ABYT = MT * 136 * 2;

    extern __shared__ __align__(16) char smem[];
    float* sb   = (float*)smem;                 // 8 x 128 bias vectors
    float* Tf   = (float*)(smem + 4096);
    char*  AhiB = smem + 4096 + MT * LDT * 4;
    char*  AloB = AhiB + ABYT;

    const int tid = threadIdx.x, wid = tid >> 5, lane = tid & 31;
    const size_t rowBase = (size_t)blockIdx.x * MT;

    // load 8 biases
    {
        const float* bs[8] = { w.b_ji, w.b_rb0, w.b_rb1, w.b_fin,
                               w.b_ra00, w.b_ra01, w.b_ra10, w.b_ra11 };
        for (int v = 0; v < 8; v++)
            for (int i = tid; i < N; i += 256) sb[v * 128 + i] = bs[v][i];
    }

    stage_A<128>(m_input, rowBase, AhiB, AloB, tid);
    __syncthreads();

    const int warpM = (wid & 3) * 16;
    const int warpN = (wid >> 2) * (N / 2);
    const int n8base = warpN >> 3;
    const int r0 = lane >> 2;
    const int c0 = (lane & 3) * 2;
    const int rowA = warpM + r0;
    const int rowB = rowA + 8;
    const size_t gA = rowBase + rowA;
    const size_t gB = rowBase + rowB;

    const uint32_t aOff128 = (uint32_t)(warpM + (lane & 15)) * LDA2_128 + (uint32_t)(lane >> 4) * 16;
    const uint32_t aOff64  = (uint32_t)(warpM + (lane & 15)) * LDA2_64  + (uint32_t)(lane >> 4) * 16;
    const uint32_t hiBase = smem_u32(AhiB);
    const uint32_t loBase = smem_u32(AloB);

    float acc[N8][4];

    // ---- 0: ji (K=128): m_pre = swish(m_input@W_ji + b_ji) -> Tf ----
    zero_acc<N>(acc);
    run_mma<N, 128>(acc, hiBase + aOff128, loBase + aOff128, w.ji, lane, n8base);
    __syncthreads();   // done reading m_input A before agg staging overwrites
    #pragma unroll
    for (int j = 0; j < N8; j++) {
        const int col = warpN + j * 8 + c0;
        float b0 = sb[0 * 128 + col], b1 = sb[0 * 128 + col + 1];
        *(float2*)(Tf + rowA * LDT + col) =
            make_float2(swishf(acc[j][0] + b0), swishf(acc[j][1] + b1));
        *(float2*)(Tf + rowB * LDT + col) =
            make_float2(swishf(acc[j][2] + b0), swishf(acc[j][3] + b1));
        acc[j][0] = 0.f; acc[j][1] = 0.f; acc[j][2] = 0.f; acc[j][3] = 0.f;
    }

    stage_A<64>(agg, rowBase, AhiB, AloB, tid);
    __syncthreads();

    // ---- 1: up (K=64): t = swish(acc) + Tf -> Tf + A ----
    run_mma<N, 64>(acc, hiBase + aOff64, loBase + aOff64, w.up, lane, n8base);
    __syncthreads();
    #pragma unroll
    for (int j = 0; j < N8; j++) {
        const int col = warpN + j * 8 + c0;
        float2 tA = *(const float2*)(Tf + rowA * LDT + col);
        float2 tB = *(const float2*)(Tf + rowB * LDT + col);
        float v0 = tA.x + swishf(acc[j][0]);
        float v1 = tA.y + swishf(acc[j][1]);
        float v2 = tB.x + swishf(acc[j][2]);
        float v3 = tB.y + swishf(acc[j][3]);
        *(float2*)(Tf + rowA * LDT + col) = make_float2(v0, v1);
        *(float2*)(Tf + rowB * LDT + col) = make_float2(v2, v3);
        store_hl(AhiB, AloB, rowA, col, v0, v1, LDA2_128);
        store_hl(AhiB, AloB, rowB, col, v2, v3, LDA2_128);
        acc[j][0] = 0.f; acc[j][1] = 0.f; acc[j][2] = 0.f; acc[j][3] = 0.f;
    }
    __syncthreads();

    // ---- 2: rb0: swish -> A ----
    run_mma<N, 128>(acc, hiBase + aOff128, loBase + aOff128, w.rb0, lane, n8base);
    __syncthreads();
    #pragma unroll
    for (int j = 0; j < N8; j++) {
        const int col = warpN + j * 8 + c0;
        float b0 = sb[1 * 128 + col], b1 = sb[1 * 128 + col + 1];
        store_hl(AhiB, AloB, rowA, col, swishf(acc[j][0] + b0), swishf(acc[j][1] + b1), LDA2_128);
        store_hl(AhiB, AloB, rowB, col, swishf(acc[j][2] + b0), swishf(acc[j][3] + b1), LDA2_128);
        acc[j][0] = 0.f; acc[j][1] = 0.f; acc[j][2] = 0.f; acc[j][3] = 0.f;
    }
    __syncthreads();

    // ---- 3: rb1: h1 = Tf + swish -> Tf + A ----
    run_mma<N, 128>(acc, hiBase + aOff128, loBase + aOff128, w.rb1, lane, n8base);
    __syncthreads();
    #pragma unroll
    for (int j = 0; j < N8; j++) {
        const int col = warpN + j * 8 + c0;
        float b0 = sb[2 * 128 + col], b1 = sb[2 * 128 + col + 1];
        float2 tA = *(const float2*)(Tf + rowA * LDT + col);
        float2 tB = *(const float2*)(Tf + rowB * LDT + col);
        float v0 = tA.x + swishf(acc[j][0] + b0);
        float v1 = tA.y + swishf(acc[j][1] + b1);
        float v2 = tB.x + swishf(acc[j][2] + b0);
        float v3 = tB.y + swishf(acc[j][3] + b1);
        *(float2*)(Tf + rowA * LDT + col) = make_float2(v0, v1);
        *(float2*)(Tf + rowB * LDT + col) = make_float2(v2, v3);
        store_hl(AhiB, AloB, rowA, col, v0, v1, LDA2_128);
        store_hl(AhiB, AloB, rowB, col, v2, v3, LDA2_128);
        acc[j][0] = 0.f; acc[j][1] = 0.f; acc[j][2] = 0.f; acc[j][3] = 0.f;
    }
    __syncthreads();

    // ---- 4: fin: m2 = swish(+b_fin) + m_input -> Tf + A ----
    run_mma<N, 128>(acc, hiBase + aOff128, loBase + aOff128, w.fin, lane, n8base);
    __syncthreads();
    #pragma unroll
    for (int j = 0; j < N8; j++) {
        const int col = warpN + j * 8 + c0;
        float b0 = sb[3 * 128 + col], b1 = sb[3 * 128 + col + 1];
        float v0 = swishf(acc[j][0] + b0);
        float v1 = swishf(acc[j][1] + b1);
        float v2 = swishf(acc[j][2] + b0);
        float v3 = swishf(acc[j][3] + b1);
        float2 eA = *(const float2*)(m_input + gA * N + col);
        float2 eB = *(const float2*)(m_input + gB * N + col);
        v0 += eA.x; v1 += eA.y; v2 += eB.x; v3 += eB.y;
        *(float2*)(Tf + rowA * LDT + col) = make_float2(v0, v1);
        *(float2*)(Tf + rowB * LDT + col) = make_float2(v2, v3);
        store_hl(AhiB, AloB, rowA, col, v0, v1, LDA2_128);
        store_hl(AhiB, AloB, rowB, col, v2, v3, LDA2_128);
        acc[j][0] = 0.f; acc[j][1] = 0.f; acc[j][2] = 0.f; acc[j][3] = 0.f;
    }
    __syncthreads();

    // ---- 5: ra00: swish -> A ----
    run_mma<N, 128>(acc, hiBase + aOff128, loBase + aOff128, w.ra00, lane, n8base);
    __syncthreads();
    #pragma unroll
    for (int j = 0; j < N8; j++) {
        const int col = warpN + j * 8 + c0;
        float b0 = sb[4 * 128 + col], b1 = sb[4 * 128 + col + 1];
        store_hl(AhiB, AloB, rowA, col, swishf(acc[j][0] + b0), swishf(acc[j][1] + b1), LDA2_128);
        store_hl(AhiB, AloB, rowB, col, swishf(acc[j][2] + b0), swishf(acc[j][3] + b1), LDA2_128);
        acc[j][0] = 0.f; acc[j][1] = 0.f; acc[j][2] = 0.f; acc[j][3] = 0.f;
    }
    __syncthreads();

    // ---- 6: ra01: t2 = Tf + swish -> Tf + A ----
    run_mma<N, 128>(acc, hiBase + aOff128, loBase + aOff128, w.ra01, lane, n8base);
    __syncthreads();
    #pragma unroll
    for (int j = 0; j < N8; j++) {
        const int col = warpN + j * 8 + c0;
        float b0 = sb[5 * 128 + col], b1 = sb[5 * 128 + col + 1];
        float2 tA = *(const float2*)(Tf + rowA * LDT + col);
        float2 tB = *(const float2*)(Tf + rowB * LDT + col);
        float v0 = tA.x + swishf(acc[j][0] + b0);
        float v1 = tA.y + swishf(acc[j][1] + b1);
        float v2 = tB.x + swishf(acc[j][2] + b0);
        float v3 = tB.y + swishf(acc[j][3] + b1);
        *(float2*)(Tf + rowA * LDT + col) = make_float2(v0, v1);
        *(float2*)(Tf + rowB * LDT + col) = make_float2(v2, v3);
        store_hl(AhiB, AloB, rowA, col, v0, v1, LDA2_128);
        store_hl(AhiB, AloB, rowB, col, v2, v3, LDA2_128);
        acc[j][0] = 0.f; acc[j][1] = 0.f; acc[j][2] = 0.f; acc[j][3] = 0.f;
    }
    __syncthreads();

    // ---- 7: ra10: swish -> A ----
    run_mma<N, 128>(acc, hiBase + aOff128, loBase + aOff128, w.ra10, lane, n8base);
    __syncthreads();
    #pragma unroll
    for (int j = 0; j < N8; j++) {
        const int col = warpN + j * 8 + c0;
        float b0 = sb[6 * 128 + col], b1 = sb[6 * 128 + col + 1];
        store_hl(AhiB, AloB, rowA, col, swishf(acc[j][0] + b0), swishf(acc[j][1] + b1), LDA2_128);
        store_hl(AhiB, AloB, rowB, col, swishf(acc[j][2] + b0), swishf(acc[j][3] + b1), LDA2_128);
        acc[j][0] = 0.f; acc[j][1] = 0.f; acc[j][2] = 0.f; acc[j][3] = 0.f;
    }
    __syncthreads();

    // ---- 8: ra11: out = Tf + swish -> global ----
    run_mma<N, 128>(acc, hiBase + aOff128, loBase + aOff128, w.ra11, lane, n8base);
    #pragma unroll
    for (int j = 0; j < N8; j++) {
        const int col = warpN + j * 8 + c0;
        float b0 = sb[7 * 128 + col], b1 = sb[7 * 128 + col + 1];
        float2 tA = *(const float2*)(Tf + rowA * LDT + col);
        float2 tB = *(const float2*)(Tf + rowB * LDT + col);
        *(float2*)(out + gA * N + col) =
            make_float2(tA.x + swishf(acc[j][0] + b0), tA.y + swishf(acc[j][1] + b1));
        *(float2*)(out + gB * N + col) =
            make_float2(tB.x + swishf(acc[j][2] + b0), tB.y + swishf(acc[j][3] + b1));
    }
}

// ---------------------------------------------------------------------------
// proj8: out[rows x 8] = X[rows x NIN] @ W[NIN x 8]
// ---------------------------------------------------------------------------
template<int NIN>
__global__ __launch_bounds__(256) void proj8_kernel(
    const float* __restrict__ X, const float* __restrict__ W,
    float* __restrict__ out)
{
    __shared__ float tile[256 * NIN];
    __shared__ float Ws[NIN * 8];
    const size_t base = (size_t)blockIdx.x * 256;
    constexpr int NT4 = 256 * NIN / 4;
    const float4* src = (const float4*)(X + base * NIN);
    #pragma unroll 4
    for (int i = threadIdx.x; i < NT4; i += 256)
        ((float4*)tile)[i] = src[i];
    for (int i = threadIdx.x; i < NIN * 8; i += 256)
        Ws[i] = W[i];
    __syncthreads();

    const float* x = &tile[threadIdx.x * NIN];
    float o[8] = {0, 0, 0, 0, 0, 0, 0, 0};
    #pragma unroll
    for (int c = 0; c < NIN; c++) {
        float xv = x[c];
        #pragma unroll
        for (int b = 0; b < 8; b++)
            o[b] = fmaf(xv, Ws[c * 8 + b], o[b]);
    }
    float4* op = (float4*)(out + (base + threadIdx.x) * 8);
    op[0] = make_float4(o[0], o[1], o[2], o[3]);
    op[1] = make_float4(o[4], o[5], o[6], o[7]);
}

__global__ void zero_kernel(float4* __restrict__ p, size_t n4)
{
    size_t i = (size_t)blockIdx.x * blockDim.x + threadIdx.x;
    if (i < n4) p[i] = make_float4(0.f, 0.f, 0.f, 0.f);
}

// ---------------------------------------------------------------------------
// Triplet gather/gate/scatter -- 2 triplets per 16-lane group
// ---------------------------------------------------------------------------
__global__ __launch_bounds__(256, 8) void triplet_kernel(
    const int* __restrict__ expand_to_kj,
    const int* __restrict__ reduce_to_ji,
    const float* __restrict__ sbf8,
    const float* __restrict__ Wsbf2,
    const float* __restrict__ ang,
    float* __restrict__ agg)
{
    __shared__ float Ws[8 * 64];
    for (int i = threadIdx.x; i < 512; i += 256) Ws[i] = Wsbf2[i];
    __syncthreads();

    const int lane16 = threadIdx.x & 15;
    const size_t grp = ((size_t)blockIdx.x * 256 + threadIdx.x) >> 4;
    const size_t t0 = grp * 2;
    const size_t t1 = t0 + 1;

    const int ekj0 = __ldg(&expand_to_kj[t0]);
    const int ekj1 = __ldg(&expand_to_kj[t1]);
    const int eji0 = __ldg(&reduce_to_ji[t0]);
    const int eji1 = __ldg(&reduce_to_ji[t1]);

    float4 a0 = __ldg((const float4*)(ang + (size_t)ekj0 * 64 + lane16 * 4));
    float4 a1 = __ldg((const float4*)(ang + (size_t)ekj1 * 64 + lane16 * 4));

    const float* s0 = sbf8 + t0 * 8;
    const float* s1 = sbf8 + t1 * 8;

    float g00 = 0.f, g01 = 0.f, g02 = 0.f, g03 = 0.f;
    float g10 = 0.f, g11 = 0.f, g12 = 0.f, g13 = 0.f;
    #pragma unroll
    for (int b = 0; b < 8; b++) {
        const float sb0 = __ldg(&s0[b]);
        const float sb1 = __ldg(&s1[b]);
        const float* w = &Ws[b * 64 + lane16 * 4];
        float w0 = w[0], w1 = w[1], w2 = w[2], w3 = w[3];
        g00 = fmaf(sb0, w0, g00); g01 = fmaf(sb0, w1, g01);
        g02 = fmaf(sb0, w2, g02); g03 = fmaf(sb0, w3, g03);
        g10 = fmaf(sb1, w0, g10); g11 = fmaf(sb1, w1, g11);
        g12 = fmaf(sb1, w2, g12); g13 = fmaf(sb1, w3, g13);
    }

    float v00 = a0.x * g00, v01 = a0.y * g01, v02 = a0.z * g02, v03 = a0.w * g03;
    float v10 = a1.x * g10, v11 = a1.y * g11, v12 = a1.z * g12, v13 = a1.w * g13;

    float* d0 = agg + (size_t)eji0 * 64 + lane16 * 4;
    float* d1 = agg + (size_t)eji1 * 64 + lane16 * 4;
    asm volatile("red.global.add.v4.f32 [%0], {%1,%2,%3,%4};"
                 :: "l"(d0), "f"(v00), "f"(v01), "f"(v02), "f"(v03) : "memory");
    asm volatile("red.global.add.v4.f32 [%0], {%1,%2,%3,%4};"
                 :: "l"(d1), "f"(v10), "f"(v11), "f"(v12), "f"(v13) : "memory");
}

// ---------------------------------------------------------------------------
// Host orchestration
// ---------------------------------------------------------------------------
static inline int edge_smemsz() { return 5120 + 2 * (MT * 136 * 2); }
static inline int tail_smemsz() { return 4096 + MT * LDT * 4 + 2 * (MT * 136 * 2); }

extern "C" void kernel_launch(void* const* d_in, const int* in_sizes, int n_in,
                              void* d_out, int out_size)
{
    const float* m_input = (const float*)d_in[0];
    const float* rbf     = (const float*)d_in[1];
    const float* sbf     = (const float*)d_in[2];
    const int*   expand  = (const int*)  d_in[3];
    const int*   reduce  = (const int*)  d_in[4];
    const float* W_kj    = (const float*)d_in[5];
    const float* b_kj    = (const float*)d_in[6];
    const float* W_rbf1  = (const float*)d_in[7];
    const float* W_rbf2  = (const float*)d_in[8];
    const float* W_sbf1  = (const float*)d_in[9];
    const float* W_sbf2  = (const float*)d_in[10];
    const float* W_down  = (const float*)d_in[11];
    const float* W_up    = (const float*)d_in[12];
    const float* W_ji    = (const float*)d_in[13];
    const float* b_ji    = (const float*)d_in[14];
    const float* W_res_b = (const float*)d_in[15];
    const float* b_res_b = (const float*)d_in[16];
    const float* W_final = (const float*)d_in[17];
    const float* b_final = (const float*)d_in[18];
    const float* W_res_a = (const float*)d_in[19];
    const float* b_res_a = (const float*)d_in[20];
    float* out = (float*)d_out;

    const int E = in_sizes[0] / 128;
    const int T = in_sizes[3];

    float *ang, *agg, *rbf8, *sbf8, *wb;
    cudaGetSymbolAddress((void**)&ang,  g_ang);
    cudaGetSymbolAddress((void**)&agg,  g_agg);
    cudaGetSymbolAddress((void**)&rbf8, g_rbf8);
    cudaGetSymbolAddress((void**)&sbf8, g_sbf8);
    cudaGetSymbolAddress((void**)&wb,   g_wb);

    cudaFuncSetAttribute(edge_fused,
                         cudaFuncAttributeMaxDynamicSharedMemorySize, edge_smemsz());
    cudaFuncSetAttribute(tail_fused,
                         cudaFuncAttributeMaxDynamicSharedMemorySize, tail_smemsz());

    char* wbb = (char*)wb;
    auto wat = [&](size_t off) { return (const uint32_t*)(wbb + off); };
    const unsigned OF_KJ = 0, OF_JI = 65536, OF_RB0 = 131072, OF_RB1 = 196608,
                   OF_FIN = 262144, OF_RA00 = 327680, OF_RA01 = 393216,
                   OF_RA10 = 458752, OF_RA11 = 524288,
                   OF_DOWN = 589824, OF_UP = 622592;

    // 0-1: weight conversion (interleaved hi|lo layout)
    {
        W9 w;
        w.s[0] = W_kj;            w.off[0] = OF_KJ;
        w.s[1] = W_ji;            w.off[1] = OF_JI;
        w.s[2] = W_res_b;         w.off[2] = OF_RB0;
        w.s[3] = W_res_b + 16384; w.off[3] = OF_RB1;
        w.s[4] = W_final;         w.off[4] = OF_FIN;
        w.s[5] = W_res_a;         w.off[5] = OF_RA00;
        w.s[6] = W_res_a + 16384; w.off[6] = OF_RA01;
        w.s[7] = W_res_a + 32768; w.off[7] = OF_RA10;
        w.s[8] = W_res_a + 49152; w.off[8] = OF_RA11;
        wconv9_kernel<<<dim3(8, 9), 256>>>(w, wbb);

        W2 w2;
        w2.s[0] = W_down; w2.off[0] = OF_DOWN; w2.K[0] = 128; w2.N[0] = 64;
        w2.s[1] = W_up;   w2.off[1] = OF_UP;   w2.K[1] = 64;  w2.N[1] = 128;
        wconv2_kernel<<<dim3(8, 2), 256>>>(w2, wbb);
    }

    const int GE = E / MT;   // 4096

    // 2: rbf8
    proj8_kernel<6><<<E / 256, 256>>>(rbf, W_rbf1, rbf8);

    // 3: edge fusion: ang -> g_ang    [ncu idx 3]
    edge_fused<<<GE, 256, edge_smemsz()>>>(
        m_input, wat(OF_KJ), b_kj, wat(OF_DOWN), W_rbf2, rbf8, ang);

    // 4: sbf8
    proj8_kernel<42><<<T / 256, 256>>>(sbf, W_sbf1, sbf8);

    // 5: agg = 0
    {
        size_t n4 = (size_t)E * 64 / 4;
        zero_kernel<<<(unsigned)((n4 + 255) / 256), 256>>>((float4*)agg, n4);
    }

    // 6: scatter
    triplet_kernel<<<(unsigned)((size_t)T * 16 / 256 / 2), 256>>>(
        expand, reduce, sbf8, W_sbf2, ang, agg);

    // 7: tail: ji + steps 7-11 fused -> out
    {
        TailW w;
        w.ji   = wat(OF_JI);   w.b_ji   = b_ji;
        w.up   = wat(OF_UP);
        w.rb0  = wat(OF_RB0);  w.b_rb0  = b_res_b;
        w.rb1  = wat(OF_RB1);  w.b_rb1  = b_res_b + 128;
        w.fin  = wat(OF_FIN);  w.b_fin  = b_final;
        w.ra00 = wat(OF_RA00); w.b_ra00 = b_res_a;
        w.ra01 = wat(OF_RA01); w.b_ra01 = b_res_a + 128;
        w.ra10 = wat(OF_RA10); w.b_ra10 = b_res_a + 256;
        w.ra11 = wat(OF_RA11); w.b_ra11 = b_res_a + 384;
        tail_fused<<<GE, 256, tail_smemsz()>>>(agg, m_input, w, out);
    }
}

// round 16
// speedup vs baseline: 1.5032x; 1.0099x over previous
#include <cuda_runtime.h>
#include <cuda_bf16.h>
#include <cstdint>

// ---------------------------------------------------------------------------
// Problem constants
// ---------------------------------------------------------------------------
#define E_MAX 262144
#define T_MAX 2097152
#define MT    64          // rows per CTA tile

// ---------------------------------------------------------------------------
// Scratch (device globals -- no allocation allowed)
// ---------------------------------------------------------------------------
__device__ float g_ang [(size_t)E_MAX * 64];
__device__ float g_agg [(size_t)E_MAX * 64];
__device__ float g_sbf8[(size_t)T_MAX * 8];
__device__ float g_wb  [163840];   // 640KB: bf16 hi|lo interleaved weight fragments

__device__ __forceinline__ float swishf(float v) { return v / (1.0f + __expf(-v)); }

__device__ __forceinline__ uint32_t smem_u32(const void* p) {
    uint32_t a;
    asm("{ .reg .u64 t; cvta.to.shared.u64 t, %1; cvt.u32.u64 %0, t; }"
        : "=r"(a) : "l"(p));
    return a;
}

__device__ __forceinline__ void ldm_x4(uint32_t* r, uint32_t addr) {
    asm volatile("ldmatrix.sync.aligned.m8n8.x4.shared.b16 {%0,%1,%2,%3}, [%4];"
                 : "=r"(r[0]), "=r"(r[1]), "=r"(r[2]), "=r"(r[3]) : "r"(addr));
}

__device__ __forceinline__ void mma_bf16(float* d, const uint32_t* a, uint32_t b0, uint32_t b1) {
    asm volatile("mma.sync.aligned.m16n8k16.row.col.f32.bf16.bf16.f32 "
                 "{%0,%1,%2,%3}, {%4,%5,%6,%7}, {%8,%9}, {%0,%1,%2,%3};"
                 : "+f"(d[0]), "+f"(d[1]), "+f"(d[2]), "+f"(d[3])
                 : "r"(a[0]), "r"(a[1]), "r"(a[2]), "r"(a[3]), "r"(b0), "r"(b1));
}

// ---------------------------------------------------------------------------
// Weight conversion: W[K,N] f32 -> interleaved bf16 hi|lo fragments.
// u32 index = ((n8*KST + ks)*32 + lane)*4 + prec*2 + reg
// ---------------------------------------------------------------------------
__device__ __forceinline__ void wconv_one(const float* __restrict__ W,
                                          __nv_bfloat16* __restrict__ d16,
                                          int K, int N, int start, int stride)
{
    const int KST = K >> 4;
    for (int i = start; i < K * N; i += stride) {
        int k = i / N, n = i % N;
        float v = W[i];
        __nv_bfloat16 h = __float2bfloat16_rn(v);
        __nv_bfloat16 l = __float2bfloat16_rn(v - __bfloat162float(h));
        int ks = k >> 4, kin = k & 15, n8 = n >> 3, nin = n & 7;
        int lane = nin * 4 + ((kin & 7) >> 1);
        int reg  = kin >> 3;
        int half = kin & 1;
        int base32 = (((n8 * KST + ks) * 32 + lane) << 2) + reg;
        d16[(base32 << 1) + half]       = h;
        d16[((base32 + 2) << 1) + half] = l;
    }
}

struct W9 { const float* s[9]; unsigned off[9]; };

__global__ void wconv9_kernel(W9 w, char* base)
{
    const int wi = blockIdx.y;
    wconv_one(w.s[wi], (__nv_bfloat16*)(base + w.off[wi]), 128, 128,
              threadIdx.x + blockIdx.x * 256, 256 * gridDim.x);
}

struct W2 { const float* s[2]; unsigned off[2]; int K[2]; int N[2]; };

__global__ void wconv2_kernel(W2 w, char* base)
{
    const int wi = blockIdx.y;
    wconv_one(w.s[wi], (__nv_bfloat16*)(base + w.off[wi]), w.K[wi], w.N[wi],
              threadIdx.x + blockIdx.x * 256, 256 * gridDim.x);
}

// ---------------------------------------------------------------------------
// A staging: MT rows of f32 global -> bf16 hi/lo smem (row stride K+8 elems)
// ---------------------------------------------------------------------------
template<int K>
__device__ __forceinline__ void stage_A(const float* __restrict__ A, size_t rowBase,
                                        char* AhiB, char* AloB, int tid)
{
    constexpr int LDA = K + 8;
    const float4* Ab = (const float4*)(A + rowBase * K);
    constexpr int NF4 = MT * K / 4;
    #pragma unroll 4
    for (int i = tid; i < NF4; i += 256) {
        int r  = i / (K / 4);
        int c4 = (i % (K / 4)) * 4;
        float4 v = Ab[i];
        __nv_bfloat162 h01, h23, l01, l23;
        h01.x = __float2bfloat16_rn(v.x);
        h01.y = __float2bfloat16_rn(v.y);
        h23.x = __float2bfloat16_rn(v.z);
        h23.y = __float2bfloat16_rn(v.w);
        l01.x = __float2bfloat16_rn(v.x - __bfloat162float(h01.x));
        l01.y = __float2bfloat16_rn(v.y - __bfloat162float(h01.y));
        l23.x = __float2bfloat16_rn(v.z - __bfloat162float(h23.x));
        l23.y = __float2bfloat16_rn(v.w - __bfloat162float(h23.y));
        uint2 hv, lv;
        hv.x = *(uint32_t*)&h01; hv.y = *(uint32_t*)&h23;
        lv.x = *(uint32_t*)&l01; lv.y = *(uint32_t*)&l23;
        size_t off = (size_t)r * LDA * 2 + (size_t)c4 * 2;
        *(uint2*)(AhiB + off) = hv;
        *(uint2*)(AloB + off) = lv;
    }
}

// ---------------------------------------------------------------------------
// 3-term MMA mainloop, single pass over k-steps (R13-proven).
// ---------------------------------------------------------------------------
template<int N, int K>
__device__ __forceinline__ void run_mma(float (&acc)[N / 16][4],
                                        uint32_t aHiAddr, uint32_t aLoAddr,
                                        const uint32_t* __restrict__ Bpre,
                                        int lane, int n8base)
{
    constexpr int KST = K / 16;
    constexpr int N8  = N / 16;

    #pragma unroll
    for (int ks = 0; ks < KST; ks++) {
        uint32_t a_hi[4], a_lo[4];
        ldm_x4(a_hi, aHiAddr + ks * 32);
        ldm_x4(a_lo, aLoAddr + ks * 32);
        #pragma unroll
        for (int j = 0; j < N8; j++) {
            uint4 bb = *(const uint4*)(Bpre +
                ((((size_t)(n8base + j) * KST + ks) * 32 + lane) << 2));
            mma_bf16(acc[j], a_hi, bb.x, bb.y);
            mma_bf16(acc[j], a_hi, bb.z, bb.w);
            mma_bf16(acc[j], a_lo, bb.x, bb.y);
        }
    }
}

template<int N>
__device__ __forceinline__ void zero_acc(float (&acc)[N / 16][4])
{
    #pragma unroll
    for (int j = 0; j < N / 16; j++)
        #pragma unroll
        for (int q = 0; q < 4; q++) acc[j][q] = 0.0f;
}

__device__ __forceinline__ void store_hl(char* AhiB, char* AloB, int row, int col,
                                         float v0, float v1, int LDA2)
{
    __nv_bfloat162 h, l;
    h.x = __float2bfloat16_rn(v0);
    h.y = __float2bfloat16_rn(v1);
    l.x = __float2bfloat16_rn(v0 - __bfloat162float(h.x));
    l.y = __float2bfloat16_rn(v1 - __bfloat162float(h.y));
    *(__nv_bfloat162*)(AhiB + row * LDA2 + col * 2) = h;
    *(__nv_bfloat162*)(AloB + row * LDA2 + col * 2) = l;
}

// ---------------------------------------------------------------------------
// Edge fusion: kj+gate -> down, with the rbf [E,6]@W1 [6,8] projection
// computed inline in the gate epilogue (proj6 kernel eliminated).
//   h1  = swish(m_input @ W_kj + b_kj) * ((rbf@W1) @ Wg)   -> A smem (bf16)
//   ang = swish(h1 @ W_down)                               -> g_ang
// ---------------------------------------------------------------------------
__global__ __launch_bounds__(256, 2) void edge_fused(
    const float*    __restrict__ m_input,
    const uint32_t* __restrict__ Bkj, const float* __restrict__ bkj,
    const uint32_t* __restrict__ Bdown,
    const float*    __restrict__ Wg,    // [8 x 128] f32  (W_rbf2)
    const float*    __restrict__ W1,    // [6 x 8]  f32   (W_rbf1)
    const float*    __restrict__ rbf,   // [E x 6]
    float*          __restrict__ ang)
{
    constexpr int K = 128, N = 128;
    constexpr int N8   = N / 16;
    constexpr int LDA  = K + 8;
    constexpr int LDA2 = LDA * 2;
    constexpr int ABYT = MT * LDA * 2;

    extern __shared__ __align__(16) char smem[];
    float* sbkj = (float*)smem;              // 512 B
    float* sWg  = (float*)(smem + 512);      // 4 KB
    float* sW1  = (float*)(smem + 4608);     // 192 B
    char*  AhiB = smem + 5120;
    char*  AloB = AhiB + ABYT;

    const int tid = threadIdx.x, wid = tid >> 5, lane = tid & 31;
    const size_t rowBase = (size_t)blockIdx.x * MT;

    for (int i = tid; i < N; i += 256) sbkj[i] = bkj[i];
    for (int i = tid; i < 8 * N; i += 256) sWg[i] = Wg[i];
    if (tid < 48) sW1[tid] = W1[tid];

    stage_A<K>(m_input, rowBase, AhiB, AloB, tid);
    __syncthreads();

    const int warpM = (wid & 3) * 16;
    const int warpN = (wid >> 2) * (N / 2);
    const int n8base = warpN >> 3;

    const uint32_t aHiAddr = smem_u32(AhiB) +
        (uint32_t)(warpM + (lane & 15)) * LDA2 + (uint32_t)(lane >> 4) * 16;
    const uint32_t aLoAddr = aHiAddr + (uint32_t)ABYT;

    const int r0 = lane >> 2;
    const int c0 = (lane & 3) * 2;

    float acc[N8][4];

    // ---- GEMM 1: W_kj + rbf gate -> h1 into A smem ----
    zero_acc<N>(acc);
    run_mma<N, K>(acc, aHiAddr, aLoAddr, Bkj, lane, n8base);
    __syncthreads();   // everyone done reading A before overwrite

    {
        const int rowA = warpM + r0;
        const int rowB = rowA + 8;
        const size_t gA = rowBase + rowA;
        const size_t gB = rowBase + rowB;

        // inline proj6: r8 = rbf[row,0:6] @ W1[6,8]  (rows broadcast per quad)
        float r8A[8], r8B[8];
        {
            #pragma unroll
            for (int b = 0; b < 8; b++) { r8A[b] = 0.f; r8B[b] = 0.f; }
            #pragma unroll
            for (int c = 0; c < 6; c++) {
                float ra = __ldg(&rbf[gA * 6 + c]);
                float rb = __ldg(&rbf[gB * 6 + c]);
                #pragma unroll
                for (int b = 0; b < 8; b++) {
                    float w = sW1[c * 8 + b];
                    r8A[b] = fmaf(ra, w, r8A[b]);
                    r8B[b] = fmaf(rb, w, r8B[b]);
                }
            }
        }

        #pragma unroll
        for (int j = 0; j < N8; j++) {
            const int col = warpN + j * 8 + c0;
            float b0 = sbkj[col], b1 = sbkj[col + 1];
            float v0 = swishf(acc[j][0] + b0);
            float v1 = swishf(acc[j][1] + b1);
            float v2 = swishf(acc[j][2] + b0);
            float v3 = swishf(acc[j][3] + b1);
            float gA0 = 0.f, gA1 = 0.f, gB0 = 0.f, gB1 = 0.f;
            #pragma unroll
            for (int b = 0; b < 8; b++) {
                float w0 = sWg[b * N + col], w1 = sWg[b * N + col + 1];
                gA0 = fmaf(r8A[b], w0, gA0);
                gA1 = fmaf(r8A[b], w1, gA1);
                gB0 = fmaf(r8B[b], w0, gB0);
                gB1 = fmaf(r8B[b], w1, gB1);
            }
            v0 *= gA0; v1 *= gA1; v2 *= gB0; v3 *= gB1;
            store_hl(AhiB, AloB, rowA, col, v0, v1, LDA2);
            store_hl(AhiB, AloB, rowB, col, v2, v3, LDA2);
        }
    }
    __syncthreads();

    // ---- GEMM 2: W_down (N=64) -> ang ----
    {
        constexpr int N2 = 64;
        constexpr int N28 = N2 / 16;
        float acc2[N28][4];
        zero_acc<N2>(acc2);
        const int warpN2 = (wid >> 2) * (N2 / 2);
        run_mma<N2, K>(acc2, aHiAddr, aLoAddr, Bdown, lane, warpN2 >> 3);

        const size_t gA = rowBase + warpM + r0;
        const size_t gB = gA + 8;
        #pragma unroll
        for (int j = 0; j < N28; j++) {
            const int col = warpN2 + j * 8 + c0;
            *(float2*)(ang + gA * N2 + col) =
                make_float2(swishf(acc2[j][0]), swishf(acc2[j][1]));
            *(float2*)(ang + gB * N2 + col) =
                make_float2(swishf(acc2[j][2]), swishf(acc2[j][3]));
        }
    }
}

// ---------------------------------------------------------------------------
// tail_fused: ji + steps 7-11, 9 GEMMs per CTA tile (R15-proven).
// ---------------------------------------------------------------------------
#define LDT 132

struct TailW {
    const uint32_t *ji, *up, *rb0, *rb1, *fin, *ra00, *ra01, *ra10, *ra11;
    const float *b_ji, *b_rb0, *b_rb1, *b_fin, *b_ra00, *b_ra01, *b_ra10, *b_ra11;
};

__global__ __launch_bounds__(256, 2) void tail_fused(
    const float* __restrict__ agg,
    const float* __restrict__ m_input,
    TailW w,
    float* __restrict__ out)
{
    constexpr int N = 128;
    constexpr int N8 = N / 16;
    constexpr int LDA2_128 = 272;
    constexpr int LDA2_64  = 144;
    constexpr int ABYT = MT * 136 * 2;

    extern __shared__ __align__(16) char smem[];
    float* sb   = (float*)smem;                 // 8 x 128 bias vectors
    float* Tf   = (float*)(smem + 4096);
    char*  AhiB = smem + 4096 + MT * LDT * 4;
    char*  AloB = AhiB + ABYT;

    const int tid = threadIdx.x, wid = tid >> 5, lane = tid & 31;
    const size_t rowBase = (size_t)blockIdx.x * MT;

    {
        const float* bs[8] = { w.b_ji, w.b_rb0, w.b_rb1, w.b_fin,
                               w.b_ra00, w.b_ra01, w.b_ra10, w.b_ra11 };
        for (int v = 0; v < 8; v++)
            for (int i = tid; i < N; i += 256) sb[v * 128 + i] = bs[v][i];
    }

    stage_A<128>(m_input, rowBase, AhiB, AloB, tid);
    __syncthreads();

    const int warpM = (wid & 3) * 16;
    const int warpN = (wid >> 2) * (N / 2);
    const int n8base = warpN >> 3;
    const int r0 = lane >> 2;
    const int c0 = (lane & 3) * 2;
    const int rowA = warpM + r0;
    const int rowB = rowA + 8;
    const size_t gA = rowBase + rowA;
    const size_t gB = rowBase + rowB;

    const uint32_t aOff128 = (uint32_t)(warpM + (lane & 15)) * LDA2_128 + (uint32_t)(lane >> 4) * 16;
    const uint32_t aOff64  = (uint32_t)(warpM + (lane & 15)) * LDA2_64  + (uint32_t)(lane >> 4) * 16;
    const uint32_t hiBase = smem_u32(AhiB);
    const uint32_t loBase = smem_u32(AloB);

    float acc[N8][4];

    // ---- 0: ji (K=128): m_pre -> Tf ----
    zero_acc<N>(acc);
    run_mma<N, 128>(acc, hiBase + aOff128, loBase + aOff128, w.ji, lane, n8base);
    __syncthreads();
    #pragma unroll
    for (int j = 0; j < N8; j++) {
        const int col = warpN + j * 8 + c0;
        float b0 = sb[0 * 128 + col], b1 = sb[0 * 128 + col + 1];
        *(float2*)(Tf + rowA * LDT + col) =
            make_float2(swishf(acc[j][0] + b0), swishf(acc[j][1] + b1));
        *(float2*)(Tf + rowB * LDT + col) =
            make_float2(swishf(acc[j][2] + b0), swishf(acc[j][3] + b1));
        acc[j][0] = 0.f; acc[j][1] = 0.f; acc[j][2] = 0.f; acc[j][3] = 0.f;
    }

    stage_A<64>(agg, rowBase, AhiB, AloB, tid);
    __syncthreads();

    // ---- 1: up (K=64): t = swish + Tf -> Tf + A ----
    run_mma<N, 64>(acc, hiBase + aOff64, loBase + aOff64, w.up, lane, n8base);
    __syncthreads();
    #pragma unroll
    for (int j = 0; j < N8; j++) {
        const int col = warpN + j * 8 + c0;
        float2 tA = *(const float2*)(Tf + rowA * LDT + col);
        float2 tB = *(const float2*)(Tf + rowB * LDT + col);
        float v0 = tA.x + swishf(acc[j][0]);
        float v1 = tA.y + swishf(acc[j][1]);
        float v2 = tB.x + swishf(acc[j][2]);
        float v3 = tB.y + swishf(acc[j][3]);
        *(float2*)(Tf + rowA * LDT + col) = make_float2(v0, v1);
        *(float2*)(Tf + rowB * LDT + col) = make_float2(v2, v3);
        store_hl(AhiB, AloB, rowA, col, v0, v1, LDA2_128);
        store_hl(AhiB, AloB, rowB, col, v2, v3, LDA2_128);
        acc[j][0] = 0.f; acc[j][1] = 0.f; acc[j][2] = 0.f; acc[j][3] = 0.f;
    }
    __syncthreads();

    // ---- 2: rb0 ----
    run_mma<N, 128>(acc, hiBase + aOff128, loBase + aOff128, w.rb0, lane, n8base);
    __syncthreads();
    #pragma unroll
    for (int j = 0; j < N8; j++) {
        const int col = warpN + j * 8 + c0;
        float b0 = sb[1 * 128 + col], b1 = sb[1 * 128 + col + 1];
        store_hl(AhiB, AloB, rowA, col, swishf(acc[j][0] + b0), swishf(acc[j][1] + b1), LDA2_128);
        store_hl(AhiB, AloB, rowB, col, swishf(acc[j][2] + b0), swishf(acc[j][3] + b1), LDA2_128);
        acc[j][0] = 0.f; acc[j][1] = 0.f; acc[j][2] = 0.f; acc[j][3] = 0.f;
    }
    __syncthreads();

    // ---- 3: rb1: h1 = Tf + swish -> Tf + A ----
    run_mma<N, 128>(acc, hiBase + aOff128, loBase + aOff128, w.rb1, lane, n8base);
    __syncthreads();
    #pragma unroll
    for (int j = 0; j < N8; j++) {
        const int col = warpN + j * 8 + c0;
        float b0 = sb[2 * 128 + col], b1 = sb[2 * 128 + col + 1];
        float2 tA = *(const float2*)(Tf + rowA * LDT + col);
        float2 tB = *(const float2*)(Tf + rowB * LDT + col);
        float v0 = tA.x + swishf(acc[j][0] + b0);
        float v1 = tA.y + swishf(acc[j][1] + b1);
        float v2 = tB.x + swishf(acc[j][2] + b0);
        float v3 = tB.y + swishf(acc[j][3] + b1);
        *(float2*)(Tf + rowA * LDT + col) = make_float2(v0, v1);
        *(float2*)(Tf + rowB * LDT + col) = make_float2(v2, v3);
        store_hl(AhiB, AloB, rowA, col, v0, v1, LDA2_128);
        store_hl(AhiB, AloB, rowB, col, v2, v3, LDA2_128);
        acc[j][0] = 0.f; acc[j][1] = 0.f; acc[j][2] = 0.f; acc[j][3] = 0.f;
    }
    __syncthreads();

    // ---- 4: fin: m2 = swish(+b_fin) + m_input -> Tf + A ----
    run_mma<N, 128>(acc, hiBase + aOff128, loBase + aOff128, w.fin, lane, n8base);
    __syncthreads();
    #pragma unroll
    for (int j = 0; j < N8; j++) {
        const int col = warpN + j * 8 + c0;
        float b0 = sb[3 * 128 + col], b1 = sb[3 * 128 + col + 1];
        float v0 = swishf(acc[j][0] + b0);
        float v1 = swishf(acc[j][1] + b1);
        float v2 = swishf(acc[j][2] + b0);
        float v3 = swishf(acc[j][3] + b1);
        float2 eA = *(const float2*)(m_input + gA * N + col);
        float2 eB = *(const float2*)(m_input + gB * N + col);
        v0 += eA.x; v1 += eA.y; v2 += eB.x; v3 += eB.y;
        *(float2*)(Tf + rowA * LDT + col) = make_float2(v0, v1);
        *(float2*)(Tf + rowB * LDT + col) = make_float2(v2, v3);
        store_hl(AhiB, AloB, rowA, col, v0, v1, LDA2_128);
        store_hl(AhiB, AloB, rowB, col, v2, v3, LDA2_128);
        acc[j][0] = 0.f; acc[j][1] = 0.f; acc[j][2] = 0.f; acc[j][3] = 0.f;
    }
    __syncthreads();

    // ---- 5: ra00 ----
    run_mma<N, 128>(acc, hiBase + aOff128, loBase + aOff128, w.ra00, lane, n8base);
    __syncthreads();
    #pragma unroll
    for (int j = 0; j < N8; j++) {
        const int col = warpN + j * 8 + c0;
        float b0 = sb[4 * 128 + col], b1 = sb[4 * 128 + col + 1];
        store_hl(AhiB, AloB, rowA, col, swishf(acc[j][0] + b0), swishf(acc[j][1] + b1), LDA2_128);
        store_hl(AhiB, AloB, rowB, col, swishf(acc[j][2] + b0), swishf(acc[j][3] + b1), LDA2_128);
        acc[j][0] = 0.f; acc[j][1] = 0.f; acc[j][2] = 0.f; acc[j][3] = 0.f;
    }
    __syncthreads();

    // ---- 6: ra01: t2 = Tf + swish -> Tf + A ----
    run_mma<N, 128>(acc, hiBase + aOff128, loBase + aOff128, w.ra01, lane, n8base);
    __syncthreads();
    #pragma unroll
    for (int j = 0; j < N8; j++) {
        const int col = warpN + j * 8 + c0;
        float b0 = sb[5 * 128 + col], b1 = sb[5 * 128 + col + 1];
        float2 tA = *(const float2*)(Tf + rowA * LDT + col);
        float2 tB = *(const float2*)(Tf + rowB * LDT + col);
        float v0 = tA.x + swishf(acc[j][0] + b0);
        float v1 = tA.y + swishf(acc[j][1] + b1);
        float v2 = tB.x + swishf(acc[j][2] + b0);
        float v3 = tB.y + swishf(acc[j][3] + b1);
        *(float2*)(Tf + rowA * LDT + col) = make_float2(v0, v1);
        *(float2*)(Tf + rowB * LDT + col) = make_float2(v2, v3);
        store_hl(AhiB, AloB, rowA, col, v0, v1, LDA2_128);
        store_hl(AhiB, AloB, rowB, col, v2, v3, LDA2_128);
        acc[j][0] = 0.f; acc[j][1] = 0.f; acc[j][2] = 0.f; acc[j][3] = 0.f;
    }
    __syncthreads();

    // ---- 7: ra10 ----
    run_mma<N, 128>(acc, hiBase + aOff128, loBase + aOff128, w.ra10, lane, n8base);
    __syncthreads();
    #pragma unroll
    for (int j = 0; j < N8; j++) {
        const int col = warpN + j * 8 + c0;
        float b0 = sb[6 * 128 + col], b1 = sb[6 * 128 + col + 1];
        store_hl(AhiB, AloB, rowA, col, swishf(acc[j][0] + b0), swishf(acc[j][1] + b1), LDA2_128);
        store_hl(AhiB, AloB, rowB, col, swishf(acc[j][2] + b0), swishf(acc[j][3] + b1), LDA2_128);
        acc[j][0] = 0.f; acc[j][1] = 0.f; acc[j][2] = 0.f; acc[j][3] = 0.f;
    }
    __syncthreads();

    // ---- 8: ra11: out = Tf + swish -> global ----
    run_mma<N, 128>(acc, hiBase + aOff128, loBase + aOff128, w.ra11, lane, n8base);
    #pragma unroll
    for (int j = 0; j < N8; j++) {
        const int col = warpN + j * 8 + c0;
        float b0 = sb[7 * 128 + col], b1 = sb[7 * 128 + col + 1];
        float2 tA = *(const float2*)(Tf + rowA * LDT + col);
        float2 tB = *(const float2*)(Tf + rowB * LDT + col);
        *(float2*)(out + gA * N + col) =
            make_float2(tA.x + swishf(acc[j][0] + b0), tA.y + swishf(acc[j][1] + b1));
        *(float2*)(out + gB * N + col) =
            make_float2(tB.x + swishf(acc[j][2] + b0), tB.y + swishf(acc[j][3] + b1));
    }
}

// ---------------------------------------------------------------------------
// proj8: out[rows x 8] = X[rows x NIN] @ W[NIN x 8]  (sbf projection)
// ---------------------------------------------------------------------------
template<int NIN>
__global__ __launch_bounds__(256) void proj8_kernel(
    const float* __restrict__ X, const float* __restrict__ W,
    float* __restrict__ out)
{
    __shared__ float tile[256 * NIN];
    __shared__ float Ws[NIN * 8];
    const size_t base = (size_t)blockIdx.x * 256;
    constexpr int NT4 = 256 * NIN / 4;
    const float4* src = (const float4*)(X + base * NIN);
    #pragma unroll 4
    for (int i = threadIdx.x; i < NT4; i += 256)
        ((float4*)tile)[i] = src[i];
    for (int i = threadIdx.x; i < NIN * 8; i += 256)
        Ws[i] = W[i];
    __syncthreads();

    const float* x = &tile[threadIdx.x * NIN];
    float o[8] = {0, 0, 0, 0, 0, 0, 0, 0};
    #pragma unroll
    for (int c = 0; c < NIN; c++) {
        float xv = x[c];
        #pragma unroll
        for (int b = 0; b < 8; b++)
            o[b] = fmaf(xv, Ws[c * 8 + b], o[b]);
    }
    float4* op = (float4*)(out + (base + threadIdx.x) * 8);
    op[0] = make_float4(o[0], o[1], o[2], o[3]);
    op[1] = make_float4(o[4], o[5], o[6], o[7]);
}

__global__ void zero_kernel(float4* __restrict__ p, size_t n4)
{
    size_t i = (size_t)blockIdx.x * blockDim.x + threadIdx.x;
    if (i < n4) p[i] = make_float4(0.f, 0.f, 0.f, 0.f);
}

// ---------------------------------------------------------------------------
// Triplet gather/gate/scatter -- 4 triplets per 16-lane group (MLP=4)
// ---------------------------------------------------------------------------
__global__ __launch_bounds__(256, 8) void triplet_kernel(
    const int* __restrict__ expand_to_kj,
    const int* __restrict__ reduce_to_ji,
    const float* __restrict__ sbf8,
    const float* __restrict__ Wsbf2,
    const float* __restrict__ ang,
    float* __restrict__ agg)
{
    __shared__ float Ws[8 * 64];
    for (int i = threadIdx.x; i < 512; i += 256) Ws[i] = Wsbf2[i];
    __syncthreads();

    const int lane16 = threadIdx.x & 15;
    const size_t grp = ((size_t)blockIdx.x * 256 + threadIdx.x) >> 4;
    const size_t t0 = grp * 4;

    int ekj[4], eji[4];
    #pragma unroll
    for (int q = 0; q < 4; q++) {
        ekj[q] = __ldg(&expand_to_kj[t0 + q]);
        eji[q] = __ldg(&reduce_to_ji[t0 + q]);
    }

    float4 a[4];
    #pragma unroll
    for (int q = 0; q < 4; q++)
        a[q] = __ldg((const float4*)(ang + (size_t)ekj[q] * 64 + lane16 * 4));

    float g[4][4];
    #pragma unroll
    for (int q = 0; q < 4; q++)
        #pragma unroll
        for (int x = 0; x < 4; x++) g[q][x] = 0.f;

    #pragma unroll
    for (int b = 0; b < 8; b++) {
        const float* w = &Ws[b * 64 + lane16 * 4];
        float w0 = w[0], w1 = w[1], w2 = w[2], w3 = w[3];
        #pragma unroll
        for (int q = 0; q < 4; q++) {
            float sb = __ldg(&sbf8[(t0 + q) * 8 + b]);
            g[q][0] = fmaf(sb, w0, g[q][0]);
            g[q][1] = fmaf(sb, w1, g[q][1]);
            g[q][2] = fmaf(sb, w2, g[q][2]);
            g[q][3] = fmaf(sb, w3, g[q][3]);
        }
    }

    #pragma unroll
    for (int q = 0; q < 4; q++) {
        float v0 = a[q].x * g[q][0];
        float v1 = a[q].y * g[q][1];
        float v2 = a[q].z * g[q][2];
        float v3 = a[q].w * g[q][3];
        float* d = agg + (size_t)eji[q] * 64 + lane16 * 4;
        asm volatile("red.global.add.v4.f32 [%0], {%1,%2,%3,%4};"
                     :: "l"(d), "f"(v0), "f"(v1), "f"(v2), "f"(v3) : "memory");
    }
}

// ---------------------------------------------------------------------------
// Host orchestration
// ---------------------------------------------------------------------------
static inline int edge_smemsz() { return 5120 + 2 * (MT * 136 * 2); }
static inline int tail_smemsz() { return 4096 + MT * LDT * 4 + 2 * (MT * 136 * 2); }

extern "C" void kernel_launch(void* const* d_in, const int* in_sizes, int n_in,
                              void* d_out, int out_size)
{
    const float* m_input = (const float*)d_in[0];
    const float* rbf     = (const float*)d_in[1];
    const float* sbf     = (const float*)d_in[2];
    const int*   expand  = (const int*)  d_in[3];
    const int*   reduce  = (const int*)  d_in[4];
    const float* W_kj    = (const float*)d_in[5];
    const float* b_kj    = (const float*)d_in[6];
    const float* W_rbf1  = (const float*)d_in[7];
    const float* W_rbf2  = (const float*)d_in[8];
    const float* W_sbf1  = (const float*)d_in[9];
    const float* W_sbf2  = (const float*)d_in[10];
    const float* W_down  = (const float*)d_in[11];
    const float* W_up    = (const float*)d_in[12];
    const float* W_ji    = (const float*)d_in[13];
    const float* b_ji    = (const float*)d_in[14];
    const float* W_res_b = (const float*)d_in[15];
    const float* b_res_b = (const float*)d_in[16];
    const float* W_final = (const float*)d_in[17];
    const float* b_final = (const float*)d_in[18];
    const float* W_res_a = (const float*)d_in[19];
    const float* b_res_a = (const float*)d_in[20];
    float* out = (float*)d_out;

    const int E = in_sizes[0] / 128;
    const int T = in_sizes[3];

    float *ang, *agg, *sbf8, *wb;
    cudaGetSymbolAddress((void**)&ang,  g_ang);
    cudaGetSymbolAddress((void**)&agg,  g_agg);
    cudaGetSymbolAddress((void**)&sbf8, g_sbf8);
    cudaGetSymbolAddress((void**)&wb,   g_wb);

    cudaFuncSetAttribute(edge_fused,
                         cudaFuncAttributeMaxDynamicSharedMemorySize, edge_smemsz());
    cudaFuncSetAttribute(tail_fused,
                         cudaFuncAttributeMaxDynamicSharedMemorySize, tail_smemsz());

    char* wbb = (char*)wb;
    auto wat = [&](size_t off) { return (const uint32_t*)(wbb + off); };
    const unsigned OF_KJ = 0, OF_JI = 65536, OF_RB0 = 131072, OF_RB1 = 196608,
                   OF_FIN = 262144, OF_RA00 = 327680, OF_RA01 = 393216,
                   OF_RA10 = 458752, OF_RA11 = 524288,
                   OF_DOWN = 589824, OF_UP = 622592;

    // 0-1: weight conversion (interleaved hi|lo layout)
    {
        W9 w;
        w.s[0] = W_kj;            w.off[0] = OF_KJ;
        w.s[1] = W_ji;            w.off[1] = OF_JI;
        w.s[2] = W_res_b;         w.off[2] = OF_RB0;
        w.s[3] = W_res_b + 16384; w.off[3] = OF_RB1;
        w.s[4] = W_final;         w.off[4] = OF_FIN;
        w.s[5] = W_res_a;         w.off[5] = OF_RA00;
        w.s[6] = W_res_a + 16384; w.off[6] = OF_RA01;
        w.s[7] = W_res_a + 32768; w.off[7] = OF_RA10;
        w.s[8] = W_res_a + 49152; w.off[8] = OF_RA11;
        wconv9_kernel<<<dim3(8, 9), 256>>>(w, wbb);

        W2 w2;
        w2.s[0] = W_down; w2.off[0] = OF_DOWN; w2.K[0] = 128; w2.N[0] = 64;
        w2.s[1] = W_up;   w2.off[1] = OF_UP;   w2.K[1] = 64;  w2.N[1] = 128;
        wconv2_kernel<<<dim3(8, 2), 256>>>(w2, wbb);
    }

    const int GE = E / MT;   // 4096

    // 2: edge fusion (with inline rbf projection): ang -> g_ang
    edge_fused<<<GE, 256, edge_smemsz()>>>(
        m_input, wat(OF_KJ), b_kj, wat(OF_DOWN), W_rbf2, W_rbf1, rbf, ang);

    // 3: sbf8
    proj8_kernel<42><<<T / 256, 256>>>(sbf, W_sbf1, sbf8);

    // 4: agg = 0
    {
        size_t n4 = (size_t)E * 64 / 4;
        zero_kernel<<<(unsigned)((n4 + 255) / 256), 256>>>((float4*)agg, n4);
    }

    // 5: scatter (4 triplets per 16-lane group)
    triplet_kernel<<<(unsigned)((size_t)T * 16 / 256 / 4), 256>>>(
        expand, reduce, sbf8, W_sbf2, ang, agg);

    // 6: tail: ji + steps 7-11 fused -> out
    {
        TailW w;
        w.ji   = wat(OF_JI);   w.b_ji   = b_ji;
        w.up   = wat(OF_UP);
        w.rb0  = wat(OF_RB0);  w.b_rb0  = b_res_b;
        w.rb1  = wat(OF_RB1);  w.b_rb1  = b_res_b + 128;
        w.fin  = wat(OF_FIN);  w.b_fin  = b_final;
        w.ra00 = wat(OF_RA00); w.b_ra00 = b_res_a;
        w.ra01 = wat(OF_RA01); w.b_ra01 = b_res_a + 128;
        w.ra10 = wat(OF_RA10); w.b_ra10 = b_res_a + 256;
        w.ra11 = wat(OF_RA11); w.b_ra11 = b_res_a + 384;
        tail_fused<<<GE, 256, tail_smemsz()>>>(agg, m_input, w, out);
    }
}